// round 1
// baseline (speedup 1.0000x reference)
#include <cuda_runtime.h>
#include <math.h>
#include <stdint.h>

#define N_NODES_C 50000
#define N_EDGES_C 800000
#define N_GRAPHS_C 512
#define DIM 256
#define HEADS 4
#define HID 64
#define KGE_DIM 64

// ---------------- static device scratch (no allocations allowed) ----------------
__device__ float g_h  [N_NODES_C * DIM];
__device__ float g_xa [N_NODES_C * DIM];
__device__ float g_xb [N_NODES_C * DIM];
__device__ float g_asrc[N_NODES_C * HEADS];
__device__ float g_adst[N_NODES_C * HEADS];
__device__ int   g_deg   [N_NODES_C];
__device__ int   g_indptr[N_NODES_C + 1];
__device__ int   g_cursor[N_NODES_C];
__device__ int   g_esrc  [N_EDGES_C];
__device__ float g_hemb[N_GRAPHS_C * DIM];
__device__ float g_temb[N_GRAPHS_C * DIM];

__device__ __forceinline__ float lrelu(float x) { return x > 0.f ? x : 0.2f * x; }
__device__ __forceinline__ float elu_f(float x) { return x > 0.f ? x : expm1f(x); }
__device__ __forceinline__ float pick4(float a, float b, float c, float d, int h) {
    return h == 0 ? a : (h == 1 ? b : (h == 2 ? c : d));
}

// ---------------- CSR build (counting sort by dst) ----------------
__global__ void hist_kernel(const int* __restrict__ dst, int E, int* __restrict__ deg) {
    int e = blockIdx.x * blockDim.x + threadIdx.x;
    if (e < E) atomicAdd(&deg[dst[e]], 1);
}

__global__ void scan_kernel(const int* __restrict__ deg, int* __restrict__ indptr,
                            int* __restrict__ cursor, int n) {
    __shared__ int sh[1024];
    __shared__ int carry_s;
    int tid = threadIdx.x;
    if (tid == 0) carry_s = 0;
    __syncthreads();
    for (int base = 0; base < n; base += 1024) {
        int i = base + tid;
        int v = (i < n) ? deg[i] : 0;
        sh[tid] = v;
        __syncthreads();
        for (int o = 1; o < 1024; o <<= 1) {
            int t = (tid >= o) ? sh[tid - o] : 0;
            __syncthreads();
            sh[tid] += t;
            __syncthreads();
        }
        int excl = carry_s + sh[tid] - v;
        if (i < n) { indptr[i] = excl; cursor[i] = excl; }
        __syncthreads();
        if (tid == 1023) carry_s += sh[1023];
        __syncthreads();
    }
    if (tid == 0) indptr[n] = carry_s;
}

__global__ void scatter_kernel(const int* __restrict__ src, const int* __restrict__ dst,
                               int E, int* __restrict__ cursor, int* __restrict__ esrc) {
    int e = blockIdx.x * blockDim.x + threadIdx.x;
    if (e < E) {
        int pos = atomicAdd(&cursor[dst[e]], 1);
        esrc[pos] = src[e];
    }
}

// ---------------- FP32 GEMM: C[M,256] = A[M,256] @ B[256,256] ----------------
__global__ __launch_bounds__(256) void gemm_kernel(const float* __restrict__ A,
                                                   const float* __restrict__ B,
                                                   float* __restrict__ C, int M) {
    constexpr int K = 256, N = 256, BM = 128, BN = 64, BK = 16;
    __shared__ float As[BK][BM + 4];   // transposed: As[k][m]
    __shared__ float Bs[BK][BN + 4];
    int bm = blockIdx.x * BM;
    int bn = blockIdx.y * BN;
    int tid = threadIdx.x;
    int tx = tid & 15, ty = tid >> 4;     // thread computes rows ty*8..+7, cols tx*4..+3

    float acc[8][4];
#pragma unroll
    for (int i = 0; i < 8; ++i)
#pragma unroll
        for (int j = 0; j < 4; ++j) acc[i][j] = 0.f;

    int ar = tid >> 2;              // 0..63 (row within half-tile)
    int ac = (tid & 3) << 2;        // k offset 0,4,8,12
    int brow = tid >> 4;            // 0..15
    int bcol = (tid & 15) << 2;     // 0..60

    for (int k0 = 0; k0 < K; k0 += BK) {
#pragma unroll
        for (int i = 0; i < 2; ++i) {
            int row = bm + ar + i * 64;
            float4 av = make_float4(0.f, 0.f, 0.f, 0.f);
            if (row < M) av = *(const float4*)(A + (size_t)row * K + k0 + ac);
            As[ac + 0][ar + i * 64] = av.x;
            As[ac + 1][ar + i * 64] = av.y;
            As[ac + 2][ar + i * 64] = av.z;
            As[ac + 3][ar + i * 64] = av.w;
        }
        {
            float4 bv = *(const float4*)(B + (size_t)(k0 + brow) * N + bn + bcol);
            *(float4*)&Bs[brow][bcol] = bv;
        }
        __syncthreads();
#pragma unroll
        for (int k = 0; k < BK; ++k) {
            float4 a0 = *(const float4*)&As[k][ty * 8];
            float4 a1 = *(const float4*)&As[k][ty * 8 + 4];
            float4 b0 = *(const float4*)&Bs[k][tx * 4];
            float a[8] = {a0.x, a0.y, a0.z, a0.w, a1.x, a1.y, a1.z, a1.w};
            float b[4] = {b0.x, b0.y, b0.z, b0.w};
#pragma unroll
            for (int i = 0; i < 8; ++i)
#pragma unroll
                for (int j = 0; j < 4; ++j) acc[i][j] = fmaf(a[i], b[j], acc[i][j]);
        }
        __syncthreads();
    }
#pragma unroll
    for (int i = 0; i < 8; ++i) {
        int row = bm + ty * 8 + i;
        if (row < M) {
            float4 o = make_float4(acc[i][0], acc[i][1], acc[i][2], acc[i][3]);
            *(float4*)(C + (size_t)row * N + bn + tx * 4) = o;
        }
    }
}

// ---------------- attention logits: asrc[n,h] = h[n]·att_s[h], adst likewise ----------------
__global__ void att_kernel(const float* __restrict__ h, const float* __restrict__ att_s,
                           const float* __restrict__ att_d, float* __restrict__ asrc,
                           float* __restrict__ adst, int N) {
    int w = (blockIdx.x * blockDim.x + threadIdx.x) >> 5;
    int lane = threadIdx.x & 31;
    if (w >= N) return;
    const float4* hp = (const float4*)(h + (size_t)w * DIM);
    float4 v0 = hp[lane * 2], v1 = hp[lane * 2 + 1];
    const float4* sp = (const float4*)(att_s + lane * 8);
    const float4* dp = (const float4*)(att_d + lane * 8);
    float4 s0 = sp[0], s1 = sp[1], d0 = dp[0], d1 = dp[1];
    float ps = v0.x * s0.x + v0.y * s0.y + v0.z * s0.z + v0.w * s0.w +
               v1.x * s1.x + v1.y * s1.y + v1.z * s1.z + v1.w * s1.w;
    float pd = v0.x * d0.x + v0.y * d0.y + v0.z * d0.z + v0.w * d0.w +
               v1.x * d1.x + v1.y * d1.y + v1.z * d1.z + v1.w * d1.w;
#pragma unroll
    for (int o = 4; o; o >>= 1) {
        ps += __shfl_xor_sync(0xffffffffu, ps, o);
        pd += __shfl_xor_sync(0xffffffffu, pd, o);
    }
    if ((lane & 7) == 0) {
        asrc[w * 4 + (lane >> 3)] = ps;
        adst[w * 4 + (lane >> 3)] = pd;
    }
}

// ---------------- GAT aggregation: one warp per destination node ----------------
__global__ void aggregate_kernel(const float* __restrict__ h,
                                 const float* __restrict__ asrc,
                                 const float* __restrict__ adst,
                                 const int* __restrict__ indptr,
                                 const int* __restrict__ esrc,
                                 const float* __restrict__ bias,
                                 float* __restrict__ xout, int N) {
    int n = (blockIdx.x * blockDim.x + threadIdx.x) >> 5;
    int lane = threadIdx.x & 31;
    if (n >= N) return;
    int s0 = indptr[n], s1 = indptr[n + 1];

    float4 ad  = *(const float4*)(adst + 4 * n);
    float4 asn = *(const float4*)(asrc + 4 * n);
    float self0 = lrelu(asn.x + ad.x);
    float self1 = lrelu(asn.y + ad.y);
    float self2 = lrelu(asn.z + ad.z);
    float self3 = lrelu(asn.w + ad.w);

    // pass 1: per-head max over incoming edges (self-loop included)
    float m0 = self0, m1 = self1, m2 = self2, m3 = self3;
    for (int e = s0 + lane; e < s1; e += 32) {
        int s = esrc[e];
        float4 a = *(const float4*)(asrc + 4 * s);
        m0 = fmaxf(m0, lrelu(a.x + ad.x));
        m1 = fmaxf(m1, lrelu(a.y + ad.y));
        m2 = fmaxf(m2, lrelu(a.z + ad.z));
        m3 = fmaxf(m3, lrelu(a.w + ad.w));
    }
#pragma unroll
    for (int o = 16; o; o >>= 1) {
        m0 = fmaxf(m0, __shfl_xor_sync(0xffffffffu, m0, o));
        m1 = fmaxf(m1, __shfl_xor_sync(0xffffffffu, m1, o));
        m2 = fmaxf(m2, __shfl_xor_sync(0xffffffffu, m2, o));
        m3 = fmaxf(m3, __shfl_xor_sync(0xffffffffu, m3, o));
    }

    // pass 2: per-head sum of exp
    float t0 = 0.f, t1 = 0.f, t2 = 0.f, t3 = 0.f;
    for (int e = s0 + lane; e < s1; e += 32) {
        int s = esrc[e];
        float4 a = *(const float4*)(asrc + 4 * s);
        t0 += expf(lrelu(a.x + ad.x) - m0);
        t1 += expf(lrelu(a.y + ad.y) - m1);
        t2 += expf(lrelu(a.z + ad.z) - m2);
        t3 += expf(lrelu(a.w + ad.w) - m3);
    }
#pragma unroll
    for (int o = 16; o; o >>= 1) {
        t0 += __shfl_xor_sync(0xffffffffu, t0, o);
        t1 += __shfl_xor_sync(0xffffffffu, t1, o);
        t2 += __shfl_xor_sync(0xffffffffu, t2, o);
        t3 += __shfl_xor_sync(0xffffffffu, t3, o);
    }
    t0 += expf(self0 - m0);
    t1 += expf(self1 - m1);
    t2 += expf(self2 - m2);
    t3 += expf(self3 - m3);

    int head = lane >> 3;                    // this lane's 8 channels belong to one head
    float mh  = pick4(m0, m1, m2, m3, head);
    float inv = 1.0f / pick4(t0, t1, t2, t3, head);
    float adh = pick4(ad.x, ad.y, ad.z, ad.w, head);

    float acc[8];
#pragma unroll
    for (int i = 0; i < 8; ++i) acc[i] = 0.f;

    // self-loop contribution
    {
        float w = expf(pick4(self0, self1, self2, self3, head) - mh) * inv;
        const float4* hp = (const float4*)(h + (size_t)n * DIM);
        float4 v0 = hp[lane * 2], v1 = hp[lane * 2 + 1];
        acc[0] += w * v0.x; acc[1] += w * v0.y; acc[2] += w * v0.z; acc[3] += w * v0.w;
        acc[4] += w * v1.x; acc[5] += w * v1.y; acc[6] += w * v1.z; acc[7] += w * v1.w;
    }

    // pass 3: weighted accumulate, 8 edges per warp-step, expf once per (edge, head)
    for (int eb = s0; eb < s1; eb += 8) {
        int idx = eb + (lane & 7);
        float wv = 0.f;
        int sv = 0;
        if (idx < s1) {
            sv = esrc[idx];
            float a = __ldg(asrc + 4 * sv + head);
            wv = expf(lrelu(a + adh) - mh) * inv;
        }
        int cnt = min(8, s1 - eb);
        for (int j = 0; j < cnt; ++j) {
            float wj = __shfl_sync(0xffffffffu, wv, (lane & 24) | j);
            int sj   = __shfl_sync(0xffffffffu, sv, j);
            const float4* hp = (const float4*)(h + (size_t)sj * DIM);
            float4 v0 = hp[lane * 2], v1 = hp[lane * 2 + 1];
            acc[0] += wj * v0.x; acc[1] += wj * v0.y; acc[2] += wj * v0.z; acc[3] += wj * v0.w;
            acc[4] += wj * v1.x; acc[5] += wj * v1.y; acc[6] += wj * v1.z; acc[7] += wj * v1.w;
        }
    }

    // bias + ELU + store
    const float4* bp = (const float4*)(bias + lane * 8);
    float4 b0 = bp[0], b1 = bp[1];
    float4 o0, o1;
    o0.x = elu_f(acc[0] + b0.x); o0.y = elu_f(acc[1] + b0.y);
    o0.z = elu_f(acc[2] + b0.z); o0.w = elu_f(acc[3] + b0.w);
    o1.x = elu_f(acc[4] + b1.x); o1.y = elu_f(acc[5] + b1.y);
    o1.z = elu_f(acc[6] + b1.z); o1.w = elu_f(acc[7] + b1.w);
    float4* xo = (float4*)(xout + (size_t)n * DIM);
    xo[lane * 2] = o0;
    xo[lane * 2 + 1] = o1;
}

// ---------------- global add pool ----------------
__global__ void pool_kernel(const float* __restrict__ x, const int* __restrict__ batch,
                            float* __restrict__ emb) {
    int n = blockIdx.x;
    int c = threadIdx.x;
    int b = batch[n];
    atomicAdd(&emb[(size_t)b * DIM + c], x[(size_t)n * DIM + c]);
}

// ---------------- final MLP per graph ----------------
__global__ void mlp_kernel(const float* __restrict__ hemb, const float* __restrict__ temb,
                           const float* __restrict__ kge, const int* __restrict__ rel,
                           const float* __restrict__ W1, const float* __restrict__ b1,
                           const float* __restrict__ W2, const float* __restrict__ b2,
                           float* __restrict__ out) {
    int g = blockIdx.x;
    int t = threadIdx.x;   // 64 threads
    __shared__ float z[2 * DIM + KGE_DIM];   // 576
    for (int i = t; i < DIM; i += 64) {
        z[i]       = hemb[(size_t)g * DIM + i];
        z[DIM + i] = temb[(size_t)g * DIM + i];
    }
    int r = rel[g];
    z[2 * DIM + t] = kge[(size_t)r * KGE_DIM + t];
    __syncthreads();

    float acc = b1[t];
#pragma unroll 4
    for (int k = 0; k < 2 * DIM + KGE_DIM; ++k)
        acc = fmaf(z[k], W1[(size_t)k * 64 + t], acc);
    acc = fmaxf(acc, 0.f) * W2[t];

#pragma unroll
    for (int o = 16; o; o >>= 1) acc += __shfl_xor_sync(0xffffffffu, acc, o);
    __shared__ float wsum[2];
    if ((t & 31) == 0) wsum[t >> 5] = acc;
    __syncthreads();
    if (t == 0) out[g] = wsum[0] + wsum[1] + b2[0];
}

// ---------------- launch ----------------
extern "C" void kernel_launch(void* const* d_in, const int* in_sizes, int n_in,
                              void* d_out, int out_size) {
    const float* head_x     = (const float*)d_in[0];
    const int*   head_ei    = (const int*)  d_in[1];
    const int*   head_batch = (const int*)  d_in[2];
    const float* tail_x     = (const float*)d_in[3];
    const int*   tail_ei    = (const int*)  d_in[4];
    const int*   tail_batch = (const int*)  d_in[5];
    const int*   rel        = (const int*)  d_in[6];
    const float* Ws         = (const float*)d_in[7];
    const float* att_s      = (const float*)d_in[8];
    const float* att_d      = (const float*)d_in[9];
    const float* biases     = (const float*)d_in[10];
    const float* kge        = (const float*)d_in[11];
    const float* W1         = (const float*)d_in[12];
    const float* b1         = (const float*)d_in[13];
    const float* W2         = (const float*)d_in[14];
    const float* b2         = (const float*)d_in[15];
    float* out = (float*)d_out;

    const int N = in_sizes[0] / DIM;    // 50000
    const int E = in_sizes[1] / 2;      // 800000
    const int B = in_sizes[6];          // 512

    float *p_h, *p_xa, *p_xb, *p_asrc, *p_adst, *p_hemb, *p_temb;
    int *p_deg, *p_indptr, *p_cursor, *p_esrc;
    cudaGetSymbolAddress((void**)&p_h, g_h);
    cudaGetSymbolAddress((void**)&p_xa, g_xa);
    cudaGetSymbolAddress((void**)&p_xb, g_xb);
    cudaGetSymbolAddress((void**)&p_asrc, g_asrc);
    cudaGetSymbolAddress((void**)&p_adst, g_adst);
    cudaGetSymbolAddress((void**)&p_hemb, g_hemb);
    cudaGetSymbolAddress((void**)&p_temb, g_temb);
    cudaGetSymbolAddress((void**)&p_deg, g_deg);
    cudaGetSymbolAddress((void**)&p_indptr, g_indptr);
    cudaGetSymbolAddress((void**)&p_cursor, g_cursor);
    cudaGetSymbolAddress((void**)&p_esrc, g_esrc);

    const int wblocks = (N * 32 + 255) / 256;

    for (int enc = 0; enc < 2; ++enc) {
        const float* x0    = enc ? tail_x : head_x;
        const int*   ei    = enc ? tail_ei : head_ei;
        const int*   batch = enc ? tail_batch : head_batch;
        float*       emb   = enc ? p_temb : p_hemb;

        // build CSR by dst (counting sort)
        cudaMemsetAsync(p_deg, 0, (size_t)N * sizeof(int));
        hist_kernel<<<(E + 255) / 256, 256>>>(ei + E, E, p_deg);
        scan_kernel<<<1, 1024>>>(p_deg, p_indptr, p_cursor, N);
        scatter_kernel<<<(E + 255) / 256, 256>>>(ei, ei + E, E, p_cursor, p_esrc);

        const float* xin = x0;
        float* bufs[2] = {p_xa, p_xb};
        for (int l = 0; l < 3; ++l) {
            dim3 gg((unsigned)((N + 127) / 128), 4);
            gemm_kernel<<<gg, 256>>>(xin, Ws + (size_t)l * DIM * DIM, p_h, N);
            att_kernel<<<wblocks, 256>>>(p_h, att_s + l * HEADS * HID,
                                         att_d + l * HEADS * HID, p_asrc, p_adst, N);
            aggregate_kernel<<<wblocks, 256>>>(p_h, p_asrc, p_adst, p_indptr, p_esrc,
                                               biases + l * DIM, bufs[l & 1], N);
            xin = bufs[l & 1];
        }

        cudaMemsetAsync(emb, 0, (size_t)N_GRAPHS_C * DIM * sizeof(float));
        pool_kernel<<<N, 256>>>(xin, batch, emb);
    }

    mlp_kernel<<<B, 64>>>(p_hemb, p_temb, kge, rel, W1, b1, W2, b2, out);
}

// round 2
// speedup vs baseline: 1.0142x; 1.0142x over previous
#include <cuda_runtime.h>
#include <math.h>
#include <stdint.h>

#define N_NODES_C 50000
#define N_EDGES_C 800000
#define N_GRAPHS_C 512
#define DIM 256
#define HEADS 4
#define HID 64
#define KGE_DIM 64

// ---------------- static device scratch (no allocations allowed) ----------------
__device__ float g_h  [N_NODES_C * DIM];
__device__ float g_xa [N_NODES_C * DIM];
__device__ float g_xb [N_NODES_C * DIM];
__device__ float g_asrc[N_NODES_C * HEADS];
__device__ float g_adst[N_NODES_C * HEADS];
__device__ int   g_deg   [N_NODES_C];
__device__ int   g_indptr[N_NODES_C + 1];
__device__ int   g_cursor[N_NODES_C];
__device__ int   g_esrc  [N_EDGES_C];
__device__ float g_hemb[N_GRAPHS_C * DIM];
__device__ float g_temb[N_GRAPHS_C * DIM];

__device__ __forceinline__ float lrelu(float x) { return x > 0.f ? x : 0.2f * x; }
__device__ __forceinline__ float elu_f(float x) { return x > 0.f ? x : expm1f(x); }
__device__ __forceinline__ float pick4(float a, float b, float c, float d, int h) {
    return h == 0 ? a : (h == 1 ? b : (h == 2 ? c : d));
}

// ---------------- CSR build (counting sort by dst) ----------------
__global__ void hist_kernel(const int* __restrict__ dst, int E, int* __restrict__ deg) {
    int e = blockIdx.x * blockDim.x + threadIdx.x;
    if (e < E) atomicAdd(&deg[dst[e]], 1);
}

// single-block warp-shuffle scan: 4096 elements per iteration
__global__ void scan_kernel(const int* __restrict__ deg, int* __restrict__ indptr,
                            int* __restrict__ cursor, int n) {
    __shared__ int wsum[32];
    __shared__ int carry_s;
    int tid = threadIdx.x, lane = tid & 31, wid = tid >> 5;
    if (tid == 0) carry_s = 0;
    __syncthreads();
    for (int base = 0; base < n; base += 4096) {
        int i0 = base + tid * 4;
        int v0 = (i0 + 0 < n) ? deg[i0 + 0] : 0;
        int v1 = (i0 + 1 < n) ? deg[i0 + 1] : 0;
        int v2 = (i0 + 2 < n) ? deg[i0 + 2] : 0;
        int v3 = (i0 + 3 < n) ? deg[i0 + 3] : 0;
        int s = v0 + v1 + v2 + v3;
        int ps = s;
#pragma unroll
        for (int o = 1; o < 32; o <<= 1) {
            int t = __shfl_up_sync(0xffffffffu, ps, o);
            if (lane >= o) ps += t;
        }
        if (lane == 31) wsum[wid] = ps;
        __syncthreads();
        if (wid == 0) {
            int w = wsum[lane];
            int pw = w;
#pragma unroll
            for (int o = 1; o < 32; o <<= 1) {
                int t = __shfl_up_sync(0xffffffffu, pw, o);
                if (lane >= o) pw += t;
            }
            wsum[lane] = pw;
        }
        __syncthreads();
        int woff = wid ? wsum[wid - 1] : 0;
        int run = carry_s + woff + ps - s;   // exclusive prefix for this thread's 4 elems
        if (i0 + 0 < n) { indptr[i0 + 0] = run; cursor[i0 + 0] = run; } run += v0;
        if (i0 + 1 < n) { indptr[i0 + 1] = run; cursor[i0 + 1] = run; } run += v1;
        if (i0 + 2 < n) { indptr[i0 + 2] = run; cursor[i0 + 2] = run; } run += v2;
        if (i0 + 3 < n) { indptr[i0 + 3] = run; cursor[i0 + 3] = run; }
        __syncthreads();
        if (tid == 0) carry_s += wsum[31];
        __syncthreads();
    }
    if (tid == 0) indptr[n] = carry_s;
}

__global__ void scatter_kernel(const int* __restrict__ src, const int* __restrict__ dst,
                               int E, int* __restrict__ cursor, int* __restrict__ esrc) {
    int e = blockIdx.x * blockDim.x + threadIdx.x;
    if (e < E) {
        int pos = atomicAdd(&cursor[dst[e]], 1);
        esrc[pos] = src[e];
    }
}

// ---------------- FP32 GEMM: C[M,256] = A[M,256] @ B[256,256] ----------------
// 128x128 tile, 8x8 per thread, BK=16, double-buffered
__global__ __launch_bounds__(256, 2) void gemm_kernel(const float* __restrict__ A,
                                                      const float* __restrict__ B,
                                                      float* __restrict__ C, int M) {
    constexpr int K = 256, N = 256, BM = 128, BN = 128, BK = 16;
    __shared__ float As[2][BK][BM + 4];
    __shared__ float Bs[2][BK][BN + 4];
    int bm = blockIdx.x * BM;
    int bn = blockIdx.y * BN;
    int tid = threadIdx.x;
    int arow = tid >> 1, acol = (tid & 1) * 8;
    int brow = tid >> 4, bcol = (tid & 15) * 8;
    int tx = tid & 15, ty = tid >> 4;

    const bool aval = (bm + arow) < M;
    const float* Ap = A + (size_t)(bm + arow) * K + acol;
    const float* Bp = B + (size_t)brow * N + bn + bcol;

    float4 ra0, ra1, rb0, rb1;
    const float4 z4 = make_float4(0.f, 0.f, 0.f, 0.f);

    // fetch k0 = 0
    ra0 = aval ? *(const float4*)(Ap + 0) : z4;
    ra1 = aval ? *(const float4*)(Ap + 4) : z4;
    rb0 = *(const float4*)(Bp + 0);
    rb1 = *(const float4*)(Bp + 4);

    float acc[8][8];
#pragma unroll
    for (int i = 0; i < 8; ++i)
#pragma unroll
        for (int j = 0; j < 8; ++j) acc[i][j] = 0.f;

    // store buffer 0
    {
        As[0][acol + 0][arow] = ra0.x; As[0][acol + 1][arow] = ra0.y;
        As[0][acol + 2][arow] = ra0.z; As[0][acol + 3][arow] = ra0.w;
        As[0][acol + 4][arow] = ra1.x; As[0][acol + 5][arow] = ra1.y;
        As[0][acol + 6][arow] = ra1.z; As[0][acol + 7][arow] = ra1.w;
        *(float4*)&Bs[0][brow][bcol] = rb0;
        *(float4*)&Bs[0][brow][bcol + 4] = rb1;
    }
    __syncthreads();

    int buf = 0;
    for (int k0 = BK; k0 < K; k0 += BK) {
        // fetch next
        ra0 = aval ? *(const float4*)(Ap + k0)     : z4;
        ra1 = aval ? *(const float4*)(Ap + k0 + 4) : z4;
        rb0 = *(const float4*)(Bp + (size_t)k0 * N);
        rb1 = *(const float4*)(Bp + (size_t)k0 * N + 4);
        // compute current
#pragma unroll
        for (int k = 0; k < BK; ++k) {
            float4 a0 = *(const float4*)&As[buf][k][ty * 8];
            float4 a1 = *(const float4*)&As[buf][k][ty * 8 + 4];
            float4 b0 = *(const float4*)&Bs[buf][k][tx * 8];
            float4 b1 = *(const float4*)&Bs[buf][k][tx * 8 + 4];
            float av[8] = {a0.x, a0.y, a0.z, a0.w, a1.x, a1.y, a1.z, a1.w};
            float bv[8] = {b0.x, b0.y, b0.z, b0.w, b1.x, b1.y, b1.z, b1.w};
#pragma unroll
            for (int i = 0; i < 8; ++i)
#pragma unroll
                for (int j = 0; j < 8; ++j) acc[i][j] = fmaf(av[i], bv[j], acc[i][j]);
        }
        // store into other buffer
        int d = buf ^ 1;
        As[d][acol + 0][arow] = ra0.x; As[d][acol + 1][arow] = ra0.y;
        As[d][acol + 2][arow] = ra0.z; As[d][acol + 3][arow] = ra0.w;
        As[d][acol + 4][arow] = ra1.x; As[d][acol + 5][arow] = ra1.y;
        As[d][acol + 6][arow] = ra1.z; As[d][acol + 7][arow] = ra1.w;
        *(float4*)&Bs[d][brow][bcol] = rb0;
        *(float4*)&Bs[d][brow][bcol + 4] = rb1;
        __syncthreads();
        buf ^= 1;
    }
    // final compute
#pragma unroll
    for (int k = 0; k < BK; ++k) {
        float4 a0 = *(const float4*)&As[buf][k][ty * 8];
        float4 a1 = *(const float4*)&As[buf][k][ty * 8 + 4];
        float4 b0 = *(const float4*)&Bs[buf][k][tx * 8];
        float4 b1 = *(const float4*)&Bs[buf][k][tx * 8 + 4];
        float av[8] = {a0.x, a0.y, a0.z, a0.w, a1.x, a1.y, a1.z, a1.w};
        float bv[8] = {b0.x, b0.y, b0.z, b0.w, b1.x, b1.y, b1.z, b1.w};
#pragma unroll
        for (int i = 0; i < 8; ++i)
#pragma unroll
            for (int j = 0; j < 8; ++j) acc[i][j] = fmaf(av[i], bv[j], acc[i][j]);
    }

#pragma unroll
    for (int i = 0; i < 8; ++i) {
        int row = bm + ty * 8 + i;
        if (row < M) {
            float4 o0 = make_float4(acc[i][0], acc[i][1], acc[i][2], acc[i][3]);
            float4 o1 = make_float4(acc[i][4], acc[i][5], acc[i][6], acc[i][7]);
            *(float4*)(C + (size_t)row * N + bn + tx * 8)     = o0;
            *(float4*)(C + (size_t)row * N + bn + tx * 8 + 4) = o1;
        }
    }
}

// ---------------- attention logits: asrc[n,h] = h[n]·att_s[h], adst likewise ----------------
__global__ void att_kernel(const float* __restrict__ h, const float* __restrict__ att_s,
                           const float* __restrict__ att_d, float* __restrict__ asrc,
                           float* __restrict__ adst, int N) {
    int w = (blockIdx.x * blockDim.x + threadIdx.x) >> 5;
    int lane = threadIdx.x & 31;
    if (w >= N) return;
    const float4* hp = (const float4*)(h + (size_t)w * DIM);
    float4 v0 = hp[lane * 2], v1 = hp[lane * 2 + 1];
    const float4* sp = (const float4*)(att_s + lane * 8);
    const float4* dp = (const float4*)(att_d + lane * 8);
    float4 s0 = sp[0], s1 = sp[1], d0 = dp[0], d1 = dp[1];
    float ps = v0.x * s0.x + v0.y * s0.y + v0.z * s0.z + v0.w * s0.w +
               v1.x * s1.x + v1.y * s1.y + v1.z * s1.z + v1.w * s1.w;
    float pd = v0.x * d0.x + v0.y * d0.y + v0.z * d0.z + v0.w * d0.w +
               v1.x * d1.x + v1.y * d1.y + v1.z * d1.z + v1.w * d1.w;
#pragma unroll
    for (int o = 4; o; o >>= 1) {
        ps += __shfl_xor_sync(0xffffffffu, ps, o);
        pd += __shfl_xor_sync(0xffffffffu, pd, o);
    }
    if ((lane & 7) == 0) {
        asrc[w * 4 + (lane >> 3)] = ps;
        adst[w * 4 + (lane >> 3)] = pd;
    }
}

// ---------------- GAT aggregation: one warp per destination node (fused softmax) -------------
__global__ void aggregate_kernel(const float* __restrict__ h,
                                 const float* __restrict__ asrc,
                                 const float* __restrict__ adst,
                                 const int* __restrict__ indptr,
                                 const int* __restrict__ esrc,
                                 const float* __restrict__ bias,
                                 float* __restrict__ xout, int N) {
    int n = (blockIdx.x * blockDim.x + threadIdx.x) >> 5;
    int lane = threadIdx.x & 31;
    if (n >= N) return;
    int s0 = indptr[n], s1 = indptr[n + 1];

    float4 ad  = *(const float4*)(adst + 4 * n);
    float4 asn = *(const float4*)(asrc + 4 * n);
    float self0 = lrelu(asn.x + ad.x);
    float self1 = lrelu(asn.y + ad.y);
    float self2 = lrelu(asn.z + ad.z);
    float self3 = lrelu(asn.w + ad.w);

    // pass 1: per-head max over incoming edges (self-loop included)
    float m0 = self0, m1 = self1, m2 = self2, m3 = self3;
    for (int e = s0 + lane; e < s1; e += 32) {
        int s = esrc[e];
        float4 a = *(const float4*)(asrc + 4 * s);
        m0 = fmaxf(m0, lrelu(a.x + ad.x));
        m1 = fmaxf(m1, lrelu(a.y + ad.y));
        m2 = fmaxf(m2, lrelu(a.z + ad.z));
        m3 = fmaxf(m3, lrelu(a.w + ad.w));
    }
#pragma unroll
    for (int o = 16; o; o >>= 1) {
        m0 = fmaxf(m0, __shfl_xor_sync(0xffffffffu, m0, o));
        m1 = fmaxf(m1, __shfl_xor_sync(0xffffffffu, m1, o));
        m2 = fmaxf(m2, __shfl_xor_sync(0xffffffffu, m2, o));
        m3 = fmaxf(m3, __shfl_xor_sync(0xffffffffu, m3, o));
    }

    int head = lane >> 3;                    // this lane's 8 channels belong to one head
    float mh    = pick4(m0, m1, m2, m3, head);
    float adh   = pick4(ad.x, ad.y, ad.z, ad.w, head);
    float selfh = pick4(self0, self1, self2, self3, head);
    float wself = expf(selfh - mh);

    float acc[8];
    // self-loop contribution (unnormalized)
    {
        const float4* hp = (const float4*)(h + (size_t)n * DIM);
        float4 v0 = hp[lane * 2], v1 = hp[lane * 2 + 1];
        acc[0] = wself * v0.x; acc[1] = wself * v0.y; acc[2] = wself * v0.z; acc[3] = wself * v0.w;
        acc[4] = wself * v1.x; acc[5] = wself * v1.y; acc[6] = wself * v1.z; acc[7] = wself * v1.w;
    }

    // merged pass: unnormalized weighted accumulate + weight sum, 8 edges per warp-step
    float wsum = 0.f;
    for (int eb = s0; eb < s1; eb += 8) {
        int idx = eb + (lane & 7);
        float wv = 0.f;
        int sv = 0;
        if (idx < s1) {
            sv = esrc[idx];
            float a = __ldg(asrc + 4 * sv + head);
            wv = expf(lrelu(a + adh) - mh);
        }
        wsum += wv;
        int cnt = min(8, s1 - eb);
        for (int j = 0; j < cnt; ++j) {
            float wj = __shfl_sync(0xffffffffu, wv, (lane & 24) | j);
            int sj   = __shfl_sync(0xffffffffu, sv, j);
            const float4* hp = (const float4*)(h + (size_t)sj * DIM);
            float4 v0 = hp[lane * 2], v1 = hp[lane * 2 + 1];
            acc[0] += wj * v0.x; acc[1] += wj * v0.y; acc[2] += wj * v0.z; acc[3] += wj * v0.w;
            acc[4] += wj * v1.x; acc[5] += wj * v1.y; acc[6] += wj * v1.z; acc[7] += wj * v1.w;
        }
    }
    // reduce wsum within each head's 8-lane group
#pragma unroll
    for (int o = 4; o; o >>= 1) wsum += __shfl_xor_sync(0xffffffffu, wsum, o);
    float inv = 1.0f / (wsum + wself);

    // normalize + bias + ELU + store
    const float4* bp = (const float4*)(bias + lane * 8);
    float4 b0 = bp[0], b1 = bp[1];
    float4 o0, o1;
    o0.x = elu_f(acc[0] * inv + b0.x); o0.y = elu_f(acc[1] * inv + b0.y);
    o0.z = elu_f(acc[2] * inv + b0.z); o0.w = elu_f(acc[3] * inv + b0.w);
    o1.x = elu_f(acc[4] * inv + b1.x); o1.y = elu_f(acc[5] * inv + b1.y);
    o1.z = elu_f(acc[6] * inv + b1.z); o1.w = elu_f(acc[7] * inv + b1.w);
    float4* xo = (float4*)(xout + (size_t)n * DIM);
    xo[lane * 2] = o0;
    xo[lane * 2 + 1] = o1;
}

// ---------------- global add pool: one block per graph (batch is sorted) ----------------
__global__ void pool_kernel(const float* __restrict__ x, const int* __restrict__ batch,
                            float* __restrict__ emb, int N) {
    int g = blockIdx.x;
    int c = threadIdx.x;   // 256
    // first index with batch[i] >= g
    int lo = 0, hi = N;
    while (lo < hi) { int mid = (lo + hi) >> 1; if (batch[mid] < g) lo = mid + 1; else hi = mid; }
    int start = lo;
    hi = N;
    while (lo < hi) { int mid = (lo + hi) >> 1; if (batch[mid] < g + 1) lo = mid + 1; else hi = mid; }
    int end = lo;

    float a0 = 0.f, a1 = 0.f, a2 = 0.f, a3 = 0.f;
    int r = start;
    for (; r + 3 < end; r += 4) {
        a0 += x[(size_t)(r + 0) * DIM + c];
        a1 += x[(size_t)(r + 1) * DIM + c];
        a2 += x[(size_t)(r + 2) * DIM + c];
        a3 += x[(size_t)(r + 3) * DIM + c];
    }
    for (; r < end; ++r) a0 += x[(size_t)r * DIM + c];
    emb[(size_t)g * DIM + c] = (a0 + a1) + (a2 + a3);
}

// ---------------- final MLP per graph ----------------
__global__ void mlp_kernel(const float* __restrict__ hemb, const float* __restrict__ temb,
                           const float* __restrict__ kge, const int* __restrict__ rel,
                           const float* __restrict__ W1, const float* __restrict__ b1,
                           const float* __restrict__ W2, const float* __restrict__ b2,
                           float* __restrict__ out) {
    int g = blockIdx.x;
    int t = threadIdx.x;   // 64 threads
    __shared__ float z[2 * DIM + KGE_DIM];   // 576
    for (int i = t; i < DIM; i += 64) {
        z[i]       = hemb[(size_t)g * DIM + i];
        z[DIM + i] = temb[(size_t)g * DIM + i];
    }
    int r = rel[g];
    z[2 * DIM + t] = kge[(size_t)r * KGE_DIM + t];
    __syncthreads();

    float acc = b1[t];
#pragma unroll 4
    for (int k = 0; k < 2 * DIM + KGE_DIM; ++k)
        acc = fmaf(z[k], W1[(size_t)k * 64 + t], acc);
    acc = fmaxf(acc, 0.f) * W2[t];

#pragma unroll
    for (int o = 16; o; o >>= 1) acc += __shfl_xor_sync(0xffffffffu, acc, o);
    __shared__ float wsum[2];
    if ((t & 31) == 0) wsum[t >> 5] = acc;
    __syncthreads();
    if (t == 0) out[g] = wsum[0] + wsum[1] + b2[0];
}

// ---------------- launch ----------------
extern "C" void kernel_launch(void* const* d_in, const int* in_sizes, int n_in,
                              void* d_out, int out_size) {
    const float* head_x     = (const float*)d_in[0];
    const int*   head_ei    = (const int*)  d_in[1];
    const int*   head_batch = (const int*)  d_in[2];
    const float* tail_x     = (const float*)d_in[3];
    const int*   tail_ei    = (const int*)  d_in[4];
    const int*   tail_batch = (const int*)  d_in[5];
    const int*   rel        = (const int*)  d_in[6];
    const float* Ws         = (const float*)d_in[7];
    const float* att_s      = (const float*)d_in[8];
    const float* att_d      = (const float*)d_in[9];
    const float* biases     = (const float*)d_in[10];
    const float* kge        = (const float*)d_in[11];
    const float* W1         = (const float*)d_in[12];
    const float* b1         = (const float*)d_in[13];
    const float* W2         = (const float*)d_in[14];
    const float* b2         = (const float*)d_in[15];
    float* out = (float*)d_out;

    const int N = in_sizes[0] / DIM;    // 50000
    const int E = in_sizes[1] / 2;      // 800000
    const int B = in_sizes[6];          // 512

    float *p_h, *p_xa, *p_xb, *p_asrc, *p_adst, *p_hemb, *p_temb;
    int *p_deg, *p_indptr, *p_cursor, *p_esrc;
    cudaGetSymbolAddress((void**)&p_h, g_h);
    cudaGetSymbolAddress((void**)&p_xa, g_xa);
    cudaGetSymbolAddress((void**)&p_xb, g_xb);
    cudaGetSymbolAddress((void**)&p_asrc, g_asrc);
    cudaGetSymbolAddress((void**)&p_adst, g_adst);
    cudaGetSymbolAddress((void**)&p_hemb, g_hemb);
    cudaGetSymbolAddress((void**)&p_temb, g_temb);
    cudaGetSymbolAddress((void**)&p_deg, g_deg);
    cudaGetSymbolAddress((void**)&p_indptr, g_indptr);
    cudaGetSymbolAddress((void**)&p_cursor, g_cursor);
    cudaGetSymbolAddress((void**)&p_esrc, g_esrc);

    const int wblocks = (N * 32 + 255) / 256;

    for (int enc = 0; enc < 2; ++enc) {
        const float* x0    = enc ? tail_x : head_x;
        const int*   ei    = enc ? tail_ei : head_ei;
        const int*   batch = enc ? tail_batch : head_batch;
        float*       emb   = enc ? p_temb : p_hemb;

        // build CSR by dst (counting sort)
        cudaMemsetAsync(p_deg, 0, (size_t)N * sizeof(int));
        hist_kernel<<<(E + 255) / 256, 256>>>(ei + E, E, p_deg);
        scan_kernel<<<1, 1024>>>(p_deg, p_indptr, p_cursor, N);
        scatter_kernel<<<(E + 255) / 256, 256>>>(ei, ei + E, E, p_cursor, p_esrc);

        const float* xin = x0;
        float* bufs[2] = {p_xa, p_xb};
        for (int l = 0; l < 3; ++l) {
            dim3 gg((unsigned)((N + 127) / 128), 2);
            gemm_kernel<<<gg, 256>>>(xin, Ws + (size_t)l * DIM * DIM, p_h, N);
            att_kernel<<<wblocks, 256>>>(p_h, att_s + l * HEADS * HID,
                                         att_d + l * HEADS * HID, p_asrc, p_adst, N);
            aggregate_kernel<<<wblocks, 256>>>(p_h, p_asrc, p_adst, p_indptr, p_esrc,
                                               biases + l * DIM, bufs[l & 1], N);
            xin = bufs[l & 1];
        }

        pool_kernel<<<N_GRAPHS_C, 256>>>(xin, batch, emb, N);
    }

    mlp_kernel<<<B, 64>>>(p_hemb, p_temb, kge, rel, W1, b1, W2, b2, out);
}

// round 3
// speedup vs baseline: 1.2467x; 1.2292x over previous
#include <cuda_runtime.h>
#include <cuda_bf16.h>
#include <math.h>
#include <stdint.h>

#define N_NODES_C 50000
#define N_EDGES_C 800000
#define N_GRAPHS_C 512
#define DIM 256
#define HEADS 4
#define HID 64
#define KGE_DIM 64

// ---------------- static device scratch (no allocations allowed) ----------------
__device__ float g_h  [N_NODES_C * DIM];
__device__ float g_xa [N_NODES_C * DIM];
__device__ float g_xb [N_NODES_C * DIM];
__device__ float g_asrc[N_NODES_C * HEADS];
__device__ float g_adst[N_NODES_C * HEADS];
__device__ int   g_deg   [N_NODES_C];
__device__ int   g_indptr[N_NODES_C + 1];
__device__ int   g_cursor[N_NODES_C];
__device__ int   g_esrc  [N_EDGES_C];
__device__ float g_hemb[N_GRAPHS_C * DIM];
__device__ float g_temb[N_GRAPHS_C * DIM];
__device__ __nv_bfloat16 g_whi[3 * DIM * DIM];   // W transposed [l][n][k], hi part
__device__ __nv_bfloat16 g_wlo[3 * DIM * DIM];   // lo part

__device__ __forceinline__ float lrelu(float x) { return x > 0.f ? x : 0.2f * x; }
__device__ __forceinline__ float elu_f(float x) { return x > 0.f ? x : expm1f(x); }
__device__ __forceinline__ float pick4(float a, float b, float c, float d, int h) {
    return h == 0 ? a : (h == 1 ? b : (h == 2 ? c : d));
}
__device__ __forceinline__ uint32_t pack_bf16(__nv_bfloat16 lo, __nv_bfloat16 hi) {
    return (uint32_t)__bfloat16_as_ushort(lo) | ((uint32_t)__bfloat16_as_ushort(hi) << 16);
}

#define MMA16816(d, a0, a1, a2, a3, b0, b1)                                     \
    asm volatile("mma.sync.aligned.m16n8k16.row.col.f32.bf16.bf16.f32 "         \
                 "{%0,%1,%2,%3}, {%4,%5,%6,%7}, {%8,%9}, {%0,%1,%2,%3};"        \
                 : "+f"(d[0]), "+f"(d[1]), "+f"(d[2]), "+f"(d[3])               \
                 : "r"(a0), "r"(a1), "r"(a2), "r"(a3), "r"(b0), "r"(b1))

// ---------------- CSR build (counting sort by dst) ----------------
__global__ void hist_kernel(const int* __restrict__ dst, int E, int* __restrict__ deg) {
    int e = blockIdx.x * blockDim.x + threadIdx.x;
    if (e < E) atomicAdd(&deg[dst[e]], 1);
}

// single-block warp-shuffle scan: 4096 elements per iteration
__global__ void scan_kernel(const int* __restrict__ deg, int* __restrict__ indptr,
                            int* __restrict__ cursor, int n) {
    __shared__ int wsum[32];
    __shared__ int carry_s;
    int tid = threadIdx.x, lane = tid & 31, wid = tid >> 5;
    if (tid == 0) carry_s = 0;
    __syncthreads();
    for (int base = 0; base < n; base += 4096) {
        int i0 = base + tid * 4;
        int v0 = (i0 + 0 < n) ? deg[i0 + 0] : 0;
        int v1 = (i0 + 1 < n) ? deg[i0 + 1] : 0;
        int v2 = (i0 + 2 < n) ? deg[i0 + 2] : 0;
        int v3 = (i0 + 3 < n) ? deg[i0 + 3] : 0;
        int s = v0 + v1 + v2 + v3;
        int ps = s;
#pragma unroll
        for (int o = 1; o < 32; o <<= 1) {
            int t = __shfl_up_sync(0xffffffffu, ps, o);
            if (lane >= o) ps += t;
        }
        if (lane == 31) wsum[wid] = ps;
        __syncthreads();
        if (wid == 0) {
            int w = wsum[lane];
            int pw = w;
#pragma unroll
            for (int o = 1; o < 32; o <<= 1) {
                int t = __shfl_up_sync(0xffffffffu, pw, o);
                if (lane >= o) pw += t;
            }
            wsum[lane] = pw;
        }
        __syncthreads();
        int woff = wid ? wsum[wid - 1] : 0;
        int run = carry_s + woff + ps - s;
        if (i0 + 0 < n) { indptr[i0 + 0] = run; cursor[i0 + 0] = run; } run += v0;
        if (i0 + 1 < n) { indptr[i0 + 1] = run; cursor[i0 + 1] = run; } run += v1;
        if (i0 + 2 < n) { indptr[i0 + 2] = run; cursor[i0 + 2] = run; } run += v2;
        if (i0 + 3 < n) { indptr[i0 + 3] = run; cursor[i0 + 3] = run; }
        __syncthreads();
        if (tid == 0) carry_s += wsum[31];
        __syncthreads();
    }
    if (tid == 0) indptr[n] = carry_s;
}

__global__ void scatter_kernel(const int* __restrict__ src, const int* __restrict__ dst,
                               int E, int* __restrict__ cursor, int* __restrict__ esrc) {
    int e = blockIdx.x * blockDim.x + threadIdx.x;
    if (e < E) {
        int pos = atomicAdd(&cursor[dst[e]], 1);
        esrc[pos] = src[e];
    }
}

// ---------------- W pre-convert: fp32 [l][k][n] -> bf16 hi/lo transposed [l][n][k] ----------
__global__ void wconv_kernel(const float* __restrict__ W,
                             __nv_bfloat16* __restrict__ whi,
                             __nv_bfloat16* __restrict__ wlo) {
    int l = blockIdx.x >> 8;
    int n = blockIdx.x & 255;
    int k = threadIdx.x;
    float w = W[((size_t)l * 256 + k) * 256 + n];
    __nv_bfloat16 h = __float2bfloat16(w);
    float rem = w - __bfloat162float(h);
    whi[((size_t)l * 256 + n) * 256 + k] = h;
    wlo[((size_t)l * 256 + n) * 256 + k] = __float2bfloat16(rem);
}

// ---------------- tensor-core GEMM: C[M,256] = A[M,256] @ W[256,256] (bf16x3 split) --------
// block tile 128x64, BK=16, 8 warps of 32x32, double-buffered smem, direct lds fragments.
__global__ __launch_bounds__(256) void gemm_tc_kernel(const float* __restrict__ A,
                                                      const __nv_bfloat16* __restrict__ Bhi,
                                                      const __nv_bfloat16* __restrict__ Blo,
                                                      float* __restrict__ C, int M) {
    constexpr int LDS = 24;   // row stride in bf16 (16 data + 8 pad) -> conflict-free frags
    __shared__ __nv_bfloat16 sAhi[2][128 * LDS];
    __shared__ __nv_bfloat16 sAlo[2][128 * LDS];
    __shared__ __nv_bfloat16 sBhi[2][64 * LDS];
    __shared__ __nv_bfloat16 sBlo[2][64 * LDS];

    const int tid = threadIdx.x;
    const int bm = blockIdx.x * 128;
    const int bn = blockIdx.y * 64;

    // global load assignments
    const int arow = tid >> 1, akoff = (tid & 1) * 8;
    const int brow = tid >> 2, bkoff = (tid & 3) * 4;
    const bool aval = (bm + arow) < M;
    const float* Ap = A + (size_t)(bm + arow) * 256 + akoff;
    const __nv_bfloat16* Bhp = Bhi + (size_t)(bn + brow) * 256 + bkoff;
    const __nv_bfloat16* Blp = Blo + (size_t)(bn + brow) * 256 + bkoff;

    float a_st[8];
    uint2 bh_st, bl_st;

    const int lane = tid & 31, wid = tid >> 5;
    const int wm = (wid & 3) * 32;
    const int wn = (wid >> 2) * 32;
    const int gid = lane >> 2, tig = lane & 3;

    float acc[2][4][4];
#pragma unroll
    for (int mi = 0; mi < 2; ++mi)
#pragma unroll
        for (int ni = 0; ni < 4; ++ni)
#pragma unroll
            for (int j = 0; j < 4; ++j) acc[mi][ni][j] = 0.f;

#define LOAD_G(c)                                                          \
    do {                                                                   \
        int k0_ = (c) * 16;                                                \
        if (aval) {                                                        \
            float4 t0 = *(const float4*)(Ap + k0_);                        \
            float4 t1 = *(const float4*)(Ap + k0_ + 4);                    \
            a_st[0] = t0.x; a_st[1] = t0.y; a_st[2] = t0.z; a_st[3] = t0.w;\
            a_st[4] = t1.x; a_st[5] = t1.y; a_st[6] = t1.z; a_st[7] = t1.w;\
        } else {                                                           \
            for (int j = 0; j < 8; ++j) a_st[j] = 0.f;                     \
        }                                                                  \
        bh_st = *(const uint2*)(Bhp + k0_);                                \
        bl_st = *(const uint2*)(Blp + k0_);                                \
    } while (0)

#define STORE_S(b)                                                         \
    do {                                                                   \
        __nv_bfloat16 h_[8], l_[8];                                        \
        for (int j = 0; j < 8; ++j) {                                      \
            h_[j] = __float2bfloat16(a_st[j]);                             \
            l_[j] = __float2bfloat16(a_st[j] - __bfloat162float(h_[j]));   \
        }                                                                  \
        uint2 uh0, ul0;                                                    \
        uh0.x = pack_bf16(h_[0], h_[1]); uh0.y = pack_bf16(h_[2], h_[3]);  \
        ul0.x = pack_bf16(l_[0], l_[1]); ul0.y = pack_bf16(l_[2], l_[3]);  \
        uint2 uh1, ul1;                                                    \
        uh1.x = pack_bf16(h_[4], h_[5]); uh1.y = pack_bf16(h_[6], h_[7]);  \
        ul1.x = pack_bf16(l_[4], l_[5]); ul1.y = pack_bf16(l_[6], l_[7]);  \
        *(uint2*)&sAhi[b][arow * LDS + akoff]     = uh0;                   \
        *(uint2*)&sAhi[b][arow * LDS + akoff + 4] = uh1;                   \
        *(uint2*)&sAlo[b][arow * LDS + akoff]     = ul0;                   \
        *(uint2*)&sAlo[b][arow * LDS + akoff + 4] = ul1;                   \
        *(uint2*)&sBhi[b][brow * LDS + bkoff] = bh_st;                     \
        *(uint2*)&sBlo[b][brow * LDS + bkoff] = bl_st;                     \
    } while (0)

#define COMPUTE(b)                                                          \
    do {                                                                    \
        uint32_t bh[4][2], bl[4][2];                                        \
        _Pragma("unroll")                                                   \
        for (int ni = 0; ni < 4; ++ni) {                                    \
            int n_ = (wn + ni * 8 + gid) * LDS + tig * 2;                   \
            bh[ni][0] = *(const uint32_t*)&sBhi[b][n_];                     \
            bh[ni][1] = *(const uint32_t*)&sBhi[b][n_ + 8];                 \
            bl[ni][0] = *(const uint32_t*)&sBlo[b][n_];                     \
            bl[ni][1] = *(const uint32_t*)&sBlo[b][n_ + 8];                 \
        }                                                                   \
        _Pragma("unroll")                                                   \
        for (int mi = 0; mi < 2; ++mi) {                                    \
            int r_ = (wm + mi * 16 + gid) * LDS + tig * 2;                  \
            uint32_t ah[4], al[4];                                          \
            ah[0] = *(const uint32_t*)&sAhi[b][r_];                         \
            ah[1] = *(const uint32_t*)&sAhi[b][r_ + 8 * LDS];               \
            ah[2] = *(const uint32_t*)&sAhi[b][r_ + 8];                     \
            ah[3] = *(const uint32_t*)&sAhi[b][r_ + 8 * LDS + 8];           \
            al[0] = *(const uint32_t*)&sAlo[b][r_];                         \
            al[1] = *(const uint32_t*)&sAlo[b][r_ + 8 * LDS];               \
            al[2] = *(const uint32_t*)&sAlo[b][r_ + 8];                     \
            al[3] = *(const uint32_t*)&sAlo[b][r_ + 8 * LDS + 8];           \
            _Pragma("unroll")                                               \
            for (int ni = 0; ni < 4; ++ni) {                                \
                MMA16816(acc[mi][ni], ah[0], ah[1], ah[2], ah[3],           \
                         bh[ni][0], bh[ni][1]);                             \
                MMA16816(acc[mi][ni], ah[0], ah[1], ah[2], ah[3],           \
                         bl[ni][0], bl[ni][1]);                             \
                MMA16816(acc[mi][ni], al[0], al[1], al[2], al[3],           \
                         bh[ni][0], bh[ni][1]);                             \
            }                                                               \
        }                                                                   \
    } while (0)

    LOAD_G(0);
    STORE_S(0);
    __syncthreads();

    int buf = 0;
#pragma unroll 1
    for (int c = 0; c < 16; ++c) {
        if (c < 15) LOAD_G(c + 1);
        COMPUTE(buf);
        if (c < 15) {
            STORE_S(buf ^ 1);
            __syncthreads();
            buf ^= 1;
        }
    }

    // epilogue
#pragma unroll
    for (int mi = 0; mi < 2; ++mi)
#pragma unroll
        for (int ni = 0; ni < 4; ++ni) {
            int r0 = bm + wm + mi * 16 + gid;
            int col = bn + wn + ni * 8 + tig * 2;
            if (r0 < M) {
                float2 v = make_float2(acc[mi][ni][0], acc[mi][ni][1]);
                *(float2*)&C[(size_t)r0 * 256 + col] = v;
            }
            if (r0 + 8 < M) {
                float2 v = make_float2(acc[mi][ni][2], acc[mi][ni][3]);
                *(float2*)&C[(size_t)(r0 + 8) * 256 + col] = v;
            }
        }
#undef LOAD_G
#undef STORE_S
#undef COMPUTE
}

// ---------------- attention logits: asrc[n,h] = h[n]·att_s[h], adst likewise ----------------
__global__ void att_kernel(const float* __restrict__ h, const float* __restrict__ att_s,
                           const float* __restrict__ att_d, float* __restrict__ asrc,
                           float* __restrict__ adst, int N) {
    int w = (blockIdx.x * blockDim.x + threadIdx.x) >> 5;
    int lane = threadIdx.x & 31;
    if (w >= N) return;
    const float4* hp = (const float4*)(h + (size_t)w * DIM);
    float4 v0 = hp[lane * 2], v1 = hp[lane * 2 + 1];
    const float4* sp = (const float4*)(att_s + lane * 8);
    const float4* dp = (const float4*)(att_d + lane * 8);
    float4 s0 = sp[0], s1 = sp[1], d0 = dp[0], d1 = dp[1];
    float ps = v0.x * s0.x + v0.y * s0.y + v0.z * s0.z + v0.w * s0.w +
               v1.x * s1.x + v1.y * s1.y + v1.z * s1.z + v1.w * s1.w;
    float pd = v0.x * d0.x + v0.y * d0.y + v0.z * d0.z + v0.w * d0.w +
               v1.x * d1.x + v1.y * d1.y + v1.z * d1.z + v1.w * d1.w;
#pragma unroll
    for (int o = 4; o; o >>= 1) {
        ps += __shfl_xor_sync(0xffffffffu, ps, o);
        pd += __shfl_xor_sync(0xffffffffu, pd, o);
    }
    if ((lane & 7) == 0) {
        asrc[w * 4 + (lane >> 3)] = ps;
        adst[w * 4 + (lane >> 3)] = pd;
    }
}

// ---------------- GAT aggregation: one warp per destination node (fused softmax) -------------
__global__ void aggregate_kernel(const float* __restrict__ h,
                                 const float* __restrict__ asrc,
                                 const float* __restrict__ adst,
                                 const int* __restrict__ indptr,
                                 const int* __restrict__ esrc,
                                 const float* __restrict__ bias,
                                 float* __restrict__ xout, int N) {
    int n = (blockIdx.x * blockDim.x + threadIdx.x) >> 5;
    int lane = threadIdx.x & 31;
    if (n >= N) return;
    int s0 = indptr[n], s1 = indptr[n + 1];

    float4 ad  = *(const float4*)(adst + 4 * n);
    float4 asn = *(const float4*)(asrc + 4 * n);
    float self0 = lrelu(asn.x + ad.x);
    float self1 = lrelu(asn.y + ad.y);
    float self2 = lrelu(asn.z + ad.z);
    float self3 = lrelu(asn.w + ad.w);

    // pass 1: per-head max over incoming edges (self-loop included)
    float m0 = self0, m1 = self1, m2 = self2, m3 = self3;
    for (int e = s0 + lane; e < s1; e += 32) {
        int s = esrc[e];
        float4 a = *(const float4*)(asrc + 4 * s);
        m0 = fmaxf(m0, lrelu(a.x + ad.x));
        m1 = fmaxf(m1, lrelu(a.y + ad.y));
        m2 = fmaxf(m2, lrelu(a.z + ad.z));
        m3 = fmaxf(m3, lrelu(a.w + ad.w));
    }
#pragma unroll
    for (int o = 16; o; o >>= 1) {
        m0 = fmaxf(m0, __shfl_xor_sync(0xffffffffu, m0, o));
        m1 = fmaxf(m1, __shfl_xor_sync(0xffffffffu, m1, o));
        m2 = fmaxf(m2, __shfl_xor_sync(0xffffffffu, m2, o));
        m3 = fmaxf(m3, __shfl_xor_sync(0xffffffffu, m3, o));
    }

    int head = lane >> 3;
    float mh    = pick4(m0, m1, m2, m3, head);
    float adh   = pick4(ad.x, ad.y, ad.z, ad.w, head);
    float selfh = pick4(self0, self1, self2, self3, head);
    float wself = expf(selfh - mh);

    float acc[8];
    {
        const float4* hp = (const float4*)(h + (size_t)n * DIM);
        float4 v0 = hp[lane * 2], v1 = hp[lane * 2 + 1];
        acc[0] = wself * v0.x; acc[1] = wself * v0.y; acc[2] = wself * v0.z; acc[3] = wself * v0.w;
        acc[4] = wself * v1.x; acc[5] = wself * v1.y; acc[6] = wself * v1.z; acc[7] = wself * v1.w;
    }

    float wsum = 0.f;
    for (int eb = s0; eb < s1; eb += 8) {
        int idx = eb + (lane & 7);
        float wv = 0.f;
        int sv = 0;
        if (idx < s1) {
            sv = esrc[idx];
            float a = __ldg(asrc + 4 * sv + head);
            wv = expf(lrelu(a + adh) - mh);
        }
        wsum += wv;
        int cnt = min(8, s1 - eb);
        for (int j = 0; j < cnt; ++j) {
            float wj = __shfl_sync(0xffffffffu, wv, (lane & 24) | j);
            int sj   = __shfl_sync(0xffffffffu, sv, j);
            const float4* hp = (const float4*)(h + (size_t)sj * DIM);
            float4 v0 = hp[lane * 2], v1 = hp[lane * 2 + 1];
            acc[0] += wj * v0.x; acc[1] += wj * v0.y; acc[2] += wj * v0.z; acc[3] += wj * v0.w;
            acc[4] += wj * v1.x; acc[5] += wj * v1.y; acc[6] += wj * v1.z; acc[7] += wj * v1.w;
        }
    }
#pragma unroll
    for (int o = 4; o; o >>= 1) wsum += __shfl_xor_sync(0xffffffffu, wsum, o);
    float inv = 1.0f / (wsum + wself);

    const float4* bp = (const float4*)(bias + lane * 8);
    float4 b0 = bp[0], b1 = bp[1];
    float4 o0, o1;
    o0.x = elu_f(acc[0] * inv + b0.x); o0.y = elu_f(acc[1] * inv + b0.y);
    o0.z = elu_f(acc[2] * inv + b0.z); o0.w = elu_f(acc[3] * inv + b0.w);
    o1.x = elu_f(acc[4] * inv + b1.x); o1.y = elu_f(acc[5] * inv + b1.y);
    o1.z = elu_f(acc[6] * inv + b1.z); o1.w = elu_f(acc[7] * inv + b1.w);
    float4* xo = (float4*)(xout + (size_t)n * DIM);
    xo[lane * 2] = o0;
    xo[lane * 2 + 1] = o1;
}

// ---------------- global add pool: one block per graph (batch is sorted) ----------------
__global__ void pool_kernel(const float* __restrict__ x, const int* __restrict__ batch,
                            float* __restrict__ emb, int N) {
    int g = blockIdx.x;
    int c = threadIdx.x;
    int lo = 0, hi = N;
    while (lo < hi) { int mid = (lo + hi) >> 1; if (batch[mid] < g) lo = mid + 1; else hi = mid; }
    int start = lo;
    hi = N;
    while (lo < hi) { int mid = (lo + hi) >> 1; if (batch[mid] < g + 1) lo = mid + 1; else hi = mid; }
    int end = lo;

    float a0 = 0.f, a1 = 0.f, a2 = 0.f, a3 = 0.f;
    int r = start;
    for (; r + 3 < end; r += 4) {
        a0 += x[(size_t)(r + 0) * DIM + c];
        a1 += x[(size_t)(r + 1) * DIM + c];
        a2 += x[(size_t)(r + 2) * DIM + c];
        a3 += x[(size_t)(r + 3) * DIM + c];
    }
    for (; r < end; ++r) a0 += x[(size_t)r * DIM + c];
    emb[(size_t)g * DIM + c] = (a0 + a1) + (a2 + a3);
}

// ---------------- final MLP per graph ----------------
__global__ void mlp_kernel(const float* __restrict__ hemb, const float* __restrict__ temb,
                           const float* __restrict__ kge, const int* __restrict__ rel,
                           const float* __restrict__ W1, const float* __restrict__ b1,
                           const float* __restrict__ W2, const float* __restrict__ b2,
                           float* __restrict__ out) {
    int g = blockIdx.x;
    int t = threadIdx.x;
    __shared__ float z[2 * DIM + KGE_DIM];
    for (int i = t; i < DIM; i += 64) {
        z[i]       = hemb[(size_t)g * DIM + i];
        z[DIM + i] = temb[(size_t)g * DIM + i];
    }
    int r = rel[g];
    z[2 * DIM + t] = kge[(size_t)r * KGE_DIM + t];
    __syncthreads();

    float acc = b1[t];
#pragma unroll 4
    for (int k = 0; k < 2 * DIM + KGE_DIM; ++k)
        acc = fmaf(z[k], W1[(size_t)k * 64 + t], acc);
    acc = fmaxf(acc, 0.f) * W2[t];

#pragma unroll
    for (int o = 16; o; o >>= 1) acc += __shfl_xor_sync(0xffffffffu, acc, o);
    __shared__ float wsum[2];
    if ((t & 31) == 0) wsum[t >> 5] = acc;
    __syncthreads();
    if (t == 0) out[g] = wsum[0] + wsum[1] + b2[0];
}

// ---------------- launch ----------------
extern "C" void kernel_launch(void* const* d_in, const int* in_sizes, int n_in,
                              void* d_out, int out_size) {
    const float* head_x     = (const float*)d_in[0];
    const int*   head_ei    = (const int*)  d_in[1];
    const int*   head_batch = (const int*)  d_in[2];
    const float* tail_x     = (const float*)d_in[3];
    const int*   tail_ei    = (const int*)  d_in[4];
    const int*   tail_batch = (const int*)  d_in[5];
    const int*   rel        = (const int*)  d_in[6];
    const float* Ws         = (const float*)d_in[7];
    const float* att_s      = (const float*)d_in[8];
    const float* att_d      = (const float*)d_in[9];
    const float* biases     = (const float*)d_in[10];
    const float* kge        = (const float*)d_in[11];
    const float* W1         = (const float*)d_in[12];
    const float* b1         = (const float*)d_in[13];
    const float* W2         = (const float*)d_in[14];
    const float* b2         = (const float*)d_in[15];
    float* out = (float*)d_out;

    const int N = in_sizes[0] / DIM;    // 50000
    const int E = in_sizes[1] / 2;      // 800000
    const int B = in_sizes[6];          // 512

    float *p_h, *p_xa, *p_xb, *p_asrc, *p_adst, *p_hemb, *p_temb;
    int *p_deg, *p_indptr, *p_cursor, *p_esrc;
    __nv_bfloat16 *p_whi, *p_wlo;
    cudaGetSymbolAddress((void**)&p_h, g_h);
    cudaGetSymbolAddress((void**)&p_xa, g_xa);
    cudaGetSymbolAddress((void**)&p_xb, g_xb);
    cudaGetSymbolAddress((void**)&p_asrc, g_asrc);
    cudaGetSymbolAddress((void**)&p_adst, g_adst);
    cudaGetSymbolAddress((void**)&p_hemb, g_hemb);
    cudaGetSymbolAddress((void**)&p_temb, g_temb);
    cudaGetSymbolAddress((void**)&p_deg, g_deg);
    cudaGetSymbolAddress((void**)&p_indptr, g_indptr);
    cudaGetSymbolAddress((void**)&p_cursor, g_cursor);
    cudaGetSymbolAddress((void**)&p_esrc, g_esrc);
    cudaGetSymbolAddress((void**)&p_whi, g_whi);
    cudaGetSymbolAddress((void**)&p_wlo, g_wlo);

    const int wblocks = (N * 32 + 255) / 256;

    // pre-convert the 3 layer weights to transposed bf16 hi/lo
    wconv_kernel<<<3 * 256, 256>>>(Ws, p_whi, p_wlo);

    for (int enc = 0; enc < 2; ++enc) {
        const float* x0    = enc ? tail_x : head_x;
        const int*   ei    = enc ? tail_ei : head_ei;
        const int*   batch = enc ? tail_batch : head_batch;
        float*       emb   = enc ? p_temb : p_hemb;

        cudaMemsetAsync(p_deg, 0, (size_t)N * sizeof(int));
        hist_kernel<<<(E + 255) / 256, 256>>>(ei + E, E, p_deg);
        scan_kernel<<<1, 1024>>>(p_deg, p_indptr, p_cursor, N);
        scatter_kernel<<<(E + 255) / 256, 256>>>(ei, ei + E, E, p_cursor, p_esrc);

        const float* xin = x0;
        float* bufs[2] = {p_xa, p_xb};
        for (int l = 0; l < 3; ++l) {
            dim3 gg((unsigned)((N + 127) / 128), 4);
            gemm_tc_kernel<<<gg, 256>>>(xin, p_whi + (size_t)l * DIM * DIM,
                                        p_wlo + (size_t)l * DIM * DIM, p_h, N);
            att_kernel<<<wblocks, 256>>>(p_h, att_s + l * HEADS * HID,
                                         att_d + l * HEADS * HID, p_asrc, p_adst, N);
            aggregate_kernel<<<wblocks, 256>>>(p_h, p_asrc, p_adst, p_indptr, p_esrc,
                                               biases + l * DIM, bufs[l & 1], N);
            xin = bufs[l & 1];
        }

        pool_kernel<<<N_GRAPHS_C, 256>>>(xin, batch, emb, N);
    }

    mlp_kernel<<<B, 64>>>(p_hemb, p_temb, kge, rel, W1, b1, W2, b2, out);
}

// round 4
// speedup vs baseline: 1.3710x; 1.0997x over previous
#include <cuda_runtime.h>
#include <cuda_bf16.h>
#include <math.h>
#include <stdint.h>

#define N_NODES_C 50000
#define N_EDGES_C 800000
#define N_GRAPHS_C 512
#define DIM 256
#define HEADS 4
#define HID 64
#define KGE_DIM 64

// ---------------- static device scratch (no allocations allowed) ----------------
__device__ float g_h  [N_NODES_C * DIM];
__device__ float g_xa [N_NODES_C * DIM];
__device__ float g_xb [N_NODES_C * DIM];
__device__ float g_alog[N_NODES_C * 2 * HEADS];   // [asrc | adst], contiguous for one memset
__device__ int   g_deg   [N_NODES_C];
__device__ int   g_indptr[N_NODES_C + 1];
__device__ int   g_cursor[N_NODES_C];
__device__ int   g_esrc  [N_EDGES_C];
__device__ float g_hemb[N_GRAPHS_C * DIM];
__device__ float g_temb[N_GRAPHS_C * DIM];
__device__ __nv_bfloat16 g_whi[3 * DIM * DIM];   // W transposed [l][n][k], hi part
__device__ __nv_bfloat16 g_wlo[3 * DIM * DIM];   // lo part

__device__ __forceinline__ float lrelu(float x) { return x > 0.f ? x : 0.2f * x; }
__device__ __forceinline__ float elu_f(float x) { return x > 0.f ? x : expm1f(x); }
__device__ __forceinline__ float pick4(float a, float b, float c, float d, int h) {
    return h == 0 ? a : (h == 1 ? b : (h == 2 ? c : d));
}
__device__ __forceinline__ uint32_t pack_bf16(__nv_bfloat16 lo, __nv_bfloat16 hi) {
    return (uint32_t)__bfloat16_as_ushort(lo) | ((uint32_t)__bfloat16_as_ushort(hi) << 16);
}

#define MMA16816(d, a0, a1, a2, a3, b0, b1)                                     \
    asm volatile("mma.sync.aligned.m16n8k16.row.col.f32.bf16.bf16.f32 "         \
                 "{%0,%1,%2,%3}, {%4,%5,%6,%7}, {%8,%9}, {%0,%1,%2,%3};"        \
                 : "+f"(d[0]), "+f"(d[1]), "+f"(d[2]), "+f"(d[3])               \
                 : "r"(a0), "r"(a1), "r"(a2), "r"(a3), "r"(b0), "r"(b1))

// ---------------- CSR build (counting sort by dst) ----------------
__global__ void hist_kernel(const int* __restrict__ dst, int E, int* __restrict__ deg) {
    int e = blockIdx.x * blockDim.x + threadIdx.x;
    if (e < E) atomicAdd(&deg[dst[e]], 1);
}

// single-block warp-shuffle scan: 4096 elements per iteration
__global__ void scan_kernel(const int* __restrict__ deg, int* __restrict__ indptr,
                            int* __restrict__ cursor, int n) {
    __shared__ int wsum[32];
    __shared__ int carry_s;
    int tid = threadIdx.x, lane = tid & 31, wid = tid >> 5;
    if (tid == 0) carry_s = 0;
    __syncthreads();
    for (int base = 0; base < n; base += 4096) {
        int i0 = base + tid * 4;
        int v0 = (i0 + 0 < n) ? deg[i0 + 0] : 0;
        int v1 = (i0 + 1 < n) ? deg[i0 + 1] : 0;
        int v2 = (i0 + 2 < n) ? deg[i0 + 2] : 0;
        int v3 = (i0 + 3 < n) ? deg[i0 + 3] : 0;
        int s = v0 + v1 + v2 + v3;
        int ps = s;
#pragma unroll
        for (int o = 1; o < 32; o <<= 1) {
            int t = __shfl_up_sync(0xffffffffu, ps, o);
            if (lane >= o) ps += t;
        }
        if (lane == 31) wsum[wid] = ps;
        __syncthreads();
        if (wid == 0) {
            int w = wsum[lane];
            int pw = w;
#pragma unroll
            for (int o = 1; o < 32; o <<= 1) {
                int t = __shfl_up_sync(0xffffffffu, pw, o);
                if (lane >= o) pw += t;
            }
            wsum[lane] = pw;
        }
        __syncthreads();
        int woff = wid ? wsum[wid - 1] : 0;
        int run = carry_s + woff + ps - s;
        if (i0 + 0 < n) { indptr[i0 + 0] = run; cursor[i0 + 0] = run; } run += v0;
        if (i0 + 1 < n) { indptr[i0 + 1] = run; cursor[i0 + 1] = run; } run += v1;
        if (i0 + 2 < n) { indptr[i0 + 2] = run; cursor[i0 + 2] = run; } run += v2;
        if (i0 + 3 < n) { indptr[i0 + 3] = run; cursor[i0 + 3] = run; }
        __syncthreads();
        if (tid == 0) carry_s += wsum[31];
        __syncthreads();
    }
    if (tid == 0) indptr[n] = carry_s;
}

__global__ void scatter_kernel(const int* __restrict__ src, const int* __restrict__ dst,
                               int E, int* __restrict__ cursor, int* __restrict__ esrc) {
    int e = blockIdx.x * blockDim.x + threadIdx.x;
    if (e < E) {
        int pos = atomicAdd(&cursor[dst[e]], 1);
        esrc[pos] = src[e];
    }
}

// ---------------- W pre-convert: fp32 [l][k][n] -> bf16 hi/lo transposed [l][n][k] ----------
__global__ void wconv_kernel(const float* __restrict__ W,
                             __nv_bfloat16* __restrict__ whi,
                             __nv_bfloat16* __restrict__ wlo) {
    int l = blockIdx.x >> 8;
    int n = blockIdx.x & 255;
    int k = threadIdx.x;
    float w = W[((size_t)l * 256 + k) * 256 + n];
    __nv_bfloat16 h = __float2bfloat16(w);
    float rem = w - __bfloat162float(h);
    whi[((size_t)l * 256 + n) * 256 + k] = h;
    wlo[((size_t)l * 256 + n) * 256 + k] = __float2bfloat16(rem);
}

// ---------------- tensor-core GEMM + fused attention-logit epilogue --------------------------
// C[M,256] = A[M,256] @ W[256,256] (bf16x3 split). Each 64-col block tile == one head, so the
// epilogue reduces acc·att_src / acc·att_dst per row and atomically accumulates into alog.
__global__ __launch_bounds__(256) void gemm_tc_kernel(const float* __restrict__ A,
                                                      const __nv_bfloat16* __restrict__ Bhi,
                                                      const __nv_bfloat16* __restrict__ Blo,
                                                      float* __restrict__ C,
                                                      const float* __restrict__ att_s,
                                                      const float* __restrict__ att_d,
                                                      float* __restrict__ alog, int M) {
    constexpr int LDS = 24;
    __shared__ __nv_bfloat16 sAhi[2][128 * LDS];
    __shared__ __nv_bfloat16 sAlo[2][128 * LDS];
    __shared__ __nv_bfloat16 sBhi[2][64 * LDS];
    __shared__ __nv_bfloat16 sBlo[2][64 * LDS];

    const int tid = threadIdx.x;
    const int bm = blockIdx.x * 128;
    const int bn = blockIdx.y * 64;
    const int head = blockIdx.y;          // 64-col tile == one head

    const int arow = tid >> 1, akoff = (tid & 1) * 8;
    const int brow = tid >> 2, bkoff = (tid & 3) * 4;
    const bool aval = (bm + arow) < M;
    const float* Ap = A + (size_t)(bm + arow) * 256 + akoff;
    const __nv_bfloat16* Bhp = Bhi + (size_t)(bn + brow) * 256 + bkoff;
    const __nv_bfloat16* Blp = Blo + (size_t)(bn + brow) * 256 + bkoff;

    float a_st[8];
    uint2 bh_st, bl_st;

    const int lane = tid & 31, wid = tid >> 5;
    const int wm = (wid & 3) * 32;
    const int wn = (wid >> 2) * 32;
    const int gid = lane >> 2, tig = lane & 3;

    float acc[2][4][4];
#pragma unroll
    for (int mi = 0; mi < 2; ++mi)
#pragma unroll
        for (int ni = 0; ni < 4; ++ni)
#pragma unroll
            for (int j = 0; j < 4; ++j) acc[mi][ni][j] = 0.f;

#define LOAD_G(c)                                                          \
    do {                                                                   \
        int k0_ = (c) * 16;                                                \
        if (aval) {                                                        \
            float4 t0 = *(const float4*)(Ap + k0_);                        \
            float4 t1 = *(const float4*)(Ap + k0_ + 4);                    \
            a_st[0] = t0.x; a_st[1] = t0.y; a_st[2] = t0.z; a_st[3] = t0.w;\
            a_st[4] = t1.x; a_st[5] = t1.y; a_st[6] = t1.z; a_st[7] = t1.w;\
        } else {                                                           \
            for (int j = 0; j < 8; ++j) a_st[j] = 0.f;                     \
        }                                                                  \
        bh_st = *(const uint2*)(Bhp + k0_);                                \
        bl_st = *(const uint2*)(Blp + k0_);                                \
    } while (0)

#define STORE_S(b)                                                         \
    do {                                                                   \
        __nv_bfloat16 h_[8], l_[8];                                        \
        for (int j = 0; j < 8; ++j) {                                      \
            h_[j] = __float2bfloat16(a_st[j]);                             \
            l_[j] = __float2bfloat16(a_st[j] - __bfloat162float(h_[j]));   \
        }                                                                  \
        uint2 uh0, ul0;                                                    \
        uh0.x = pack_bf16(h_[0], h_[1]); uh0.y = pack_bf16(h_[2], h_[3]);  \
        ul0.x = pack_bf16(l_[0], l_[1]); ul0.y = pack_bf16(l_[2], l_[3]);  \
        uint2 uh1, ul1;                                                    \
        uh1.x = pack_bf16(h_[4], h_[5]); uh1.y = pack_bf16(h_[6], h_[7]);  \
        ul1.x = pack_bf16(l_[4], l_[5]); ul1.y = pack_bf16(l_[6], l_[7]);  \
        *(uint2*)&sAhi[b][arow * LDS + akoff]     = uh0;                   \
        *(uint2*)&sAhi[b][arow * LDS + akoff + 4] = uh1;                   \
        *(uint2*)&sAlo[b][arow * LDS + akoff]     = ul0;                   \
        *(uint2*)&sAlo[b][arow * LDS + akoff + 4] = ul1;                   \
        *(uint2*)&sBhi[b][brow * LDS + bkoff] = bh_st;                     \
        *(uint2*)&sBlo[b][brow * LDS + bkoff] = bl_st;                     \
    } while (0)

#define COMPUTE(b)                                                          \
    do {                                                                    \
        uint32_t bh[4][2], bl[4][2];                                        \
        _Pragma("unroll")                                                   \
        for (int ni = 0; ni < 4; ++ni) {                                    \
            int n_ = (wn + ni * 8 + gid) * LDS + tig * 2;                   \
            bh[ni][0] = *(const uint32_t*)&sBhi[b][n_];                     \
            bh[ni][1] = *(const uint32_t*)&sBhi[b][n_ + 8];                 \
            bl[ni][0] = *(const uint32_t*)&sBlo[b][n_];                     \
            bl[ni][1] = *(const uint32_t*)&sBlo[b][n_ + 8];                 \
        }                                                                   \
        _Pragma("unroll")                                                   \
        for (int mi = 0; mi < 2; ++mi) {                                    \
            int r_ = (wm + mi * 16 + gid) * LDS + tig * 2;                  \
            uint32_t ah[4], al[4];                                          \
            ah[0] = *(const uint32_t*)&sAhi[b][r_];                         \
            ah[1] = *(const uint32_t*)&sAhi[b][r_ + 8 * LDS];               \
            ah[2] = *(const uint32_t*)&sAhi[b][r_ + 8];                     \
            ah[3] = *(const uint32_t*)&sAhi[b][r_ + 8 * LDS + 8];           \
            al[0] = *(const uint32_t*)&sAlo[b][r_];                         \
            al[1] = *(const uint32_t*)&sAlo[b][r_ + 8 * LDS];               \
            al[2] = *(const uint32_t*)&sAlo[b][r_ + 8];                     \
            al[3] = *(const uint32_t*)&sAlo[b][r_ + 8 * LDS + 8];           \
            _Pragma("unroll")                                               \
            for (int ni = 0; ni < 4; ++ni) {                                \
                MMA16816(acc[mi][ni], ah[0], ah[1], ah[2], ah[3],           \
                         bh[ni][0], bh[ni][1]);                             \
                MMA16816(acc[mi][ni], ah[0], ah[1], ah[2], ah[3],           \
                         bl[ni][0], bl[ni][1]);                             \
                MMA16816(acc[mi][ni], al[0], al[1], al[2], al[3],           \
                         bh[ni][0], bh[ni][1]);                             \
            }                                                               \
        }                                                                   \
    } while (0)

    LOAD_G(0);
    STORE_S(0);
    __syncthreads();

    int buf = 0;
#pragma unroll 1
    for (int c = 0; c < 16; ++c) {
        if (c < 15) LOAD_G(c + 1);
        COMPUTE(buf);
        if (c < 15) {
            STORE_S(buf ^ 1);
            __syncthreads();
            buf ^= 1;
        }
    }

    // ---- epilogue: store C and fused attention-logit partial dots ----
    // thread's columns within the head: c0 = wn + ni*8 + tig*2 (and +1)
    float sv[4], dv[4];   // attention vector values for its 8 columns (pairs)
#pragma unroll
    for (int ni = 0; ni < 4; ++ni) {
        int c0 = wn + ni * 8 + tig * 2;
        // stash pairs: use float2 loads
        float2 s2 = *(const float2*)(att_s + head * HID + c0);
        float2 d2 = *(const float2*)(att_d + head * HID + c0);
        sv[ni] = s2.x; dv[ni] = d2.x;
        // store second element in separate regs via reuse below
        // (handled inline in the loop that follows)
        (void)s2; (void)d2;
    }

#pragma unroll
    for (int mi = 0; mi < 2; ++mi) {
        float ps0 = 0.f, pd0 = 0.f, ps1 = 0.f, pd1 = 0.f;
#pragma unroll
        for (int ni = 0; ni < 4; ++ni) {
            int c0 = wn + ni * 8 + tig * 2;
            float2 s2 = *(const float2*)(att_s + head * HID + c0);
            float2 d2 = *(const float2*)(att_d + head * HID + c0);
            ps0 += acc[mi][ni][0] * s2.x + acc[mi][ni][1] * s2.y;
            pd0 += acc[mi][ni][0] * d2.x + acc[mi][ni][1] * d2.y;
            ps1 += acc[mi][ni][2] * s2.x + acc[mi][ni][3] * s2.y;
            pd1 += acc[mi][ni][2] * d2.x + acc[mi][ni][3] * d2.y;
        }
        // reduce across tig (lanes differing in bits 0-1)
#pragma unroll
        for (int o = 1; o < 4; o <<= 1) {
            ps0 += __shfl_xor_sync(0xffffffffu, ps0, o);
            pd0 += __shfl_xor_sync(0xffffffffu, pd0, o);
            ps1 += __shfl_xor_sync(0xffffffffu, ps1, o);
            pd1 += __shfl_xor_sync(0xffffffffu, pd1, o);
        }
        int r0 = bm + wm + mi * 16 + gid;
        if (tig == 0) {
            if (r0 < M) {
                atomicAdd(&alog[(size_t)r0 * 4 + head], ps0);
                atomicAdd(&alog[(size_t)(N_NODES_C + r0) * 4 + head], pd0);
            }
            if (r0 + 8 < M) {
                atomicAdd(&alog[(size_t)(r0 + 8) * 4 + head], ps1);
                atomicAdd(&alog[(size_t)(N_NODES_C + r0 + 8) * 4 + head], pd1);
            }
        }
        // C store
#pragma unroll
        for (int ni = 0; ni < 4; ++ni) {
            int col = bn + wn + ni * 8 + tig * 2;
            if (r0 < M) {
                float2 v = make_float2(acc[mi][ni][0], acc[mi][ni][1]);
                *(float2*)&C[(size_t)r0 * 256 + col] = v;
            }
            if (r0 + 8 < M) {
                float2 v = make_float2(acc[mi][ni][2], acc[mi][ni][3]);
                *(float2*)&C[(size_t)(r0 + 8) * 256 + col] = v;
            }
        }
    }
#undef LOAD_G
#undef STORE_S
#undef COMPUTE
}

// ---------------- GAT aggregation: single pass, no max subtraction ----------------
__global__ void aggregate_kernel(const float* __restrict__ h,
                                 const float* __restrict__ asrc,
                                 const float* __restrict__ adst,
                                 const int* __restrict__ indptr,
                                 const int* __restrict__ esrc,
                                 const float* __restrict__ bias,
                                 float* __restrict__ xout, int N) {
    int n = (blockIdx.x * blockDim.x + threadIdx.x) >> 5;
    int lane = threadIdx.x & 31;
    if (n >= N) return;
    int s0 = indptr[n], s1 = indptr[n + 1];

    float4 ad  = *(const float4*)(adst + 4 * n);
    float4 asn = *(const float4*)(asrc + 4 * n);

    int head = lane >> 3;
    float adh   = pick4(ad.x, ad.y, ad.z, ad.w, head);
    float ash   = pick4(asn.x, asn.y, asn.z, asn.w, head);
    float wself = expf(lrelu(ash + adh));

    float acc[8];
    {
        const float4* hp = (const float4*)(h + (size_t)n * DIM);
        float4 v0 = hp[lane * 2], v1 = hp[lane * 2 + 1];
        acc[0] = wself * v0.x; acc[1] = wself * v0.y; acc[2] = wself * v0.z; acc[3] = wself * v0.w;
        acc[4] = wself * v1.x; acc[5] = wself * v1.y; acc[6] = wself * v1.z; acc[7] = wself * v1.w;
    }

    float wsum = 0.f;
    for (int eb = s0; eb < s1; eb += 8) {
        int idx = eb + (lane & 7);
        float wv = 0.f;
        int sv = 0;
        if (idx < s1) {
            sv = esrc[idx];
            float a = __ldg(asrc + 4 * sv + head);
            wv = expf(lrelu(a + adh));
        }
        wsum += wv;
        int cnt = min(8, s1 - eb);
        for (int j = 0; j < cnt; ++j) {
            float wj = __shfl_sync(0xffffffffu, wv, (lane & 24) | j);
            int sj   = __shfl_sync(0xffffffffu, sv, j);
            const float4* hp = (const float4*)(h + (size_t)sj * DIM);
            float4 v0 = hp[lane * 2], v1 = hp[lane * 2 + 1];
            acc[0] += wj * v0.x; acc[1] += wj * v0.y; acc[2] += wj * v0.z; acc[3] += wj * v0.w;
            acc[4] += wj * v1.x; acc[5] += wj * v1.y; acc[6] += wj * v1.z; acc[7] += wj * v1.w;
        }
    }
#pragma unroll
    for (int o = 4; o; o >>= 1) wsum += __shfl_xor_sync(0xffffffffu, wsum, o);
    float inv = 1.0f / (wsum + wself);

    const float4* bp = (const float4*)(bias + lane * 8);
    float4 b0 = bp[0], b1 = bp[1];
    float4 o0, o1;
    o0.x = elu_f(acc[0] * inv + b0.x); o0.y = elu_f(acc[1] * inv + b0.y);
    o0.z = elu_f(acc[2] * inv + b0.z); o0.w = elu_f(acc[3] * inv + b0.w);
    o1.x = elu_f(acc[4] * inv + b1.x); o1.y = elu_f(acc[5] * inv + b1.y);
    o1.z = elu_f(acc[6] * inv + b1.z); o1.w = elu_f(acc[7] * inv + b1.w);
    float4* xo = (float4*)(xout + (size_t)n * DIM);
    xo[lane * 2] = o0;
    xo[lane * 2 + 1] = o1;
}

// ---------------- global add pool: one block per graph (batch is sorted) ----------------
__global__ void pool_kernel(const float* __restrict__ x, const int* __restrict__ batch,
                            float* __restrict__ emb, int N) {
    int g = blockIdx.x;
    int c = threadIdx.x;
    int lo = 0, hi = N;
    while (lo < hi) { int mid = (lo + hi) >> 1; if (batch[mid] < g) lo = mid + 1; else hi = mid; }
    int start = lo;
    hi = N;
    while (lo < hi) { int mid = (lo + hi) >> 1; if (batch[mid] < g + 1) lo = mid + 1; else hi = mid; }
    int end = lo;

    float a0 = 0.f, a1 = 0.f, a2 = 0.f, a3 = 0.f;
    int r = start;
    for (; r + 3 < end; r += 4) {
        a0 += x[(size_t)(r + 0) * DIM + c];
        a1 += x[(size_t)(r + 1) * DIM + c];
        a2 += x[(size_t)(r + 2) * DIM + c];
        a3 += x[(size_t)(r + 3) * DIM + c];
    }
    for (; r < end; ++r) a0 += x[(size_t)r * DIM + c];
    emb[(size_t)g * DIM + c] = (a0 + a1) + (a2 + a3);
}

// ---------------- final MLP per graph ----------------
__global__ void mlp_kernel(const float* __restrict__ hemb, const float* __restrict__ temb,
                           const float* __restrict__ kge, const int* __restrict__ rel,
                           const float* __restrict__ W1, const float* __restrict__ b1,
                           const float* __restrict__ W2, const float* __restrict__ b2,
                           float* __restrict__ out) {
    int g = blockIdx.x;
    int t = threadIdx.x;
    __shared__ float z[2 * DIM + KGE_DIM];
    for (int i = t; i < DIM; i += 64) {
        z[i]       = hemb[(size_t)g * DIM + i];
        z[DIM + i] = temb[(size_t)g * DIM + i];
    }
    int r = rel[g];
    z[2 * DIM + t] = kge[(size_t)r * KGE_DIM + t];
    __syncthreads();

    float acc = b1[t];
#pragma unroll 4
    for (int k = 0; k < 2 * DIM + KGE_DIM; ++k)
        acc = fmaf(z[k], W1[(size_t)k * 64 + t], acc);
    acc = fmaxf(acc, 0.f) * W2[t];

#pragma unroll
    for (int o = 16; o; o >>= 1) acc += __shfl_xor_sync(0xffffffffu, acc, o);
    __shared__ float wsum[2];
    if ((t & 31) == 0) wsum[t >> 5] = acc;
    __syncthreads();
    if (t == 0) out[g] = wsum[0] + wsum[1] + b2[0];
}

// ---------------- launch ----------------
extern "C" void kernel_launch(void* const* d_in, const int* in_sizes, int n_in,
                              void* d_out, int out_size) {
    const float* head_x     = (const float*)d_in[0];
    const int*   head_ei    = (const int*)  d_in[1];
    const int*   head_batch = (const int*)  d_in[2];
    const float* tail_x     = (const float*)d_in[3];
    const int*   tail_ei    = (const int*)  d_in[4];
    const int*   tail_batch = (const int*)  d_in[5];
    const int*   rel        = (const int*)  d_in[6];
    const float* Ws         = (const float*)d_in[7];
    const float* att_s      = (const float*)d_in[8];
    const float* att_d      = (const float*)d_in[9];
    const float* biases     = (const float*)d_in[10];
    const float* kge        = (const float*)d_in[11];
    const float* W1         = (const float*)d_in[12];
    const float* b1         = (const float*)d_in[13];
    const float* W2         = (const float*)d_in[14];
    const float* b2         = (const float*)d_in[15];
    float* out = (float*)d_out;

    const int N = in_sizes[0] / DIM;    // 50000
    const int E = in_sizes[1] / 2;      // 800000
    const int B = in_sizes[6];          // 512

    float *p_h, *p_xa, *p_xb, *p_alog, *p_hemb, *p_temb;
    int *p_deg, *p_indptr, *p_cursor, *p_esrc;
    __nv_bfloat16 *p_whi, *p_wlo;
    cudaGetSymbolAddress((void**)&p_h, g_h);
    cudaGetSymbolAddress((void**)&p_xa, g_xa);
    cudaGetSymbolAddress((void**)&p_xb, g_xb);
    cudaGetSymbolAddress((void**)&p_alog, g_alog);
    cudaGetSymbolAddress((void**)&p_hemb, g_hemb);
    cudaGetSymbolAddress((void**)&p_temb, g_temb);
    cudaGetSymbolAddress((void**)&p_deg, g_deg);
    cudaGetSymbolAddress((void**)&p_indptr, g_indptr);
    cudaGetSymbolAddress((void**)&p_cursor, g_cursor);
    cudaGetSymbolAddress((void**)&p_esrc, g_esrc);
    cudaGetSymbolAddress((void**)&p_whi, g_whi);
    cudaGetSymbolAddress((void**)&p_wlo, g_wlo);

    float* p_asrc = p_alog;
    float* p_adst = p_alog + (size_t)N_NODES_C * HEADS;

    const int wblocks = (N * 32 + 255) / 256;

    // pre-convert the 3 layer weights to transposed bf16 hi/lo
    wconv_kernel<<<3 * 256, 256>>>(Ws, p_whi, p_wlo);

    for (int enc = 0; enc < 2; ++enc) {
        const float* x0    = enc ? tail_x : head_x;
        const int*   ei    = enc ? tail_ei : head_ei;
        const int*   batch = enc ? tail_batch : head_batch;
        float*       emb   = enc ? p_temb : p_hemb;

        cudaMemsetAsync(p_deg, 0, (size_t)N * sizeof(int));
        hist_kernel<<<(E + 255) / 256, 256>>>(ei + E, E, p_deg);
        scan_kernel<<<1, 1024>>>(p_deg, p_indptr, p_cursor, N);
        scatter_kernel<<<(E + 255) / 256, 256>>>(ei, ei + E, E, p_cursor, p_esrc);

        const float* xin = x0;
        float* bufs[2] = {p_xa, p_xb};
        for (int l = 0; l < 3; ++l) {
            cudaMemsetAsync(p_alog, 0, (size_t)N_NODES_C * 2 * HEADS * sizeof(float));
            dim3 gg((unsigned)((N + 127) / 128), 4);
            gemm_tc_kernel<<<gg, 256>>>(xin, p_whi + (size_t)l * DIM * DIM,
                                        p_wlo + (size_t)l * DIM * DIM, p_h,
                                        att_s + l * HEADS * HID, att_d + l * HEADS * HID,
                                        p_alog, N);
            aggregate_kernel<<<wblocks, 256>>>(p_h, p_asrc, p_adst, p_indptr, p_esrc,
                                               biases + l * DIM, bufs[l & 1], N);
            xin = bufs[l & 1];
        }

        pool_kernel<<<N_GRAPHS_C, 256>>>(xin, batch, emb, N);
    }

    mlp_kernel<<<B, 64>>>(p_hemb, p_temb, kge, rel, W1, b1, W2, b2, out);
}

// round 5
// speedup vs baseline: 1.5331x; 1.1183x over previous
#include <cuda_runtime.h>
#include <cuda_bf16.h>
#include <math.h>
#include <stdint.h>

#define N_NODES_C 50000
#define N_EDGES_C 800000
#define N_GRAPHS_C 512
#define DIM 256
#define HEADS 4
#define HID 64
#define KGE_DIM 64

// ---------------- static device scratch (no allocations allowed) ----------------
// one full set per encoder so head/tail pipelines can run concurrently
__device__ float g_h   [2][N_NODES_C * DIM];
__device__ float g_xa  [2][N_NODES_C * DIM];
__device__ float g_xb  [2][N_NODES_C * DIM];
__device__ float g_alog[2][N_NODES_C * 2 * HEADS];   // [asrc | adst]
__device__ int   g_deg   [2][N_NODES_C];
__device__ int   g_indptr[2][N_NODES_C + 1];
__device__ int   g_cursor[2][N_NODES_C];
__device__ int   g_esrc  [2][N_EDGES_C];
__device__ float g_hemb[N_GRAPHS_C * DIM];
__device__ float g_temb[N_GRAPHS_C * DIM];
__device__ __nv_bfloat16 g_whi[3 * DIM * DIM];   // W transposed [l][n][k], hi part
__device__ __nv_bfloat16 g_wlo[3 * DIM * DIM];   // lo part

__device__ __forceinline__ float lrelu(float x) { return x > 0.f ? x : 0.2f * x; }
__device__ __forceinline__ float elu_f(float x) { return x > 0.f ? x : expm1f(x); }
__device__ __forceinline__ float pick4(float a, float b, float c, float d, int h) {
    return h == 0 ? a : (h == 1 ? b : (h == 2 ? c : d));
}
__device__ __forceinline__ uint32_t pack_bf16(__nv_bfloat16 lo, __nv_bfloat16 hi) {
    return (uint32_t)__bfloat16_as_ushort(lo) | ((uint32_t)__bfloat16_as_ushort(hi) << 16);
}

#define MMA16816(d, a0, a1, a2, a3, b0, b1)                                     \
    asm volatile("mma.sync.aligned.m16n8k16.row.col.f32.bf16.bf16.f32 "         \
                 "{%0,%1,%2,%3}, {%4,%5,%6,%7}, {%8,%9}, {%0,%1,%2,%3};"        \
                 : "+f"(d[0]), "+f"(d[1]), "+f"(d[2]), "+f"(d[3])               \
                 : "r"(a0), "r"(a1), "r"(a2), "r"(a3), "r"(b0), "r"(b1))

// ---------------- CSR build (counting sort by dst) ----------------
__global__ void hist_kernel(const int* __restrict__ dst, int E, int* __restrict__ deg) {
    int e = blockIdx.x * blockDim.x + threadIdx.x;
    if (e < E) atomicAdd(&deg[dst[e]], 1);
}

// single-block warp-shuffle scan: 4096 elements per iteration
__global__ void scan_kernel(const int* __restrict__ deg, int* __restrict__ indptr,
                            int* __restrict__ cursor, int n) {
    __shared__ int wsum[32];
    __shared__ int carry_s;
    int tid = threadIdx.x, lane = tid & 31, wid = tid >> 5;
    if (tid == 0) carry_s = 0;
    __syncthreads();
    for (int base = 0; base < n; base += 4096) {
        int i0 = base + tid * 4;
        int v0 = (i0 + 0 < n) ? deg[i0 + 0] : 0;
        int v1 = (i0 + 1 < n) ? deg[i0 + 1] : 0;
        int v2 = (i0 + 2 < n) ? deg[i0 + 2] : 0;
        int v3 = (i0 + 3 < n) ? deg[i0 + 3] : 0;
        int s = v0 + v1 + v2 + v3;
        int ps = s;
#pragma unroll
        for (int o = 1; o < 32; o <<= 1) {
            int t = __shfl_up_sync(0xffffffffu, ps, o);
            if (lane >= o) ps += t;
        }
        if (lane == 31) wsum[wid] = ps;
        __syncthreads();
        if (wid == 0) {
            int w = wsum[lane];
            int pw = w;
#pragma unroll
            for (int o = 1; o < 32; o <<= 1) {
                int t = __shfl_up_sync(0xffffffffu, pw, o);
                if (lane >= o) pw += t;
            }
            wsum[lane] = pw;
        }
        __syncthreads();
        int woff = wid ? wsum[wid - 1] : 0;
        int run = carry_s + woff + ps - s;
        if (i0 + 0 < n) { indptr[i0 + 0] = run; cursor[i0 + 0] = run; } run += v0;
        if (i0 + 1 < n) { indptr[i0 + 1] = run; cursor[i0 + 1] = run; } run += v1;
        if (i0 + 2 < n) { indptr[i0 + 2] = run; cursor[i0 + 2] = run; } run += v2;
        if (i0 + 3 < n) { indptr[i0 + 3] = run; cursor[i0 + 3] = run; }
        __syncthreads();
        if (tid == 0) carry_s += wsum[31];
        __syncthreads();
    }
    if (tid == 0) indptr[n] = carry_s;
}

__global__ void scatter_kernel(const int* __restrict__ src, const int* __restrict__ dst,
                               int E, int* __restrict__ cursor, int* __restrict__ esrc) {
    int e = blockIdx.x * blockDim.x + threadIdx.x;
    if (e < E) {
        int pos = atomicAdd(&cursor[dst[e]], 1);
        esrc[pos] = src[e];
    }
}

// ---------------- W pre-convert: fp32 [l][k][n] -> bf16 hi/lo transposed [l][n][k] ----------
__global__ void wconv_kernel(const float* __restrict__ W,
                             __nv_bfloat16* __restrict__ whi,
                             __nv_bfloat16* __restrict__ wlo) {
    int l = blockIdx.x >> 8;
    int n = blockIdx.x & 255;
    int k = threadIdx.x;
    float w = W[((size_t)l * 256 + k) * 256 + n];
    __nv_bfloat16 h = __float2bfloat16(w);
    float rem = w - __bfloat162float(h);
    whi[((size_t)l * 256 + n) * 256 + k] = h;
    wlo[((size_t)l * 256 + n) * 256 + k] = __float2bfloat16(rem);
}

// ---------------- tensor-core GEMM + fused attention-logit epilogue --------------------------
// C[M,256] = A[M,256] @ W[256,256] (bf16x3 split). Each 64-col block tile == one head; the
// epilogue reduces acc·att_src / acc·att_dst per row (smem cross-warp reduce, plain store).
__global__ __launch_bounds__(256) void gemm_tc_kernel(const float* __restrict__ A,
                                                      const __nv_bfloat16* __restrict__ Bhi,
                                                      const __nv_bfloat16* __restrict__ Blo,
                                                      float* __restrict__ C,
                                                      const float* __restrict__ att_s,
                                                      const float* __restrict__ att_d,
                                                      float* __restrict__ alog, int M) {
    constexpr int LDS = 24;
    __shared__ __nv_bfloat16 sAhi[2][128 * LDS];
    __shared__ __nv_bfloat16 sAlo[2][128 * LDS];
    __shared__ __nv_bfloat16 sBhi[2][64 * LDS];
    __shared__ __nv_bfloat16 sBlo[2][64 * LDS];
    __shared__ float sred[128][2];

    const int tid = threadIdx.x;
    const int bm = blockIdx.x * 128;
    const int bn = blockIdx.y * 64;
    const int head = blockIdx.y;          // 64-col tile == one head

    const int arow = tid >> 1, akoff = (tid & 1) * 8;
    const int brow = tid >> 2, bkoff = (tid & 3) * 4;
    const bool aval = (bm + arow) < M;
    const float* Ap = A + (size_t)(bm + arow) * 256 + akoff;
    const __nv_bfloat16* Bhp = Bhi + (size_t)(bn + brow) * 256 + bkoff;
    const __nv_bfloat16* Blp = Blo + (size_t)(bn + brow) * 256 + bkoff;

    float a_st[8];
    uint2 bh_st, bl_st;

    const int lane = tid & 31, wid = tid >> 5;
    const int wm = (wid & 3) * 32;
    const int wn = (wid >> 2) * 32;
    const int gid = lane >> 2, tig = lane & 3;

    float acc[2][4][4];
#pragma unroll
    for (int mi = 0; mi < 2; ++mi)
#pragma unroll
        for (int ni = 0; ni < 4; ++ni)
#pragma unroll
            for (int j = 0; j < 4; ++j) acc[mi][ni][j] = 0.f;

#define LOAD_G(c)                                                          \
    do {                                                                   \
        int k0_ = (c) * 16;                                                \
        if (aval) {                                                        \
            float4 t0 = *(const float4*)(Ap + k0_);                        \
            float4 t1 = *(const float4*)(Ap + k0_ + 4);                    \
            a_st[0] = t0.x; a_st[1] = t0.y; a_st[2] = t0.z; a_st[3] = t0.w;\
            a_st[4] = t1.x; a_st[5] = t1.y; a_st[6] = t1.z; a_st[7] = t1.w;\
        } else {                                                           \
            for (int j = 0; j < 8; ++j) a_st[j] = 0.f;                     \
        }                                                                  \
        bh_st = *(const uint2*)(Bhp + k0_);                                \
        bl_st = *(const uint2*)(Blp + k0_);                                \
    } while (0)

#define STORE_S(b)                                                         \
    do {                                                                   \
        __nv_bfloat16 h_[8], l_[8];                                        \
        for (int j = 0; j < 8; ++j) {                                      \
            h_[j] = __float2bfloat16(a_st[j]);                             \
            l_[j] = __float2bfloat16(a_st[j] - __bfloat162float(h_[j]));   \
        }                                                                  \
        uint2 uh0, ul0;                                                    \
        uh0.x = pack_bf16(h_[0], h_[1]); uh0.y = pack_bf16(h_[2], h_[3]);  \
        ul0.x = pack_bf16(l_[0], l_[1]); ul0.y = pack_bf16(l_[2], l_[3]);  \
        uint2 uh1, ul1;                                                    \
        uh1.x = pack_bf16(h_[4], h_[5]); uh1.y = pack_bf16(h_[6], h_[7]);  \
        ul1.x = pack_bf16(l_[4], l_[5]); ul1.y = pack_bf16(l_[6], l_[7]);  \
        *(uint2*)&sAhi[b][arow * LDS + akoff]     = uh0;                   \
        *(uint2*)&sAhi[b][arow * LDS + akoff + 4] = uh1;                   \
        *(uint2*)&sAlo[b][arow * LDS + akoff]     = ul0;                   \
        *(uint2*)&sAlo[b][arow * LDS + akoff + 4] = ul1;                   \
        *(uint2*)&sBhi[b][brow * LDS + bkoff] = bh_st;                     \
        *(uint2*)&sBlo[b][brow * LDS + bkoff] = bl_st;                     \
    } while (0)

#define COMPUTE(b)                                                          \
    do {                                                                    \
        uint32_t bh[4][2], bl[4][2];                                        \
        _Pragma("unroll")                                                   \
        for (int ni = 0; ni < 4; ++ni) {                                    \
            int n_ = (wn + ni * 8 + gid) * LDS + tig * 2;                   \
            bh[ni][0] = *(const uint32_t*)&sBhi[b][n_];                     \
            bh[ni][1] = *(const uint32_t*)&sBhi[b][n_ + 8];                 \
            bl[ni][0] = *(const uint32_t*)&sBlo[b][n_];                     \
            bl[ni][1] = *(const uint32_t*)&sBlo[b][n_ + 8];                 \
        }                                                                   \
        _Pragma("unroll")                                                   \
        for (int mi = 0; mi < 2; ++mi) {                                    \
            int r_ = (wm + mi * 16 + gid) * LDS + tig * 2;                  \
            uint32_t ah[4], al[4];                                          \
            ah[0] = *(const uint32_t*)&sAhi[b][r_];                         \
            ah[1] = *(const uint32_t*)&sAhi[b][r_ + 8 * LDS];               \
            ah[2] = *(const uint32_t*)&sAhi[b][r_ + 8];                     \
            ah[3] = *(const uint32_t*)&sAhi[b][r_ + 8 * LDS + 8];           \
            al[0] = *(const uint32_t*)&sAlo[b][r_];                         \
            al[1] = *(const uint32_t*)&sAlo[b][r_ + 8 * LDS];               \
            al[2] = *(const uint32_t*)&sAlo[b][r_ + 8];                     \
            al[3] = *(const uint32_t*)&sAlo[b][r_ + 8 * LDS + 8];           \
            _Pragma("unroll")                                               \
            for (int ni = 0; ni < 4; ++ni) {                                \
                MMA16816(acc[mi][ni], ah[0], ah[1], ah[2], ah[3],           \
                         bh[ni][0], bh[ni][1]);                             \
                MMA16816(acc[mi][ni], ah[0], ah[1], ah[2], ah[3],           \
                         bl[ni][0], bl[ni][1]);                             \
                MMA16816(acc[mi][ni], al[0], al[1], al[2], al[3],           \
                         bh[ni][0], bh[ni][1]);                             \
            }                                                               \
        }                                                                   \
    } while (0)

    LOAD_G(0);
    STORE_S(0);
    __syncthreads();

    int buf = 0;
#pragma unroll 1
    for (int c = 0; c < 16; ++c) {
        if (c < 15) LOAD_G(c + 1);
        COMPUTE(buf);
        if (c < 15) {
            STORE_S(buf ^ 1);
            __syncthreads();
            buf ^= 1;
        }
    }

    // ---- epilogue: C stores + fused attention-logit dots (smem cross-warp reduce) ----
    float rps[2][2], rpd[2][2];
#pragma unroll
    for (int mi = 0; mi < 2; ++mi) {
        float ps0 = 0.f, pd0 = 0.f, ps1 = 0.f, pd1 = 0.f;
#pragma unroll
        for (int ni = 0; ni < 4; ++ni) {
            int c0 = wn + ni * 8 + tig * 2;
            float2 s2 = *(const float2*)(att_s + head * HID + c0);
            float2 d2 = *(const float2*)(att_d + head * HID + c0);
            ps0 += acc[mi][ni][0] * s2.x + acc[mi][ni][1] * s2.y;
            pd0 += acc[mi][ni][0] * d2.x + acc[mi][ni][1] * d2.y;
            ps1 += acc[mi][ni][2] * s2.x + acc[mi][ni][3] * s2.y;
            pd1 += acc[mi][ni][2] * d2.x + acc[mi][ni][3] * d2.y;
        }
#pragma unroll
        for (int o = 1; o < 4; o <<= 1) {
            ps0 += __shfl_xor_sync(0xffffffffu, ps0, o);
            pd0 += __shfl_xor_sync(0xffffffffu, pd0, o);
            ps1 += __shfl_xor_sync(0xffffffffu, ps1, o);
            pd1 += __shfl_xor_sync(0xffffffffu, pd1, o);
        }
        rps[mi][0] = ps0; rpd[mi][0] = pd0;
        rps[mi][1] = ps1; rpd[mi][1] = pd1;

        int r0 = bm + wm + mi * 16 + gid;
#pragma unroll
        for (int ni = 0; ni < 4; ++ni) {
            int col = bn + wn + ni * 8 + tig * 2;
            if (r0 < M) {
                float2 v = make_float2(acc[mi][ni][0], acc[mi][ni][1]);
                *(float2*)&C[(size_t)r0 * 256 + col] = v;
            }
            if (r0 + 8 < M) {
                float2 v = make_float2(acc[mi][ni][2], acc[mi][ni][3]);
                *(float2*)&C[(size_t)(r0 + 8) * 256 + col] = v;
            }
        }
    }

    // warps 4-7 (wn==32 half) publish partials; warps 0-3 add and store
    if (wid >= 4 && tig == 0) {
#pragma unroll
        for (int mi = 0; mi < 2; ++mi) {
            int lr = wm + mi * 16 + gid;
            sred[lr][0]     = rps[mi][0];
            sred[lr][1]     = rpd[mi][0];
            sred[lr + 8][0] = rps[mi][1];
            sred[lr + 8][1] = rpd[mi][1];
        }
    }
    __syncthreads();
    if (wid < 4 && tig == 0) {
#pragma unroll
        for (int mi = 0; mi < 2; ++mi) {
            int lr = wm + mi * 16 + gid;
            int r0 = bm + lr;
            if (r0 < M) {
                alog[(size_t)r0 * 4 + head]                 = rps[mi][0] + sred[lr][0];
                alog[(size_t)(N_NODES_C + r0) * 4 + head]   = rpd[mi][0] + sred[lr][1];
            }
            if (r0 + 8 < M) {
                alog[(size_t)(r0 + 8) * 4 + head]               = rps[mi][1] + sred[lr + 8][0];
                alog[(size_t)(N_NODES_C + r0 + 8) * 4 + head]   = rpd[mi][1] + sred[lr + 8][1];
            }
        }
    }
#undef LOAD_G
#undef STORE_S
#undef COMPUTE
}

// ---------------- GAT aggregation: single pass, no max subtraction ----------------
__global__ void aggregate_kernel(const float* __restrict__ h,
                                 const float* __restrict__ asrc,
                                 const float* __restrict__ adst,
                                 const int* __restrict__ indptr,
                                 const int* __restrict__ esrc,
                                 const float* __restrict__ bias,
                                 float* __restrict__ xout, int N) {
    int n = (blockIdx.x * blockDim.x + threadIdx.x) >> 5;
    int lane = threadIdx.x & 31;
    if (n >= N) return;
    int s0 = indptr[n], s1 = indptr[n + 1];

    float4 ad  = *(const float4*)(adst + 4 * n);
    float4 asn = *(const float4*)(asrc + 4 * n);

    int head = lane >> 3;
    float adh   = pick4(ad.x, ad.y, ad.z, ad.w, head);
    float ash   = pick4(asn.x, asn.y, asn.z, asn.w, head);
    float wself = expf(lrelu(ash + adh));

    float acc[8];
    {
        const float4* hp = (const float4*)(h + (size_t)n * DIM);
        float4 v0 = hp[lane * 2], v1 = hp[lane * 2 + 1];
        acc[0] = wself * v0.x; acc[1] = wself * v0.y; acc[2] = wself * v0.z; acc[3] = wself * v0.w;
        acc[4] = wself * v1.x; acc[5] = wself * v1.y; acc[6] = wself * v1.z; acc[7] = wself * v1.w;
    }

    float wsum = 0.f;
    for (int eb = s0; eb < s1; eb += 8) {
        int idx = eb + (lane & 7);
        float wv = 0.f;
        int sv = 0;
        if (idx < s1) {
            sv = esrc[idx];
            float a = __ldg(asrc + 4 * sv + head);
            wv = expf(lrelu(a + adh));
        }
        wsum += wv;
        int cnt = min(8, s1 - eb);
        for (int j = 0; j < cnt; ++j) {
            float wj = __shfl_sync(0xffffffffu, wv, (lane & 24) | j);
            int sj   = __shfl_sync(0xffffffffu, sv, j);
            const float4* hp = (const float4*)(h + (size_t)sj * DIM);
            float4 v0 = hp[lane * 2], v1 = hp[lane * 2 + 1];
            acc[0] += wj * v0.x; acc[1] += wj * v0.y; acc[2] += wj * v0.z; acc[3] += wj * v0.w;
            acc[4] += wj * v1.x; acc[5] += wj * v1.y; acc[6] += wj * v1.z; acc[7] += wj * v1.w;
        }
    }
#pragma unroll
    for (int o = 4; o; o >>= 1) wsum += __shfl_xor_sync(0xffffffffu, wsum, o);
    float inv = 1.0f / (wsum + wself);

    const float4* bp = (const float4*)(bias + lane * 8);
    float4 b0 = bp[0], b1 = bp[1];
    float4 o0, o1;
    o0.x = elu_f(acc[0] * inv + b0.x); o0.y = elu_f(acc[1] * inv + b0.y);
    o0.z = elu_f(acc[2] * inv + b0.z); o0.w = elu_f(acc[3] * inv + b0.w);
    o1.x = elu_f(acc[4] * inv + b1.x); o1.y = elu_f(acc[5] * inv + b1.y);
    o1.z = elu_f(acc[6] * inv + b1.z); o1.w = elu_f(acc[7] * inv + b1.w);
    float4* xo = (float4*)(xout + (size_t)n * DIM);
    xo[lane * 2] = o0;
    xo[lane * 2 + 1] = o1;
}

// ---------------- global add pool: one block per graph (batch is sorted) ----------------
__global__ void pool_kernel(const float* __restrict__ x, const int* __restrict__ batch,
                            float* __restrict__ emb, int N) {
    int g = blockIdx.x;
    int c = threadIdx.x;
    int lo = 0, hi = N;
    while (lo < hi) { int mid = (lo + hi) >> 1; if (batch[mid] < g) lo = mid + 1; else hi = mid; }
    int start = lo;
    hi = N;
    while (lo < hi) { int mid = (lo + hi) >> 1; if (batch[mid] < g + 1) lo = mid + 1; else hi = mid; }
    int end = lo;

    float a0 = 0.f, a1 = 0.f, a2 = 0.f, a3 = 0.f;
    int r = start;
    for (; r + 3 < end; r += 4) {
        a0 += x[(size_t)(r + 0) * DIM + c];
        a1 += x[(size_t)(r + 1) * DIM + c];
        a2 += x[(size_t)(r + 2) * DIM + c];
        a3 += x[(size_t)(r + 3) * DIM + c];
    }
    for (; r < end; ++r) a0 += x[(size_t)r * DIM + c];
    emb[(size_t)g * DIM + c] = (a0 + a1) + (a2 + a3);
}

// ---------------- final MLP per graph ----------------
__global__ void mlp_kernel(const float* __restrict__ hemb, const float* __restrict__ temb,
                           const float* __restrict__ kge, const int* __restrict__ rel,
                           const float* __restrict__ W1, const float* __restrict__ b1,
                           const float* __restrict__ W2, const float* __restrict__ b2,
                           float* __restrict__ out) {
    int g = blockIdx.x;
    int t = threadIdx.x;
    __shared__ float z[2 * DIM + KGE_DIM];
    for (int i = t; i < DIM; i += 64) {
        z[i]       = hemb[(size_t)g * DIM + i];
        z[DIM + i] = temb[(size_t)g * DIM + i];
    }
    int r = rel[g];
    z[2 * DIM + t] = kge[(size_t)r * KGE_DIM + t];
    __syncthreads();

    float acc = b1[t];
#pragma unroll 4
    for (int k = 0; k < 2 * DIM + KGE_DIM; ++k)
        acc = fmaf(z[k], W1[(size_t)k * 64 + t], acc);
    acc = fmaxf(acc, 0.f) * W2[t];

#pragma unroll
    for (int o = 16; o; o >>= 1) acc += __shfl_xor_sync(0xffffffffu, acc, o);
    __shared__ float wsum[2];
    if ((t & 31) == 0) wsum[t >> 5] = acc;
    __syncthreads();
    if (t == 0) out[g] = wsum[0] + wsum[1] + b2[0];
}

// ---------------- launch ----------------
extern "C" void kernel_launch(void* const* d_in, const int* in_sizes, int n_in,
                              void* d_out, int out_size) {
    const float* head_x     = (const float*)d_in[0];
    const int*   head_ei    = (const int*)  d_in[1];
    const int*   head_batch = (const int*)  d_in[2];
    const float* tail_x     = (const float*)d_in[3];
    const int*   tail_ei    = (const int*)  d_in[4];
    const int*   tail_batch = (const int*)  d_in[5];
    const int*   rel        = (const int*)  d_in[6];
    const float* Ws         = (const float*)d_in[7];
    const float* att_s      = (const float*)d_in[8];
    const float* att_d      = (const float*)d_in[9];
    const float* biases     = (const float*)d_in[10];
    const float* kge        = (const float*)d_in[11];
    const float* W1         = (const float*)d_in[12];
    const float* b1         = (const float*)d_in[13];
    const float* W2         = (const float*)d_in[14];
    const float* b2         = (const float*)d_in[15];
    float* out = (float*)d_out;

    const int N = in_sizes[0] / DIM;    // 50000
    const int E = in_sizes[1] / 2;      // 800000
    const int B = in_sizes[6];          // 512

    // lazily create the second stream + fork/join events (host resources only;
    // created during the correctness call, so capture sees only record/wait edges)
    static cudaStream_t s2 = nullptr;
    static cudaEvent_t evFork = nullptr, evJoin = nullptr;
    if (s2 == nullptr) {
        cudaStreamCreateWithFlags(&s2, cudaStreamNonBlocking);
        cudaEventCreateWithFlags(&evFork, cudaEventDisableTiming);
        cudaEventCreateWithFlags(&evJoin, cudaEventDisableTiming);
    }

    float *p_h[2], *p_xa[2], *p_xb[2], *p_alog[2];
    int *p_deg[2], *p_indptr[2], *p_cursor[2], *p_esrc[2];
    float *p_hemb, *p_temb;
    __nv_bfloat16 *p_whi, *p_wlo;
    {
        float* base;
        cudaGetSymbolAddress((void**)&base, g_h);
        p_h[0] = base; p_h[1] = base + (size_t)N_NODES_C * DIM;
        cudaGetSymbolAddress((void**)&base, g_xa);
        p_xa[0] = base; p_xa[1] = base + (size_t)N_NODES_C * DIM;
        cudaGetSymbolAddress((void**)&base, g_xb);
        p_xb[0] = base; p_xb[1] = base + (size_t)N_NODES_C * DIM;
        cudaGetSymbolAddress((void**)&base, g_alog);
        p_alog[0] = base; p_alog[1] = base + (size_t)N_NODES_C * 2 * HEADS;
        int* ibase;
        cudaGetSymbolAddress((void**)&ibase, g_deg);
        p_deg[0] = ibase; p_deg[1] = ibase + N_NODES_C;
        cudaGetSymbolAddress((void**)&ibase, g_indptr);
        p_indptr[0] = ibase; p_indptr[1] = ibase + N_NODES_C + 1;
        cudaGetSymbolAddress((void**)&ibase, g_cursor);
        p_cursor[0] = ibase; p_cursor[1] = ibase + N_NODES_C;
        cudaGetSymbolAddress((void**)&ibase, g_esrc);
        p_esrc[0] = ibase; p_esrc[1] = ibase + N_EDGES_C;
    }
    cudaGetSymbolAddress((void**)&p_hemb, g_hemb);
    cudaGetSymbolAddress((void**)&p_temb, g_temb);
    cudaGetSymbolAddress((void**)&p_whi, g_whi);
    cudaGetSymbolAddress((void**)&p_wlo, g_wlo);

    const int wblocks = (N * 32 + 255) / 256;

    // pre-convert the 3 layer weights to transposed bf16 hi/lo (default stream)
    wconv_kernel<<<3 * 256, 256>>>(Ws, p_whi, p_wlo);

    // fork: tail encoder runs on s2, head on default stream
    cudaEventRecord(evFork, 0);
    cudaStreamWaitEvent(s2, evFork, 0);

    for (int enc = 0; enc < 2; ++enc) {
        cudaStream_t st = enc ? s2 : 0;
        const float* x0    = enc ? tail_x : head_x;
        const int*   ei    = enc ? tail_ei : head_ei;
        const int*   batch = enc ? tail_batch : head_batch;
        float*       emb   = enc ? p_temb : p_hemb;

        cudaMemsetAsync(p_deg[enc], 0, (size_t)N * sizeof(int), st);
        hist_kernel<<<(E + 255) / 256, 256, 0, st>>>(ei + E, E, p_deg[enc]);
        scan_kernel<<<1, 1024, 0, st>>>(p_deg[enc], p_indptr[enc], p_cursor[enc], N);
        scatter_kernel<<<(E + 255) / 256, 256, 0, st>>>(ei, ei + E, E, p_cursor[enc], p_esrc[enc]);

        const float* xin = x0;
        float* bufs[2] = {p_xa[enc], p_xb[enc]};
        float* asrc_p = p_alog[enc];
        float* adst_p = p_alog[enc] + (size_t)N_NODES_C * HEADS;
        for (int l = 0; l < 3; ++l) {
            dim3 gg((unsigned)((N + 127) / 128), 4);
            gemm_tc_kernel<<<gg, 256, 0, st>>>(xin, p_whi + (size_t)l * DIM * DIM,
                                               p_wlo + (size_t)l * DIM * DIM, p_h[enc],
                                               att_s + l * HEADS * HID, att_d + l * HEADS * HID,
                                               p_alog[enc], N);
            aggregate_kernel<<<wblocks, 256, 0, st>>>(p_h[enc], asrc_p, adst_p,
                                                      p_indptr[enc], p_esrc[enc],
                                                      biases + l * DIM, bufs[l & 1], N);
            xin = bufs[l & 1];
        }

        pool_kernel<<<N_GRAPHS_C, 256, 0, st>>>(xin, batch, emb, N);
    }

    // join: default stream waits for tail pipeline
    cudaEventRecord(evJoin, s2);
    cudaStreamWaitEvent(0, evJoin, 0);

    mlp_kernel<<<B, 64>>>(p_hemb, p_temb, kge, rel, W1, b1, W2, b2, out);
}

// round 6
// speedup vs baseline: 1.6438x; 1.0722x over previous
#include <cuda_runtime.h>
#include <cuda_bf16.h>
#include <math.h>
#include <stdint.h>

#define N_NODES_C 50000
#define N_EDGES_C 800000
#define N_GRAPHS_C 512
#define DIM 256
#define HEADS 4
#define HID 64
#define KGE_DIM 64

// ---------------- static device scratch (no allocations allowed) ----------------
// one full set per encoder so head/tail pipelines can run concurrently
__device__ uint32_t g_h [2][N_NODES_C * 128];        // h packed as bf16x2, 128 words/row
__device__ float g_xa  [2][N_NODES_C * DIM];
__device__ float g_xb  [2][N_NODES_C * DIM];
__device__ float g_alog[2][N_NODES_C * 2 * HEADS];   // [asrc | adst]
__device__ int   g_deg   [2][N_NODES_C];
__device__ int   g_indptr[2][N_NODES_C + 1];
__device__ int   g_cursor[2][N_NODES_C];
__device__ int   g_esrc  [2][N_EDGES_C];
__device__ float g_hemb[N_GRAPHS_C * DIM];
__device__ float g_temb[N_GRAPHS_C * DIM];
__device__ __nv_bfloat16 g_whi[3 * DIM * DIM];   // W transposed [l][n][k], hi part
__device__ __nv_bfloat16 g_wlo[3 * DIM * DIM];   // lo part

__device__ __forceinline__ float lrelu(float x) { return x > 0.f ? x : 0.2f * x; }
__device__ __forceinline__ float elu_f(float x) { return x > 0.f ? x : expm1f(x); }
__device__ __forceinline__ float pick4(float a, float b, float c, float d, int h) {
    return h == 0 ? a : (h == 1 ? b : (h == 2 ? c : d));
}
__device__ __forceinline__ uint32_t pack_bf16(__nv_bfloat16 lo, __nv_bfloat16 hi) {
    return (uint32_t)__bfloat16_as_ushort(lo) | ((uint32_t)__bfloat16_as_ushort(hi) << 16);
}
__device__ __forceinline__ uint32_t pack2f(float a, float b) {
    uint32_t r;
    asm("cvt.rn.bf16x2.f32 %0, %2, %1;" : "=r"(r) : "f"(a), "f"(b));
    return r;
}
__device__ __forceinline__ float2 unpack2f(uint32_t u) {
    __nv_bfloat162 b = *reinterpret_cast<__nv_bfloat162*>(&u);
    return __bfloat1622float2(b);
}

#define MMA16816(d, a0, a1, a2, a3, b0, b1)                                     \
    asm volatile("mma.sync.aligned.m16n8k16.row.col.f32.bf16.bf16.f32 "         \
                 "{%0,%1,%2,%3}, {%4,%5,%6,%7}, {%8,%9}, {%0,%1,%2,%3};"        \
                 : "+f"(d[0]), "+f"(d[1]), "+f"(d[2]), "+f"(d[3])               \
                 : "r"(a0), "r"(a1), "r"(a2), "r"(a3), "r"(b0), "r"(b1))

// ---------------- CSR build (counting sort by dst) ----------------
__global__ void hist_kernel(const int* __restrict__ dst, int E, int* __restrict__ deg) {
    int e = blockIdx.x * blockDim.x + threadIdx.x;
    if (e < E) atomicAdd(&deg[dst[e]], 1);
}

// single-block warp-shuffle scan: 4096 elements per iteration
__global__ void scan_kernel(const int* __restrict__ deg, int* __restrict__ indptr,
                            int* __restrict__ cursor, int n) {
    __shared__ int wsum[32];
    __shared__ int carry_s;
    int tid = threadIdx.x, lane = tid & 31, wid = tid >> 5;
    if (tid == 0) carry_s = 0;
    __syncthreads();
    for (int base = 0; base < n; base += 4096) {
        int i0 = base + tid * 4;
        int v0 = (i0 + 0 < n) ? deg[i0 + 0] : 0;
        int v1 = (i0 + 1 < n) ? deg[i0 + 1] : 0;
        int v2 = (i0 + 2 < n) ? deg[i0 + 2] : 0;
        int v3 = (i0 + 3 < n) ? deg[i0 + 3] : 0;
        int s = v0 + v1 + v2 + v3;
        int ps = s;
#pragma unroll
        for (int o = 1; o < 32; o <<= 1) {
            int t = __shfl_up_sync(0xffffffffu, ps, o);
            if (lane >= o) ps += t;
        }
        if (lane == 31) wsum[wid] = ps;
        __syncthreads();
        if (wid == 0) {
            int w = wsum[lane];
            int pw = w;
#pragma unroll
            for (int o = 1; o < 32; o <<= 1) {
                int t = __shfl_up_sync(0xffffffffu, pw, o);
                if (lane >= o) pw += t;
            }
            wsum[lane] = pw;
        }
        __syncthreads();
        int woff = wid ? wsum[wid - 1] : 0;
        int run = carry_s + woff + ps - s;
        if (i0 + 0 < n) { indptr[i0 + 0] = run; cursor[i0 + 0] = run; } run += v0;
        if (i0 + 1 < n) { indptr[i0 + 1] = run; cursor[i0 + 1] = run; } run += v1;
        if (i0 + 2 < n) { indptr[i0 + 2] = run; cursor[i0 + 2] = run; } run += v2;
        if (i0 + 3 < n) { indptr[i0 + 3] = run; cursor[i0 + 3] = run; }
        __syncthreads();
        if (tid == 0) carry_s += wsum[31];
        __syncthreads();
    }
    if (tid == 0) indptr[n] = carry_s;
}

__global__ void scatter_kernel(const int* __restrict__ src, const int* __restrict__ dst,
                               int E, int* __restrict__ cursor, int* __restrict__ esrc) {
    int e = blockIdx.x * blockDim.x + threadIdx.x;
    if (e < E) {
        int pos = atomicAdd(&cursor[dst[e]], 1);
        esrc[pos] = src[e];
    }
}

// ---------------- W pre-convert: fp32 [l][k][n] -> bf16 hi/lo transposed [l][n][k] ----------
__global__ void wconv_kernel(const float* __restrict__ W,
                             __nv_bfloat16* __restrict__ whi,
                             __nv_bfloat16* __restrict__ wlo) {
    int l = blockIdx.x >> 8;
    int n = blockIdx.x & 255;
    int k = threadIdx.x;
    float w = W[((size_t)l * 256 + k) * 256 + n];
    __nv_bfloat16 h = __float2bfloat16(w);
    float rem = w - __bfloat162float(h);
    whi[((size_t)l * 256 + n) * 256 + k] = h;
    wlo[((size_t)l * 256 + n) * 256 + k] = __float2bfloat16(rem);
}

// ---------------- tensor-core GEMM + fused attention-logit epilogue --------------------------
// Cb[M,128] (bf16x2 packed) = A[M,256] @ W[256,256] (bf16x3 split). Head = blockIdx.y.
// Attention logits reduced from fp32 accumulators (smem cross-warp reduce, plain store).
__global__ __launch_bounds__(256) void gemm_tc_kernel(const float* __restrict__ A,
                                                      const __nv_bfloat16* __restrict__ Bhi,
                                                      const __nv_bfloat16* __restrict__ Blo,
                                                      uint32_t* __restrict__ Cb,
                                                      const float* __restrict__ att_s,
                                                      const float* __restrict__ att_d,
                                                      float* __restrict__ alog, int M) {
    constexpr int LDS = 24;
    __shared__ __nv_bfloat16 sAhi[2][128 * LDS];
    __shared__ __nv_bfloat16 sAlo[2][128 * LDS];
    __shared__ __nv_bfloat16 sBhi[2][64 * LDS];
    __shared__ __nv_bfloat16 sBlo[2][64 * LDS];
    __shared__ float sred[128][2];

    const int tid = threadIdx.x;
    const int bm = blockIdx.x * 128;
    const int bn = blockIdx.y * 64;
    const int head = blockIdx.y;          // 64-col tile == one head

    const int arow = tid >> 1, akoff = (tid & 1) * 8;
    const int brow = tid >> 2, bkoff = (tid & 3) * 4;
    const bool aval = (bm + arow) < M;
    const float* Ap = A + (size_t)(bm + arow) * 256 + akoff;
    const __nv_bfloat16* Bhp = Bhi + (size_t)(bn + brow) * 256 + bkoff;
    const __nv_bfloat16* Blp = Blo + (size_t)(bn + brow) * 256 + bkoff;

    float a_st[8];
    uint2 bh_st, bl_st;

    const int lane = tid & 31, wid = tid >> 5;
    const int wm = (wid & 3) * 32;
    const int wn = (wid >> 2) * 32;
    const int gid = lane >> 2, tig = lane & 3;

    float acc[2][4][4];
#pragma unroll
    for (int mi = 0; mi < 2; ++mi)
#pragma unroll
        for (int ni = 0; ni < 4; ++ni)
#pragma unroll
            for (int j = 0; j < 4; ++j) acc[mi][ni][j] = 0.f;

#define LOAD_G(c)                                                          \
    do {                                                                   \
        int k0_ = (c) * 16;                                                \
        if (aval) {                                                        \
            float4 t0 = *(const float4*)(Ap + k0_);                        \
            float4 t1 = *(const float4*)(Ap + k0_ + 4);                    \
            a_st[0] = t0.x; a_st[1] = t0.y; a_st[2] = t0.z; a_st[3] = t0.w;\
            a_st[4] = t1.x; a_st[5] = t1.y; a_st[6] = t1.z; a_st[7] = t1.w;\
        } else {                                                           \
            for (int j = 0; j < 8; ++j) a_st[j] = 0.f;                     \
        }                                                                  \
        bh_st = *(const uint2*)(Bhp + k0_);                                \
        bl_st = *(const uint2*)(Blp + k0_);                                \
    } while (0)

#define STORE_S(b)                                                         \
    do {                                                                   \
        __nv_bfloat16 h_[8], l_[8];                                        \
        for (int j = 0; j < 8; ++j) {                                      \
            h_[j] = __float2bfloat16(a_st[j]);                             \
            l_[j] = __float2bfloat16(a_st[j] - __bfloat162float(h_[j]));   \
        }                                                                  \
        uint2 uh0, ul0;                                                    \
        uh0.x = pack_bf16(h_[0], h_[1]); uh0.y = pack_bf16(h_[2], h_[3]);  \
        ul0.x = pack_bf16(l_[0], l_[1]); ul0.y = pack_bf16(l_[2], l_[3]);  \
        uint2 uh1, ul1;                                                    \
        uh1.x = pack_bf16(h_[4], h_[5]); uh1.y = pack_bf16(h_[6], h_[7]);  \
        ul1.x = pack_bf16(l_[4], l_[5]); ul1.y = pack_bf16(l_[6], l_[7]);  \
        *(uint2*)&sAhi[b][arow * LDS + akoff]     = uh0;                   \
        *(uint2*)&sAhi[b][arow * LDS + akoff + 4] = uh1;                   \
        *(uint2*)&sAlo[b][arow * LDS + akoff]     = ul0;                   \
        *(uint2*)&sAlo[b][arow * LDS + akoff + 4] = ul1;                   \
        *(uint2*)&sBhi[b][brow * LDS + bkoff] = bh_st;                     \
        *(uint2*)&sBlo[b][brow * LDS + bkoff] = bl_st;                     \
    } while (0)

#define COMPUTE(b)                                                          \
    do {                                                                    \
        uint32_t bh[4][2], bl[4][2];                                        \
        _Pragma("unroll")                                                   \
        for (int ni = 0; ni < 4; ++ni) {                                    \
            int n_ = (wn + ni * 8 + gid) * LDS + tig * 2;                   \
            bh[ni][0] = *(const uint32_t*)&sBhi[b][n_];                     \
            bh[ni][1] = *(const uint32_t*)&sBhi[b][n_ + 8];                 \
            bl[ni][0] = *(const uint32_t*)&sBlo[b][n_];                     \
            bl[ni][1] = *(const uint32_t*)&sBlo[b][n_ + 8];                 \
        }                                                                   \
        _Pragma("unroll")                                                   \
        for (int mi = 0; mi < 2; ++mi) {                                    \
            int r_ = (wm + mi * 16 + gid) * LDS + tig * 2;                  \
            uint32_t ah[4], al[4];                                          \
            ah[0] = *(const uint32_t*)&sAhi[b][r_];                         \
            ah[1] = *(const uint32_t*)&sAhi[b][r_ + 8 * LDS];               \
            ah[2] = *(const uint32_t*)&sAhi[b][r_ + 8];                     \
            ah[3] = *(const uint32_t*)&sAhi[b][r_ + 8 * LDS + 8];           \
            al[0] = *(const uint32_t*)&sAlo[b][r_];                         \
            al[1] = *(const uint32_t*)&sAlo[b][r_ + 8 * LDS];               \
            al[2] = *(const uint32_t*)&sAlo[b][r_ + 8];                     \
            al[3] = *(const uint32_t*)&sAlo[b][r_ + 8 * LDS + 8];           \
            _Pragma("unroll")                                               \
            for (int ni = 0; ni < 4; ++ni) {                                \
                MMA16816(acc[mi][ni], ah[0], ah[1], ah[2], ah[3],           \
                         bh[ni][0], bh[ni][1]);                             \
                MMA16816(acc[mi][ni], ah[0], ah[1], ah[2], ah[3],           \
                         bl[ni][0], bl[ni][1]);                             \
                MMA16816(acc[mi][ni], al[0], al[1], al[2], al[3],           \
                         bh[ni][0], bh[ni][1]);                             \
            }                                                               \
        }                                                                   \
    } while (0)

    LOAD_G(0);
    STORE_S(0);
    __syncthreads();

    int buf = 0;
#pragma unroll 1
    for (int c = 0; c < 16; ++c) {
        if (c < 15) LOAD_G(c + 1);
        COMPUTE(buf);
        if (c < 15) {
            STORE_S(buf ^ 1);
            __syncthreads();
            buf ^= 1;
        }
    }

    // ---- epilogue: packed bf16 C stores + fused attention-logit dots ----
    float rps[2][2], rpd[2][2];
#pragma unroll
    for (int mi = 0; mi < 2; ++mi) {
        float ps0 = 0.f, pd0 = 0.f, ps1 = 0.f, pd1 = 0.f;
#pragma unroll
        for (int ni = 0; ni < 4; ++ni) {
            int c0 = wn + ni * 8 + tig * 2;
            float2 s2 = *(const float2*)(att_s + head * HID + c0);
            float2 d2 = *(const float2*)(att_d + head * HID + c0);
            ps0 += acc[mi][ni][0] * s2.x + acc[mi][ni][1] * s2.y;
            pd0 += acc[mi][ni][0] * d2.x + acc[mi][ni][1] * d2.y;
            ps1 += acc[mi][ni][2] * s2.x + acc[mi][ni][3] * s2.y;
            pd1 += acc[mi][ni][2] * d2.x + acc[mi][ni][3] * d2.y;
        }
#pragma unroll
        for (int o = 1; o < 4; o <<= 1) {
            ps0 += __shfl_xor_sync(0xffffffffu, ps0, o);
            pd0 += __shfl_xor_sync(0xffffffffu, pd0, o);
            ps1 += __shfl_xor_sync(0xffffffffu, ps1, o);
            pd1 += __shfl_xor_sync(0xffffffffu, pd1, o);
        }
        rps[mi][0] = ps0; rpd[mi][0] = pd0;
        rps[mi][1] = ps1; rpd[mi][1] = pd1;

        int r0 = bm + wm + mi * 16 + gid;
#pragma unroll
        for (int ni = 0; ni < 4; ++ni) {
            int col = bn + wn + ni * 8 + tig * 2;      // even
            if (r0 < M)
                Cb[(size_t)r0 * 128 + (col >> 1)] = pack2f(acc[mi][ni][0], acc[mi][ni][1]);
            if (r0 + 8 < M)
                Cb[(size_t)(r0 + 8) * 128 + (col >> 1)] = pack2f(acc[mi][ni][2], acc[mi][ni][3]);
        }
    }

    // warps 4-7 (wn==32 half) publish partials; warps 0-3 add and store
    if (wid >= 4 && tig == 0) {
#pragma unroll
        for (int mi = 0; mi < 2; ++mi) {
            int lr = wm + mi * 16 + gid;
            sred[lr][0]     = rps[mi][0];
            sred[lr][1]     = rpd[mi][0];
            sred[lr + 8][0] = rps[mi][1];
            sred[lr + 8][1] = rpd[mi][1];
        }
    }
    __syncthreads();
    if (wid < 4 && tig == 0) {
#pragma unroll
        for (int mi = 0; mi < 2; ++mi) {
            int lr = wm + mi * 16 + gid;
            int r0 = bm + lr;
            if (r0 < M) {
                alog[(size_t)r0 * 4 + head]                 = rps[mi][0] + sred[lr][0];
                alog[(size_t)(N_NODES_C + r0) * 4 + head]   = rpd[mi][0] + sred[lr][1];
            }
            if (r0 + 8 < M) {
                alog[(size_t)(r0 + 8) * 4 + head]               = rps[mi][1] + sred[lr + 8][0];
                alog[(size_t)(N_NODES_C + r0 + 8) * 4 + head]   = rpd[mi][1] + sred[lr + 8][1];
            }
        }
    }
#undef LOAD_G
#undef STORE_S
#undef COMPUTE
}

// ---------------- GAT aggregation: single pass, bf16 value gather ----------------
__global__ void aggregate_kernel(const uint32_t* __restrict__ hb,
                                 const float* __restrict__ asrc,
                                 const float* __restrict__ adst,
                                 const int* __restrict__ indptr,
                                 const int* __restrict__ esrc,
                                 const float* __restrict__ bias,
                                 float* __restrict__ xout, int N) {
    int n = (blockIdx.x * blockDim.x + threadIdx.x) >> 5;
    int lane = threadIdx.x & 31;
    if (n >= N) return;
    int s0 = indptr[n], s1 = indptr[n + 1];

    float4 ad  = *(const float4*)(adst + 4 * n);
    float4 asn = *(const float4*)(asrc + 4 * n);

    int head = lane >> 3;
    float adh   = pick4(ad.x, ad.y, ad.z, ad.w, head);
    float ash   = pick4(asn.x, asn.y, asn.z, asn.w, head);
    float wself = expf(lrelu(ash + adh));

    float acc[8];
    {
        uint4 p = *(const uint4*)(hb + (size_t)n * 128 + lane * 4);
        float2 f0 = unpack2f(p.x), f1 = unpack2f(p.y), f2 = unpack2f(p.z), f3 = unpack2f(p.w);
        acc[0] = wself * f0.x; acc[1] = wself * f0.y;
        acc[2] = wself * f1.x; acc[3] = wself * f1.y;
        acc[4] = wself * f2.x; acc[5] = wself * f2.y;
        acc[6] = wself * f3.x; acc[7] = wself * f3.y;
    }

    float wsum = 0.f;
    for (int eb = s0; eb < s1; eb += 8) {
        int idx = eb + (lane & 7);
        float wv = 0.f;
        int sv = 0;
        if (idx < s1) {
            sv = esrc[idx];
            float a = __ldg(asrc + 4 * sv + head);
            wv = expf(lrelu(a + adh));
        }
        wsum += wv;
        int cnt = min(8, s1 - eb);
        for (int j = 0; j < cnt; ++j) {
            float wj = __shfl_sync(0xffffffffu, wv, (lane & 24) | j);
            int sj   = __shfl_sync(0xffffffffu, sv, j);
            uint4 p = *(const uint4*)(hb + (size_t)sj * 128 + lane * 4);
            float2 f0 = unpack2f(p.x), f1 = unpack2f(p.y), f2 = unpack2f(p.z), f3 = unpack2f(p.w);
            acc[0] += wj * f0.x; acc[1] += wj * f0.y;
            acc[2] += wj * f1.x; acc[3] += wj * f1.y;
            acc[4] += wj * f2.x; acc[5] += wj * f2.y;
            acc[6] += wj * f3.x; acc[7] += wj * f3.y;
        }
    }
#pragma unroll
    for (int o = 4; o; o >>= 1) wsum += __shfl_xor_sync(0xffffffffu, wsum, o);
    float inv = 1.0f / (wsum + wself);

    const float4* bp = (const float4*)(bias + lane * 8);
    float4 b0 = bp[0], b1 = bp[1];
    float4 o0, o1;
    o0.x = elu_f(acc[0] * inv + b0.x); o0.y = elu_f(acc[1] * inv + b0.y);
    o0.z = elu_f(acc[2] * inv + b0.z); o0.w = elu_f(acc[3] * inv + b0.w);
    o1.x = elu_f(acc[4] * inv + b1.x); o1.y = elu_f(acc[5] * inv + b1.y);
    o1.z = elu_f(acc[6] * inv + b1.z); o1.w = elu_f(acc[7] * inv + b1.w);
    float4* xo = (float4*)(xout + (size_t)n * DIM);
    xo[lane * 2] = o0;
    xo[lane * 2 + 1] = o1;
}

// ---------------- global add pool: one block per graph (batch is sorted) ----------------
__global__ void pool_kernel(const float* __restrict__ x, const int* __restrict__ batch,
                            float* __restrict__ emb, int N) {
    int g = blockIdx.x;
    int c = threadIdx.x;
    int lo = 0, hi = N;
    while (lo < hi) { int mid = (lo + hi) >> 1; if (batch[mid] < g) lo = mid + 1; else hi = mid; }
    int start = lo;
    hi = N;
    while (lo < hi) { int mid = (lo + hi) >> 1; if (batch[mid] < g + 1) lo = mid + 1; else hi = mid; }
    int end = lo;

    float a0 = 0.f, a1 = 0.f, a2 = 0.f, a3 = 0.f;
    int r = start;
    for (; r + 3 < end; r += 4) {
        a0 += x[(size_t)(r + 0) * DIM + c];
        a1 += x[(size_t)(r + 1) * DIM + c];
        a2 += x[(size_t)(r + 2) * DIM + c];
        a3 += x[(size_t)(r + 3) * DIM + c];
    }
    for (; r < end; ++r) a0 += x[(size_t)r * DIM + c];
    emb[(size_t)g * DIM + c] = (a0 + a1) + (a2 + a3);
}

// ---------------- final MLP per graph ----------------
__global__ void mlp_kernel(const float* __restrict__ hemb, const float* __restrict__ temb,
                           const float* __restrict__ kge, const int* __restrict__ rel,
                           const float* __restrict__ W1, const float* __restrict__ b1,
                           const float* __restrict__ W2, const float* __restrict__ b2,
                           float* __restrict__ out) {
    int g = blockIdx.x;
    int t = threadIdx.x;
    __shared__ float z[2 * DIM + KGE_DIM];
    for (int i = t; i < DIM; i += 64) {
        z[i]       = hemb[(size_t)g * DIM + i];
        z[DIM + i] = temb[(size_t)g * DIM + i];
    }
    int r = rel[g];
    z[2 * DIM + t] = kge[(size_t)r * KGE_DIM + t];
    __syncthreads();

    float acc = b1[t];
#pragma unroll 4
    for (int k = 0; k < 2 * DIM + KGE_DIM; ++k)
        acc = fmaf(z[k], W1[(size_t)k * 64 + t], acc);
    acc = fmaxf(acc, 0.f) * W2[t];

#pragma unroll
    for (int o = 16; o; o >>= 1) acc += __shfl_xor_sync(0xffffffffu, acc, o);
    __shared__ float wsum[2];
    if ((t & 31) == 0) wsum[t >> 5] = acc;
    __syncthreads();
    if (t == 0) out[g] = wsum[0] + wsum[1] + b2[0];
}

// ---------------- launch ----------------
extern "C" void kernel_launch(void* const* d_in, const int* in_sizes, int n_in,
                              void* d_out, int out_size) {
    const float* head_x     = (const float*)d_in[0];
    const int*   head_ei    = (const int*)  d_in[1];
    const int*   head_batch = (const int*)  d_in[2];
    const float* tail_x     = (const float*)d_in[3];
    const int*   tail_ei    = (const int*)  d_in[4];
    const int*   tail_batch = (const int*)  d_in[5];
    const int*   rel        = (const int*)  d_in[6];
    const float* Ws         = (const float*)d_in[7];
    const float* att_s      = (const float*)d_in[8];
    const float* att_d      = (const float*)d_in[9];
    const float* biases     = (const float*)d_in[10];
    const float* kge        = (const float*)d_in[11];
    const float* W1         = (const float*)d_in[12];
    const float* b1         = (const float*)d_in[13];
    const float* W2         = (const float*)d_in[14];
    const float* b2         = (const float*)d_in[15];
    float* out = (float*)d_out;

    const int N = in_sizes[0] / DIM;    // 50000
    const int E = in_sizes[1] / 2;      // 800000
    const int B = in_sizes[6];          // 512

    // lazily create streams + events (host resources only)
    static cudaStream_t sMain2 = nullptr, sCsr0 = nullptr, sCsr1 = nullptr;
    static cudaEvent_t evFork = nullptr, evJoin = nullptr, evCsr0 = nullptr, evCsr1 = nullptr;
    if (sMain2 == nullptr) {
        cudaStreamCreateWithFlags(&sMain2, cudaStreamNonBlocking);
        cudaStreamCreateWithFlags(&sCsr0, cudaStreamNonBlocking);
        cudaStreamCreateWithFlags(&sCsr1, cudaStreamNonBlocking);
        cudaEventCreateWithFlags(&evFork, cudaEventDisableTiming);
        cudaEventCreateWithFlags(&evJoin, cudaEventDisableTiming);
        cudaEventCreateWithFlags(&evCsr0, cudaEventDisableTiming);
        cudaEventCreateWithFlags(&evCsr1, cudaEventDisableTiming);
    }

    uint32_t* p_h[2];
    float *p_xa[2], *p_xb[2], *p_alog[2];
    int *p_deg[2], *p_indptr[2], *p_cursor[2], *p_esrc[2];
    float *p_hemb, *p_temb;
    __nv_bfloat16 *p_whi, *p_wlo;
    {
        uint32_t* ubase;
        cudaGetSymbolAddress((void**)&ubase, g_h);
        p_h[0] = ubase; p_h[1] = ubase + (size_t)N_NODES_C * 128;
        float* base;
        cudaGetSymbolAddress((void**)&base, g_xa);
        p_xa[0] = base; p_xa[1] = base + (size_t)N_NODES_C * DIM;
        cudaGetSymbolAddress((void**)&base, g_xb);
        p_xb[0] = base; p_xb[1] = base + (size_t)N_NODES_C * DIM;
        cudaGetSymbolAddress((void**)&base, g_alog);
        p_alog[0] = base; p_alog[1] = base + (size_t)N_NODES_C * 2 * HEADS;
        int* ibase;
        cudaGetSymbolAddress((void**)&ibase, g_deg);
        p_deg[0] = ibase; p_deg[1] = ibase + N_NODES_C;
        cudaGetSymbolAddress((void**)&ibase, g_indptr);
        p_indptr[0] = ibase; p_indptr[1] = ibase + N_NODES_C + 1;
        cudaGetSymbolAddress((void**)&ibase, g_cursor);
        p_cursor[0] = ibase; p_cursor[1] = ibase + N_NODES_C;
        cudaGetSymbolAddress((void**)&ibase, g_esrc);
        p_esrc[0] = ibase; p_esrc[1] = ibase + N_EDGES_C;
    }
    cudaGetSymbolAddress((void**)&p_hemb, g_hemb);
    cudaGetSymbolAddress((void**)&p_temb, g_temb);
    cudaGetSymbolAddress((void**)&p_whi, g_whi);
    cudaGetSymbolAddress((void**)&p_wlo, g_wlo);

    const int wblocks = (N * 32 + 255) / 256;

    // pre-convert the 3 layer weights (default stream, before fork)
    wconv_kernel<<<3 * 256, 256>>>(Ws, p_whi, p_wlo);

    // fork: tail encoder on sMain2, CSR builds on sCsr0/sCsr1
    cudaEventRecord(evFork, 0);
    cudaStreamWaitEvent(sMain2, evFork, 0);
    cudaStreamWaitEvent(sCsr0, evFork, 0);
    cudaStreamWaitEvent(sCsr1, evFork, 0);

    for (int enc = 0; enc < 2; ++enc) {
        cudaStream_t st  = enc ? sMain2 : 0;
        cudaStream_t stc = enc ? sCsr1 : sCsr0;
        cudaEvent_t evC  = enc ? evCsr1 : evCsr0;
        const float* x0    = enc ? tail_x : head_x;
        const int*   ei    = enc ? tail_ei : head_ei;
        const int*   batch = enc ? tail_batch : head_batch;
        float*       emb   = enc ? p_temb : p_hemb;

        // CSR build on side stream (independent of GEMM)
        cudaMemsetAsync(p_deg[enc], 0, (size_t)N * sizeof(int), stc);
        hist_kernel<<<(E + 255) / 256, 256, 0, stc>>>(ei + E, E, p_deg[enc]);
        scan_kernel<<<1, 1024, 0, stc>>>(p_deg[enc], p_indptr[enc], p_cursor[enc], N);
        scatter_kernel<<<(E + 255) / 256, 256, 0, stc>>>(ei, ei + E, E, p_cursor[enc], p_esrc[enc]);
        cudaEventRecord(evC, stc);

        const float* xin = x0;
        float* bufs[2] = {p_xa[enc], p_xb[enc]};
        float* asrc_p = p_alog[enc];
        float* adst_p = p_alog[enc] + (size_t)N_NODES_C * HEADS;
        for (int l = 0; l < 3; ++l) {
            dim3 gg((unsigned)((N + 127) / 128), 4);
            gemm_tc_kernel<<<gg, 256, 0, st>>>(xin, p_whi + (size_t)l * DIM * DIM,
                                               p_wlo + (size_t)l * DIM * DIM, p_h[enc],
                                               att_s + l * HEADS * HID, att_d + l * HEADS * HID,
                                               p_alog[enc], N);
            if (l == 0) cudaStreamWaitEvent(st, evC, 0);   // CSR ready before first aggregate
            aggregate_kernel<<<wblocks, 256, 0, st>>>(p_h[enc], asrc_p, adst_p,
                                                      p_indptr[enc], p_esrc[enc],
                                                      biases + l * DIM, bufs[l & 1], N);
            xin = bufs[l & 1];
        }

        pool_kernel<<<N_GRAPHS_C, 256, 0, st>>>(xin, batch, emb, N);
    }

    // join: default stream waits for tail pipeline
    cudaEventRecord(evJoin, sMain2);
    cudaStreamWaitEvent(0, evJoin, 0);

    mlp_kernel<<<B, 64>>>(p_hemb, p_temb, kge, rel, W1, b1, W2, b2, out);
}

// round 7
// speedup vs baseline: 1.6851x; 1.0251x over previous
#include <cuda_runtime.h>
#include <cuda_bf16.h>
#include <cuda_fp16.h>
#include <math.h>
#include <stdint.h>

#define N_NODES_C 50000
#define N_EDGES_C 800000
#define N_GRAPHS_C 512
#define DIM 256
#define HEADS 4
#define HID 64
#define KGE_DIM 64

// ---------------- static device scratch (no allocations allowed) ----------------
// one full set per encoder so head/tail pipelines can run concurrently
__device__ uint32_t g_h [2][N_NODES_C * 128];        // h packed as half2, 128 words/row
__device__ uint32_t g_xa[2][N_NODES_C * 128];        // layer intermediates packed half2
__device__ uint32_t g_xb[2][N_NODES_C * 128];
__device__ float g_alog[2][N_NODES_C * 2 * HEADS];   // [asrc | adst]
__device__ int   g_deg   [2][N_NODES_C];
__device__ int   g_indptr[2][N_NODES_C + 1];
__device__ int   g_cursor[2][N_NODES_C];
__device__ int   g_esrc  [2][N_EDGES_C];
__device__ float g_hemb[N_GRAPHS_C * DIM];
__device__ float g_temb[N_GRAPHS_C * DIM];
__device__ __nv_bfloat16 g_whi[3 * DIM * DIM];   // W transposed [l][n][k], hi part
__device__ __nv_bfloat16 g_wlo[3 * DIM * DIM];   // lo part

__device__ __forceinline__ float lrelu(float x) { return x > 0.f ? x : 0.2f * x; }
__device__ __forceinline__ float elu_f(float x) { return x > 0.f ? x : expm1f(x); }
__device__ __forceinline__ float pick4(float a, float b, float c, float d, int h) {
    return h == 0 ? a : (h == 1 ? b : (h == 2 ? c : d));
}
__device__ __forceinline__ uint32_t pack_bf16(__nv_bfloat16 lo, __nv_bfloat16 hi) {
    return (uint32_t)__bfloat16_as_ushort(lo) | ((uint32_t)__bfloat16_as_ushort(hi) << 16);
}
__device__ __forceinline__ uint32_t pack2h(float a, float b) {
    __half2 h = __floats2half2_rn(a, b);
    return *reinterpret_cast<uint32_t*>(&h);
}
__device__ __forceinline__ float2 unpack2h(uint32_t u) {
    __half2 h = *reinterpret_cast<__half2*>(&u);
    return __half22float2(h);
}

#define MMA16816(d, a0, a1, a2, a3, b0, b1)                                     \
    asm volatile("mma.sync.aligned.m16n8k16.row.col.f32.bf16.bf16.f32 "         \
                 "{%0,%1,%2,%3}, {%4,%5,%6,%7}, {%8,%9}, {%0,%1,%2,%3};"        \
                 : "+f"(d[0]), "+f"(d[1]), "+f"(d[2]), "+f"(d[3])               \
                 : "r"(a0), "r"(a1), "r"(a2), "r"(a3), "r"(b0), "r"(b1))

// ---------------- CSR build (counting sort by dst) ----------------
__global__ void hist_kernel(const int* __restrict__ dst, int E, int* __restrict__ deg) {
    int e = blockIdx.x * blockDim.x + threadIdx.x;
    if (e < E) atomicAdd(&deg[dst[e]], 1);
}

// single-block warp-shuffle scan: 4096 elements per iteration
__global__ void scan_kernel(const int* __restrict__ deg, int* __restrict__ indptr,
                            int* __restrict__ cursor, int n) {
    __shared__ int wsum[32];
    __shared__ int carry_s;
    int tid = threadIdx.x, lane = tid & 31, wid = tid >> 5;
    if (tid == 0) carry_s = 0;
    __syncthreads();
    for (int base = 0; base < n; base += 4096) {
        int i0 = base + tid * 4;
        int v0 = (i0 + 0 < n) ? deg[i0 + 0] : 0;
        int v1 = (i0 + 1 < n) ? deg[i0 + 1] : 0;
        int v2 = (i0 + 2 < n) ? deg[i0 + 2] : 0;
        int v3 = (i0 + 3 < n) ? deg[i0 + 3] : 0;
        int s = v0 + v1 + v2 + v3;
        int ps = s;
#pragma unroll
        for (int o = 1; o < 32; o <<= 1) {
            int t = __shfl_up_sync(0xffffffffu, ps, o);
            if (lane >= o) ps += t;
        }
        if (lane == 31) wsum[wid] = ps;
        __syncthreads();
        if (wid == 0) {
            int w = wsum[lane];
            int pw = w;
#pragma unroll
            for (int o = 1; o < 32; o <<= 1) {
                int t = __shfl_up_sync(0xffffffffu, pw, o);
                if (lane >= o) pw += t;
            }
            wsum[lane] = pw;
        }
        __syncthreads();
        int woff = wid ? wsum[wid - 1] : 0;
        int run = carry_s + woff + ps - s;
        if (i0 + 0 < n) { indptr[i0 + 0] = run; cursor[i0 + 0] = run; } run += v0;
        if (i0 + 1 < n) { indptr[i0 + 1] = run; cursor[i0 + 1] = run; } run += v1;
        if (i0 + 2 < n) { indptr[i0 + 2] = run; cursor[i0 + 2] = run; } run += v2;
        if (i0 + 3 < n) { indptr[i0 + 3] = run; cursor[i0 + 3] = run; }
        __syncthreads();
        if (tid == 0) carry_s += wsum[31];
        __syncthreads();
    }
    if (tid == 0) indptr[n] = carry_s;
}

__global__ void scatter_kernel(const int* __restrict__ src, const int* __restrict__ dst,
                               int E, int* __restrict__ cursor, int* __restrict__ esrc) {
    int e = blockIdx.x * blockDim.x + threadIdx.x;
    if (e < E) {
        int pos = atomicAdd(&cursor[dst[e]], 1);
        esrc[pos] = src[e];
    }
}

// ---------------- W pre-convert: fp32 [l][k][n] -> bf16 hi/lo transposed [l][n][k] ----------
__global__ void wconv_kernel(const float* __restrict__ W,
                             __nv_bfloat16* __restrict__ whi,
                             __nv_bfloat16* __restrict__ wlo) {
    int l = blockIdx.x >> 8;
    int n = blockIdx.x & 255;
    int k = threadIdx.x;
    float w = W[((size_t)l * 256 + k) * 256 + n];
    __nv_bfloat16 h = __float2bfloat16(w);
    float rem = w - __bfloat162float(h);
    whi[((size_t)l * 256 + n) * 256 + k] = h;
    wlo[((size_t)l * 256 + n) * 256 + k] = __float2bfloat16(rem);
}

// ---------------- tensor-core GEMM + fused attention-logit epilogue --------------------------
// Cb[M,128] (half2 packed) = A[M,256] @ W[256,256] (bf16x3 split). Head = blockIdx.y.
// A is fp32 (PACKED=false, layer 0) or packed half2 (PACKED=true, layers 1-2).
template <bool PACKED>
__global__ __launch_bounds__(256) void gemm_tc_kernel(const void* __restrict__ Avoid,
                                                      const __nv_bfloat16* __restrict__ Bhi,
                                                      const __nv_bfloat16* __restrict__ Blo,
                                                      uint32_t* __restrict__ Cb,
                                                      const float* __restrict__ att_s,
                                                      const float* __restrict__ att_d,
                                                      float* __restrict__ alog, int M) {
    constexpr int LDS = 24;
    __shared__ __nv_bfloat16 sAhi[2][128 * LDS];
    __shared__ __nv_bfloat16 sAlo[2][128 * LDS];
    __shared__ __nv_bfloat16 sBhi[2][64 * LDS];
    __shared__ __nv_bfloat16 sBlo[2][64 * LDS];
    __shared__ float sred[128][2];

    const int tid = threadIdx.x;
    const int bm = blockIdx.x * 128;
    const int bn = blockIdx.y * 64;
    const int head = blockIdx.y;          // 64-col tile == one head

    const int arow = tid >> 1, akoff = (tid & 1) * 8;
    const int brow = tid >> 2, bkoff = (tid & 3) * 4;
    const bool aval = (bm + arow) < M;
    const float*    Apf = (const float*)Avoid + (size_t)(bm + arow) * 256 + akoff;
    const uint32_t* Aph = (const uint32_t*)Avoid + (size_t)(bm + arow) * 128 + (akoff >> 1);
    const __nv_bfloat16* Bhp = Bhi + (size_t)(bn + brow) * 256 + bkoff;
    const __nv_bfloat16* Blp = Blo + (size_t)(bn + brow) * 256 + bkoff;

    float a_st[8];
    uint2 bh_st, bl_st;

    const int lane = tid & 31, wid = tid >> 5;
    const int wm = (wid & 3) * 32;
    const int wn = (wid >> 2) * 32;
    const int gid = lane >> 2, tig = lane & 3;

    float acc[2][4][4];
#pragma unroll
    for (int mi = 0; mi < 2; ++mi)
#pragma unroll
        for (int ni = 0; ni < 4; ++ni)
#pragma unroll
            for (int j = 0; j < 4; ++j) acc[mi][ni][j] = 0.f;

#define LOAD_G(c)                                                          \
    do {                                                                   \
        int k0_ = (c) * 16;                                                \
        if (PACKED) {                                                      \
            if (aval) {                                                    \
                uint4 t = *(const uint4*)(Aph + (k0_ >> 1));               \
                float2 f0 = unpack2h(t.x), f1 = unpack2h(t.y);             \
                float2 f2 = unpack2h(t.z), f3 = unpack2h(t.w);             \
                a_st[0] = f0.x; a_st[1] = f0.y; a_st[2] = f1.x; a_st[3] = f1.y; \
                a_st[4] = f2.x; a_st[5] = f2.y; a_st[6] = f3.x; a_st[7] = f3.y; \
            } else {                                                       \
                for (int j = 0; j < 8; ++j) a_st[j] = 0.f;                 \
            }                                                              \
        } else {                                                           \
            if (aval) {                                                    \
                float4 t0 = *(const float4*)(Apf + k0_);                   \
                float4 t1 = *(const float4*)(Apf + k0_ + 4);               \
                a_st[0] = t0.x; a_st[1] = t0.y; a_st[2] = t0.z; a_st[3] = t0.w; \
                a_st[4] = t1.x; a_st[5] = t1.y; a_st[6] = t1.z; a_st[7] = t1.w; \
            } else {                                                       \
                for (int j = 0; j < 8; ++j) a_st[j] = 0.f;                 \
            }                                                              \
        }                                                                  \
        bh_st = *(const uint2*)(Bhp + k0_);                                \
        bl_st = *(const uint2*)(Blp + k0_);                                \
    } while (0)

#define STORE_S(b)                                                         \
    do {                                                                   \
        __nv_bfloat16 h_[8], l_[8];                                        \
        for (int j = 0; j < 8; ++j) {                                      \
            h_[j] = __float2bfloat16(a_st[j]);                             \
            l_[j] = __float2bfloat16(a_st[j] - __bfloat162float(h_[j]));   \
        }                                                                  \
        uint2 uh0, ul0;                                                    \
        uh0.x = pack_bf16(h_[0], h_[1]); uh0.y = pack_bf16(h_[2], h_[3]);  \
        ul0.x = pack_bf16(l_[0], l_[1]); ul0.y = pack_bf16(l_[2], l_[3]);  \
        uint2 uh1, ul1;                                                    \
        uh1.x = pack_bf16(h_[4], h_[5]); uh1.y = pack_bf16(h_[6], h_[7]);  \
        ul1.x = pack_bf16(l_[4], l_[5]); ul1.y = pack_bf16(l_[6], l_[7]);  \
        *(uint2*)&sAhi[b][arow * LDS + akoff]     = uh0;                   \
        *(uint2*)&sAhi[b][arow * LDS + akoff + 4] = uh1;                   \
        *(uint2*)&sAlo[b][arow * LDS + akoff]     = ul0;                   \
        *(uint2*)&sAlo[b][arow * LDS + akoff + 4] = ul1;                   \
        *(uint2*)&sBhi[b][brow * LDS + bkoff] = bh_st;                     \
        *(uint2*)&sBlo[b][brow * LDS + bkoff] = bl_st;                     \
    } while (0)

#define COMPUTE(b)                                                          \
    do {                                                                    \
        uint32_t bh[4][2], bl[4][2];                                        \
        _Pragma("unroll")                                                   \
        for (int ni = 0; ni < 4; ++ni) {                                    \
            int n_ = (wn + ni * 8 + gid) * LDS + tig * 2;                   \
            bh[ni][0] = *(const uint32_t*)&sBhi[b][n_];                     \
            bh[ni][1] = *(const uint32_t*)&sBhi[b][n_ + 8];                 \
            bl[ni][0] = *(const uint32_t*)&sBlo[b][n_];                     \
            bl[ni][1] = *(const uint32_t*)&sBlo[b][n_ + 8];                 \
        }                                                                   \
        _Pragma("unroll")                                                   \
        for (int mi = 0; mi < 2; ++mi) {                                    \
            int r_ = (wm + mi * 16 + gid) * LDS + tig * 2;                  \
            uint32_t ah[4], al[4];                                          \
            ah[0] = *(const uint32_t*)&sAhi[b][r_];                         \
            ah[1] = *(const uint32_t*)&sAhi[b][r_ + 8 * LDS];               \
            ah[2] = *(const uint32_t*)&sAhi[b][r_ + 8];                     \
            ah[3] = *(const uint32_t*)&sAhi[b][r_ + 8 * LDS + 8];           \
            al[0] = *(const uint32_t*)&sAlo[b][r_];                         \
            al[1] = *(const uint32_t*)&sAlo[b][r_ + 8 * LDS];               \
            al[2] = *(const uint32_t*)&sAlo[b][r_ + 8];                     \
            al[3] = *(const uint32_t*)&sAlo[b][r_ + 8 * LDS + 8];           \
            _Pragma("unroll")                                               \
            for (int ni = 0; ni < 4; ++ni) {                                \
                MMA16816(acc[mi][ni], ah[0], ah[1], ah[2], ah[3],           \
                         bh[ni][0], bh[ni][1]);                             \
                MMA16816(acc[mi][ni], ah[0], ah[1], ah[2], ah[3],           \
                         bl[ni][0], bl[ni][1]);                             \
                MMA16816(acc[mi][ni], al[0], al[1], al[2], al[3],           \
                         bh[ni][0], bh[ni][1]);                             \
            }                                                               \
        }                                                                   \
    } while (0)

    LOAD_G(0);
    STORE_S(0);
    __syncthreads();

    int buf = 0;
#pragma unroll 1
    for (int c = 0; c < 16; ++c) {
        if (c < 15) LOAD_G(c + 1);
        COMPUTE(buf);
        if (c < 15) {
            STORE_S(buf ^ 1);
            __syncthreads();
            buf ^= 1;
        }
    }

    // ---- epilogue: packed half2 C stores + fused attention-logit dots ----
    float rps[2][2], rpd[2][2];
#pragma unroll
    for (int mi = 0; mi < 2; ++mi) {
        float ps0 = 0.f, pd0 = 0.f, ps1 = 0.f, pd1 = 0.f;
#pragma unroll
        for (int ni = 0; ni < 4; ++ni) {
            int c0 = wn + ni * 8 + tig * 2;
            float2 s2 = *(const float2*)(att_s + head * HID + c0);
            float2 d2 = *(const float2*)(att_d + head * HID + c0);
            ps0 += acc[mi][ni][0] * s2.x + acc[mi][ni][1] * s2.y;
            pd0 += acc[mi][ni][0] * d2.x + acc[mi][ni][1] * d2.y;
            ps1 += acc[mi][ni][2] * s2.x + acc[mi][ni][3] * s2.y;
            pd1 += acc[mi][ni][2] * d2.x + acc[mi][ni][3] * d2.y;
        }
#pragma unroll
        for (int o = 1; o < 4; o <<= 1) {
            ps0 += __shfl_xor_sync(0xffffffffu, ps0, o);
            pd0 += __shfl_xor_sync(0xffffffffu, pd0, o);
            ps1 += __shfl_xor_sync(0xffffffffu, ps1, o);
            pd1 += __shfl_xor_sync(0xffffffffu, pd1, o);
        }
        rps[mi][0] = ps0; rpd[mi][0] = pd0;
        rps[mi][1] = ps1; rpd[mi][1] = pd1;

        int r0 = bm + wm + mi * 16 + gid;
#pragma unroll
        for (int ni = 0; ni < 4; ++ni) {
            int col = bn + wn + ni * 8 + tig * 2;      // even
            if (r0 < M)
                Cb[(size_t)r0 * 128 + (col >> 1)] = pack2h(acc[mi][ni][0], acc[mi][ni][1]);
            if (r0 + 8 < M)
                Cb[(size_t)(r0 + 8) * 128 + (col >> 1)] = pack2h(acc[mi][ni][2], acc[mi][ni][3]);
        }
    }

    // warps 4-7 (wn==32 half) publish partials; warps 0-3 add and store
    if (wid >= 4 && tig == 0) {
#pragma unroll
        for (int mi = 0; mi < 2; ++mi) {
            int lr = wm + mi * 16 + gid;
            sred[lr][0]     = rps[mi][0];
            sred[lr][1]     = rpd[mi][0];
            sred[lr + 8][0] = rps[mi][1];
            sred[lr + 8][1] = rpd[mi][1];
        }
    }
    __syncthreads();
    if (wid < 4 && tig == 0) {
#pragma unroll
        for (int mi = 0; mi < 2; ++mi) {
            int lr = wm + mi * 16 + gid;
            int r0 = bm + lr;
            if (r0 < M) {
                alog[(size_t)r0 * 4 + head]                 = rps[mi][0] + sred[lr][0];
                alog[(size_t)(N_NODES_C + r0) * 4 + head]   = rpd[mi][0] + sred[lr][1];
            }
            if (r0 + 8 < M) {
                alog[(size_t)(r0 + 8) * 4 + head]               = rps[mi][1] + sred[lr + 8][0];
                alog[(size_t)(N_NODES_C + r0 + 8) * 4 + head]   = rpd[mi][1] + sred[lr + 8][1];
            }
        }
    }
#undef LOAD_G
#undef STORE_S
#undef COMPUTE
}

// ---------------- GAT aggregation: single pass, fp16 value gather, fp16 packed output --------
__global__ void aggregate_kernel(const uint32_t* __restrict__ hb,
                                 const float* __restrict__ asrc,
                                 const float* __restrict__ adst,
                                 const int* __restrict__ indptr,
                                 const int* __restrict__ esrc,
                                 const float* __restrict__ bias,
                                 uint32_t* __restrict__ xout, int N) {
    int n = (blockIdx.x * blockDim.x + threadIdx.x) >> 5;
    int lane = threadIdx.x & 31;
    if (n >= N) return;
    int s0 = indptr[n], s1 = indptr[n + 1];

    float4 ad  = *(const float4*)(adst + 4 * n);
    float4 asn = *(const float4*)(asrc + 4 * n);

    int head = lane >> 3;
    float adh   = pick4(ad.x, ad.y, ad.z, ad.w, head);
    float ash   = pick4(asn.x, asn.y, asn.z, asn.w, head);
    float wself = expf(lrelu(ash + adh));

    float acc[8];
    {
        uint4 p = *(const uint4*)(hb + (size_t)n * 128 + lane * 4);
        float2 f0 = unpack2h(p.x), f1 = unpack2h(p.y), f2 = unpack2h(p.z), f3 = unpack2h(p.w);
        acc[0] = wself * f0.x; acc[1] = wself * f0.y;
        acc[2] = wself * f1.x; acc[3] = wself * f1.y;
        acc[4] = wself * f2.x; acc[5] = wself * f2.y;
        acc[6] = wself * f3.x; acc[7] = wself * f3.y;
    }

    float wsum = 0.f;
    for (int eb = s0; eb < s1; eb += 8) {
        int idx = eb + (lane & 7);
        float wv = 0.f;
        int sv = 0;
        if (idx < s1) {
            sv = esrc[idx];
            float a = __ldg(asrc + 4 * sv + head);
            wv = expf(lrelu(a + adh));
        }
        wsum += wv;
        int cnt = min(8, s1 - eb);
        for (int j = 0; j < cnt; ++j) {
            float wj = __shfl_sync(0xffffffffu, wv, (lane & 24) | j);
            int sj   = __shfl_sync(0xffffffffu, sv, j);
            uint4 p = *(const uint4*)(hb + (size_t)sj * 128 + lane * 4);
            float2 f0 = unpack2h(p.x), f1 = unpack2h(p.y), f2 = unpack2h(p.z), f3 = unpack2h(p.w);
            acc[0] += wj * f0.x; acc[1] += wj * f0.y;
            acc[2] += wj * f1.x; acc[3] += wj * f1.y;
            acc[4] += wj * f2.x; acc[5] += wj * f2.y;
            acc[6] += wj * f3.x; acc[7] += wj * f3.y;
        }
    }
#pragma unroll
    for (int o = 4; o; o >>= 1) wsum += __shfl_xor_sync(0xffffffffu, wsum, o);
    float inv = 1.0f / (wsum + wself);

    const float4* bp = (const float4*)(bias + lane * 8);
    float4 b0 = bp[0], b1 = bp[1];
    uint4 o;
    o.x = pack2h(elu_f(acc[0] * inv + b0.x), elu_f(acc[1] * inv + b0.y));
    o.y = pack2h(elu_f(acc[2] * inv + b0.z), elu_f(acc[3] * inv + b0.w));
    o.z = pack2h(elu_f(acc[4] * inv + b1.x), elu_f(acc[5] * inv + b1.y));
    o.w = pack2h(elu_f(acc[6] * inv + b1.z), elu_f(acc[7] * inv + b1.w));
    *(uint4*)(xout + (size_t)n * 128 + lane * 4) = o;
}

// ---------------- global add pool: one block (128 thr) per graph (batch is sorted) -----------
__global__ void pool_kernel(const uint32_t* __restrict__ x, const int* __restrict__ batch,
                            float* __restrict__ emb, int N) {
    int g = blockIdx.x;
    int c = threadIdx.x;   // 0..127 (word index = 2 channels)
    int lo = 0, hi = N;
    while (lo < hi) { int mid = (lo + hi) >> 1; if (batch[mid] < g) lo = mid + 1; else hi = mid; }
    int start = lo;
    hi = N;
    while (lo < hi) { int mid = (lo + hi) >> 1; if (batch[mid] < g + 1) lo = mid + 1; else hi = mid; }
    int end = lo;

    float ax0 = 0.f, ay0 = 0.f, ax1 = 0.f, ay1 = 0.f;
    int r = start;
    for (; r + 1 < end; r += 2) {
        float2 f0 = unpack2h(x[(size_t)(r + 0) * 128 + c]);
        float2 f1 = unpack2h(x[(size_t)(r + 1) * 128 + c]);
        ax0 += f0.x; ay0 += f0.y;
        ax1 += f1.x; ay1 += f1.y;
    }
    if (r < end) {
        float2 f0 = unpack2h(x[(size_t)r * 128 + c]);
        ax0 += f0.x; ay0 += f0.y;
    }
    emb[(size_t)g * DIM + c * 2]     = ax0 + ax1;
    emb[(size_t)g * DIM + c * 2 + 1] = ay0 + ay1;
}

// ---------------- final MLP per graph ----------------
__global__ void mlp_kernel(const float* __restrict__ hemb, const float* __restrict__ temb,
                           const float* __restrict__ kge, const int* __restrict__ rel,
                           const float* __restrict__ W1, const float* __restrict__ b1,
                           const float* __restrict__ W2, const float* __restrict__ b2,
                           float* __restrict__ out) {
    int g = blockIdx.x;
    int t = threadIdx.x;
    __shared__ float z[2 * DIM + KGE_DIM];
    for (int i = t; i < DIM; i += 64) {
        z[i]       = hemb[(size_t)g * DIM + i];
        z[DIM + i] = temb[(size_t)g * DIM + i];
    }
    int r = rel[g];
    z[2 * DIM + t] = kge[(size_t)r * KGE_DIM + t];
    __syncthreads();

    float acc = b1[t];
#pragma unroll 4
    for (int k = 0; k < 2 * DIM + KGE_DIM; ++k)
        acc = fmaf(z[k], W1[(size_t)k * 64 + t], acc);
    acc = fmaxf(acc, 0.f) * W2[t];

#pragma unroll
    for (int o = 16; o; o >>= 1) acc += __shfl_xor_sync(0xffffffffu, acc, o);
    __shared__ float wsum[2];
    if ((t & 31) == 0) wsum[t >> 5] = acc;
    __syncthreads();
    if (t == 0) out[g] = wsum[0] + wsum[1] + b2[0];
}

// ---------------- launch ----------------
extern "C" void kernel_launch(void* const* d_in, const int* in_sizes, int n_in,
                              void* d_out, int out_size) {
    const float* head_x     = (const float*)d_in[0];
    const int*   head_ei    = (const int*)  d_in[1];
    const int*   head_batch = (const int*)  d_in[2];
    const float* tail_x     = (const float*)d_in[3];
    const int*   tail_ei    = (const int*)  d_in[4];
    const int*   tail_batch = (const int*)  d_in[5];
    const int*   rel        = (const int*)  d_in[6];
    const float* Ws         = (const float*)d_in[7];
    const float* att_s      = (const float*)d_in[8];
    const float* att_d      = (const float*)d_in[9];
    const float* biases     = (const float*)d_in[10];
    const float* kge        = (const float*)d_in[11];
    const float* W1         = (const float*)d_in[12];
    const float* b1         = (const float*)d_in[13];
    const float* W2         = (const float*)d_in[14];
    const float* b2         = (const float*)d_in[15];
    float* out = (float*)d_out;

    const int N = in_sizes[0] / DIM;    // 50000
    const int E = in_sizes[1] / 2;      // 800000
    const int B = in_sizes[6];          // 512

    // lazily create streams + events (host resources only)
    static cudaStream_t sMain2 = nullptr, sCsr0 = nullptr, sCsr1 = nullptr;
    static cudaEvent_t evFork = nullptr, evJoin = nullptr, evCsr0 = nullptr, evCsr1 = nullptr;
    if (sMain2 == nullptr) {
        cudaStreamCreateWithFlags(&sMain2, cudaStreamNonBlocking);
        cudaStreamCreateWithFlags(&sCsr0, cudaStreamNonBlocking);
        cudaStreamCreateWithFlags(&sCsr1, cudaStreamNonBlocking);
        cudaEventCreateWithFlags(&evFork, cudaEventDisableTiming);
        cudaEventCreateWithFlags(&evJoin, cudaEventDisableTiming);
        cudaEventCreateWithFlags(&evCsr0, cudaEventDisableTiming);
        cudaEventCreateWithFlags(&evCsr1, cudaEventDisableTiming);
    }

    uint32_t *p_h[2], *p_xa[2], *p_xb[2];
    float *p_alog[2];
    int *p_deg[2], *p_indptr[2], *p_cursor[2], *p_esrc[2];
    float *p_hemb, *p_temb;
    __nv_bfloat16 *p_whi, *p_wlo;
    {
        uint32_t* ubase;
        cudaGetSymbolAddress((void**)&ubase, g_h);
        p_h[0] = ubase; p_h[1] = ubase + (size_t)N_NODES_C * 128;
        cudaGetSymbolAddress((void**)&ubase, g_xa);
        p_xa[0] = ubase; p_xa[1] = ubase + (size_t)N_NODES_C * 128;
        cudaGetSymbolAddress((void**)&ubase, g_xb);
        p_xb[0] = ubase; p_xb[1] = ubase + (size_t)N_NODES_C * 128;
        float* base;
        cudaGetSymbolAddress((void**)&base, g_alog);
        p_alog[0] = base; p_alog[1] = base + (size_t)N_NODES_C * 2 * HEADS;
        int* ibase;
        cudaGetSymbolAddress((void**)&ibase, g_deg);
        p_deg[0] = ibase; p_deg[1] = ibase + N_NODES_C;
        cudaGetSymbolAddress((void**)&ibase, g_indptr);
        p_indptr[0] = ibase; p_indptr[1] = ibase + N_NODES_C + 1;
        cudaGetSymbolAddress((void**)&ibase, g_cursor);
        p_cursor[0] = ibase; p_cursor[1] = ibase + N_NODES_C;
        cudaGetSymbolAddress((void**)&ibase, g_esrc);
        p_esrc[0] = ibase; p_esrc[1] = ibase + N_EDGES_C;
    }
    cudaGetSymbolAddress((void**)&p_hemb, g_hemb);
    cudaGetSymbolAddress((void**)&p_temb, g_temb);
    cudaGetSymbolAddress((void**)&p_whi, g_whi);
    cudaGetSymbolAddress((void**)&p_wlo, g_wlo);

    const int wblocks = (N * 32 + 255) / 256;

    // pre-convert the 3 layer weights (default stream, before fork)
    wconv_kernel<<<3 * 256, 256>>>(Ws, p_whi, p_wlo);

    // fork: tail encoder on sMain2, CSR builds on sCsr0/sCsr1
    cudaEventRecord(evFork, 0);
    cudaStreamWaitEvent(sMain2, evFork, 0);
    cudaStreamWaitEvent(sCsr0, evFork, 0);
    cudaStreamWaitEvent(sCsr1, evFork, 0);

    for (int enc = 0; enc < 2; ++enc) {
        cudaStream_t st  = enc ? sMain2 : 0;
        cudaStream_t stc = enc ? sCsr1 : sCsr0;
        cudaEvent_t evC  = enc ? evCsr1 : evCsr0;
        const float* x0    = enc ? tail_x : head_x;
        const int*   ei    = enc ? tail_ei : head_ei;
        const int*   batch = enc ? tail_batch : head_batch;
        float*       emb   = enc ? p_temb : p_hemb;

        // CSR build on side stream (independent of GEMM)
        cudaMemsetAsync(p_deg[enc], 0, (size_t)N * sizeof(int), stc);
        hist_kernel<<<(E + 255) / 256, 256, 0, stc>>>(ei + E, E, p_deg[enc]);
        scan_kernel<<<1, 1024, 0, stc>>>(p_deg[enc], p_indptr[enc], p_cursor[enc], N);
        scatter_kernel<<<(E + 255) / 256, 256, 0, stc>>>(ei, ei + E, E, p_cursor[enc], p_esrc[enc]);
        cudaEventRecord(evC, stc);

        float* asrc_p = p_alog[enc];
        float* adst_p = p_alog[enc] + (size_t)N_NODES_C * HEADS;
        uint32_t* bufs[2] = {p_xa[enc], p_xb[enc]};
        dim3 gg((unsigned)((N + 127) / 128), 4);

        for (int l = 0; l < 3; ++l) {
            const void* Ain = (l == 0) ? (const void*)x0 : (const void*)bufs[(l + 1) & 1];
            if (l == 0)
                gemm_tc_kernel<false><<<gg, 256, 0, st>>>(Ain, p_whi + (size_t)l * DIM * DIM,
                                                          p_wlo + (size_t)l * DIM * DIM, p_h[enc],
                                                          att_s + l * HEADS * HID,
                                                          att_d + l * HEADS * HID,
                                                          p_alog[enc], N);
            else
                gemm_tc_kernel<true><<<gg, 256, 0, st>>>(Ain, p_whi + (size_t)l * DIM * DIM,
                                                         p_wlo + (size_t)l * DIM * DIM, p_h[enc],
                                                         att_s + l * HEADS * HID,
                                                         att_d + l * HEADS * HID,
                                                         p_alog[enc], N);
            if (l == 0) cudaStreamWaitEvent(st, evC, 0);   // CSR ready before first aggregate
            aggregate_kernel<<<wblocks, 256, 0, st>>>(p_h[enc], asrc_p, adst_p,
                                                      p_indptr[enc], p_esrc[enc],
                                                      biases + l * DIM, bufs[l & 1], N);
        }

        pool_kernel<<<N_GRAPHS_C, 128, 0, st>>>(bufs[0], batch, emb, N);   // layer2 output in bufs[0]
    }

    // join: default stream waits for tail pipeline
    cudaEventRecord(evJoin, sMain2);
    cudaStreamWaitEvent(0, evJoin, 0);

    mlp_kernel<<<B, 64>>>(p_hemb, p_temb, kge, rel, W1, b1, W2, b2, out);
}

// round 11
// speedup vs baseline: 1.8271x; 1.0843x over previous
#include <cuda_runtime.h>
#include <cuda_bf16.h>
#include <cuda_fp16.h>
#include <math.h>
#include <stdint.h>

#define N_NODES_C 50000
#define N_EDGES_C 800000
#define N_GRAPHS_C 512
#define DIM 256
#define HEADS 4
#define HID 64
#define KGE_DIM 64

// ---------------- static device scratch (no allocations allowed) ----------------
// one full set per encoder so head/tail pipelines can run concurrently
__device__ uint32_t g_h [2][N_NODES_C * 128];        // h packed as half2, 128 words/row
__device__ uint32_t g_xa[2][N_NODES_C * 128];        // layer intermediates packed half2
__device__ uint32_t g_xb[2][N_NODES_C * 128];
__device__ float g_alog[2][N_NODES_C * 2 * HEADS];   // [asrc | adst]
__device__ int   g_deg   [2][N_NODES_C];
__device__ int   g_indptr[2][N_NODES_C + 1];
__device__ int   g_cursor[2][N_NODES_C];
__device__ int   g_esrc  [2][N_EDGES_C];
__device__ float g_hemb[N_GRAPHS_C * DIM];
__device__ float g_temb[N_GRAPHS_C * DIM];
__device__ __nv_bfloat16 g_whi[3 * DIM * DIM];   // W transposed [l][n][k], hi part
__device__ __nv_bfloat16 g_wlo[3 * DIM * DIM];   // lo part

__device__ __forceinline__ float lrelu(float x) { return x > 0.f ? x : 0.2f * x; }
__device__ __forceinline__ float elu_f(float x) { return x > 0.f ? x : expm1f(x); }
__device__ __forceinline__ float pick4(float a, float b, float c, float d, int h) {
    return h == 0 ? a : (h == 1 ? b : (h == 2 ? c : d));
}
__device__ __forceinline__ uint32_t pack_bf16(__nv_bfloat16 lo, __nv_bfloat16 hi) {
    return (uint32_t)__bfloat16_as_ushort(lo) | ((uint32_t)__bfloat16_as_ushort(hi) << 16);
}
__device__ __forceinline__ uint32_t pack2h(float a, float b) {
    __half2 h = __floats2half2_rn(a, b);
    return *reinterpret_cast<uint32_t*>(&h);
}
__device__ __forceinline__ float2 unpack2h(uint32_t u) {
    __half2 h = *reinterpret_cast<__half2*>(&u);
    return __half22float2(h);
}

#define MMA16816(d, a0, a1, a2, a3, b0, b1)                                     \
    asm volatile("mma.sync.aligned.m16n8k16.row.col.f32.bf16.bf16.f32 "         \
                 "{%0,%1,%2,%3}, {%4,%5,%6,%7}, {%8,%9}, {%0,%1,%2,%3};"        \
                 : "+f"(d[0]), "+f"(d[1]), "+f"(d[2]), "+f"(d[3])               \
                 : "r"(a0), "r"(a1), "r"(a2), "r"(a3), "r"(b0), "r"(b1))

// ---------------- CSR build (counting sort by dst) ----------------
__global__ void hist_kernel(const int* __restrict__ dst, int E, int* __restrict__ deg) {
    int e = blockIdx.x * blockDim.x + threadIdx.x;
    if (e < E) atomicAdd(&deg[dst[e]], 1);
}

// single-block warp-shuffle scan: 4096 elements per iteration
__global__ void scan_kernel(const int* __restrict__ deg, int* __restrict__ indptr,
                            int* __restrict__ cursor, int n) {
    __shared__ int wsum[32];
    __shared__ int carry_s;
    int tid = threadIdx.x, lane = tid & 31, wid = tid >> 5;
    if (tid == 0) carry_s = 0;
    __syncthreads();
    for (int base = 0; base < n; base += 4096) {
        int i0 = base + tid * 4;
        int v0 = (i0 + 0 < n) ? deg[i0 + 0] : 0;
        int v1 = (i0 + 1 < n) ? deg[i0 + 1] : 0;
        int v2 = (i0 + 2 < n) ? deg[i0 + 2] : 0;
        int v3 = (i0 + 3 < n) ? deg[i0 + 3] : 0;
        int s = v0 + v1 + v2 + v3;
        int ps = s;
#pragma unroll
        for (int o = 1; o < 32; o <<= 1) {
            int t = __shfl_up_sync(0xffffffffu, ps, o);
            if (lane >= o) ps += t;
        }
        if (lane == 31) wsum[wid] = ps;
        __syncthreads();
        if (wid == 0) {
            int w = wsum[lane];
            int pw = w;
#pragma unroll
            for (int o = 1; o < 32; o <<= 1) {
                int t = __shfl_up_sync(0xffffffffu, pw, o);
                if (lane >= o) pw += t;
            }
            wsum[lane] = pw;
        }
        __syncthreads();
        int woff = wid ? wsum[wid - 1] : 0;
        int run = carry_s + woff + ps - s;
        if (i0 + 0 < n) { indptr[i0 + 0] = run; cursor[i0 + 0] = run; } run += v0;
        if (i0 + 1 < n) { indptr[i0 + 1] = run; cursor[i0 + 1] = run; } run += v1;
        if (i0 + 2 < n) { indptr[i0 + 2] = run; cursor[i0 + 2] = run; } run += v2;
        if (i0 + 3 < n) { indptr[i0 + 3] = run; cursor[i0 + 3] = run; }
        __syncthreads();
        if (tid == 0) carry_s += wsum[31];
        __syncthreads();
    }
    if (tid == 0) indptr[n] = carry_s;
}

__global__ void scatter_kernel(const int* __restrict__ src, const int* __restrict__ dst,
                               int E, int* __restrict__ cursor, int* __restrict__ esrc) {
    int e = blockIdx.x * blockDim.x + threadIdx.x;
    if (e < E) {
        int pos = atomicAdd(&cursor[dst[e]], 1);
        esrc[pos] = src[e];
    }
}

// ---------------- W pre-convert: fp32 [l][k][n] -> bf16 hi/lo transposed [l][n][k] ----------
__global__ void wconv_kernel(const float* __restrict__ W,
                             __nv_bfloat16* __restrict__ whi,
                             __nv_bfloat16* __restrict__ wlo) {
    int l = blockIdx.x >> 8;
    int n = blockIdx.x & 255;
    int k = threadIdx.x;
    float w = W[((size_t)l * 256 + k) * 256 + n];
    __nv_bfloat16 h = __float2bfloat16(w);
    float rem = w - __bfloat162float(h);
    whi[((size_t)l * 256 + n) * 256 + k] = h;
    wlo[((size_t)l * 256 + n) * 256 + k] = __float2bfloat16(rem);
}

// ---------------- tensor-core GEMM + fused attention-logit epilogue --------------------------
// Cb[M,128] (half2 packed) = A[M,256] @ W[256,256] (bf16x3 split). Head = blockIdx.y.
// A is fp32 (PACKED=false, layer 0) or packed half2 (PACKED=true, layers 1-2).
template <bool PACKED>
__global__ __launch_bounds__(256) void gemm_tc_kernel(const void* __restrict__ Avoid,
                                                      const __nv_bfloat16* __restrict__ Bhi,
                                                      const __nv_bfloat16* __restrict__ Blo,
                                                      uint32_t* __restrict__ Cb,
                                                      const float* __restrict__ att_s,
                                                      const float* __restrict__ att_d,
                                                      float* __restrict__ alog, int M) {
    constexpr int LDS = 24;
    __shared__ __nv_bfloat16 sAhi[2][128 * LDS];
    __shared__ __nv_bfloat16 sAlo[2][128 * LDS];
    __shared__ __nv_bfloat16 sBhi[2][64 * LDS];
    __shared__ __nv_bfloat16 sBlo[2][64 * LDS];
    __shared__ float sred[128][2];

    const int tid = threadIdx.x;
    const int bm = blockIdx.x * 128;
    const int bn = blockIdx.y * 64;
    const int head = blockIdx.y;          // 64-col tile == one head

    const int arow = tid >> 1, akoff = (tid & 1) * 8;
    const int brow = tid >> 2, bkoff = (tid & 3) * 4;
    const bool aval = (bm + arow) < M;
    const float*    Apf = (const float*)Avoid + (size_t)(bm + arow) * 256 + akoff;
    const uint32_t* Aph = (const uint32_t*)Avoid + (size_t)(bm + arow) * 128 + (akoff >> 1);
    const __nv_bfloat16* Bhp = Bhi + (size_t)(bn + brow) * 256 + bkoff;
    const __nv_bfloat16* Blp = Blo + (size_t)(bn + brow) * 256 + bkoff;

    float a_st[8];
    uint2 bh_st, bl_st;

    const int lane = tid & 31, wid = tid >> 5;
    const int wm = (wid & 3) * 32;
    const int wn = (wid >> 2) * 32;
    const int gid = lane >> 2, tig = lane & 3;

    float acc[2][4][4];
#pragma unroll
    for (int mi = 0; mi < 2; ++mi)
#pragma unroll
        for (int ni = 0; ni < 4; ++ni)
#pragma unroll
            for (int j = 0; j < 4; ++j) acc[mi][ni][j] = 0.f;

#define LOAD_G(c)                                                          \
    do {                                                                   \
        int k0_ = (c) * 16;                                                \
        if (PACKED) {                                                      \
            if (aval) {                                                    \
                uint4 t = *(const uint4*)(Aph + (k0_ >> 1));               \
                float2 f0 = unpack2h(t.x), f1 = unpack2h(t.y);             \
                float2 f2 = unpack2h(t.z), f3 = unpack2h(t.w);             \
                a_st[0] = f0.x; a_st[1] = f0.y; a_st[2] = f1.x; a_st[3] = f1.y; \
                a_st[4] = f2.x; a_st[5] = f2.y; a_st[6] = f3.x; a_st[7] = f3.y; \
            } else {                                                       \
                for (int j = 0; j < 8; ++j) a_st[j] = 0.f;                 \
            }                                                              \
        } else {                                                           \
            if (aval) {                                                    \
                float4 t0 = *(const float4*)(Apf + k0_);                   \
                float4 t1 = *(const float4*)(Apf + k0_ + 4);               \
                a_st[0] = t0.x; a_st[1] = t0.y; a_st[2] = t0.z; a_st[3] = t0.w; \
                a_st[4] = t1.x; a_st[5] = t1.y; a_st[6] = t1.z; a_st[7] = t1.w; \
            } else {                                                       \
                for (int j = 0; j < 8; ++j) a_st[j] = 0.f;                 \
            }                                                              \
        }                                                                  \
        bh_st = *(const uint2*)(Bhp + k0_);                                \
        bl_st = *(const uint2*)(Blp + k0_);                                \
    } while (0)

#define STORE_S(b)                                                         \
    do {                                                                   \
        __nv_bfloat16 h_[8], l_[8];                                        \
        for (int j = 0; j < 8; ++j) {                                      \
            h_[j] = __float2bfloat16(a_st[j]);                             \
            l_[j] = __float2bfloat16(a_st[j] - __bfloat162float(h_[j]));   \
        }                                                                  \
        uint2 uh0, ul0;                                                    \
        uh0.x = pack_bf16(h_[0], h_[1]); uh0.y = pack_bf16(h_[2], h_[3]);  \
        ul0.x = pack_bf16(l_[0], l_[1]); ul0.y = pack_bf16(l_[2], l_[3]);  \
        uint2 uh1, ul1;                                                    \
        uh1.x = pack_bf16(h_[4], h_[5]); uh1.y = pack_bf16(h_[6], h_[7]);  \
        ul1.x = pack_bf16(l_[4], l_[5]); ul1.y = pack_bf16(l_[6], l_[7]);  \
        *(uint2*)&sAhi[b][arow * LDS + akoff]     = uh0;                   \
        *(uint2*)&sAhi[b][arow * LDS + akoff + 4] = uh1;                   \
        *(uint2*)&sAlo[b][arow * LDS + akoff]     = ul0;                   \
        *(uint2*)&sAlo[b][arow * LDS + akoff + 4] = ul1;                   \
        *(uint2*)&sBhi[b][brow * LDS + bkoff] = bh_st;                     \
        *(uint2*)&sBlo[b][brow * LDS + bkoff] = bl_st;                     \
    } while (0)

#define COMPUTE(b)                                                          \
    do {                                                                    \
        uint32_t bh[4][2], bl[4][2];                                        \
        _Pragma("unroll")                                                   \
        for (int ni = 0; ni < 4; ++ni) {                                    \
            int n_ = (wn + ni * 8 + gid) * LDS + tig * 2;                   \
            bh[ni][0] = *(const uint32_t*)&sBhi[b][n_];                     \
            bh[ni][1] = *(const uint32_t*)&sBhi[b][n_ + 8];                 \
            bl[ni][0] = *(const uint32_t*)&sBlo[b][n_];                     \
            bl[ni][1] = *(const uint32_t*)&sBlo[b][n_ + 8];                 \
        }                                                                   \
        _Pragma("unroll")                                                   \
        for (int mi = 0; mi < 2; ++mi) {                                    \
            int r_ = (wm + mi * 16 + gid) * LDS + tig * 2;                  \
            uint32_t ah[4], al[4];                                          \
            ah[0] = *(const uint32_t*)&sAhi[b][r_];                         \
            ah[1] = *(const uint32_t*)&sAhi[b][r_ + 8 * LDS];               \
            ah[2] = *(const uint32_t*)&sAhi[b][r_ + 8];                     \
            ah[3] = *(const uint32_t*)&sAhi[b][r_ + 8 * LDS + 8];           \
            al[0] = *(const uint32_t*)&sAlo[b][r_];                         \
            al[1] = *(const uint32_t*)&sAlo[b][r_ + 8 * LDS];               \
            al[2] = *(const uint32_t*)&sAlo[b][r_ + 8];                     \
            al[3] = *(const uint32_t*)&sAlo[b][r_ + 8 * LDS + 8];           \
            _Pragma("unroll")                                               \
            for (int ni = 0; ni < 4; ++ni) {                                \
                MMA16816(acc[mi][ni], ah[0], ah[1], ah[2], ah[3],           \
                         bh[ni][0], bh[ni][1]);                             \
                MMA16816(acc[mi][ni], ah[0], ah[1], ah[2], ah[3],           \
                         bl[ni][0], bl[ni][1]);                             \
                MMA16816(acc[mi][ni], al[0], al[1], al[2], al[3],           \
                         bh[ni][0], bh[ni][1]);                             \
            }                                                               \
        }                                                                   \
    } while (0)

    LOAD_G(0);
    STORE_S(0);
    __syncthreads();

    int buf = 0;
#pragma unroll 1
    for (int c = 0; c < 16; ++c) {
        if (c < 15) LOAD_G(c + 1);
        COMPUTE(buf);
        if (c < 15) {
            STORE_S(buf ^ 1);
            __syncthreads();
            buf ^= 1;
        }
    }

    // ---- epilogue: packed half2 C stores + fused attention-logit dots ----
    float rps[2][2], rpd[2][2];
#pragma unroll
    for (int mi = 0; mi < 2; ++mi) {
        float ps0 = 0.f, pd0 = 0.f, ps1 = 0.f, pd1 = 0.f;
#pragma unroll
        for (int ni = 0; ni < 4; ++ni) {
            int c0 = wn + ni * 8 + tig * 2;
            float2 s2 = *(const float2*)(att_s + head * HID + c0);
            float2 d2 = *(const float2*)(att_d + head * HID + c0);
            ps0 += acc[mi][ni][0] * s2.x + acc[mi][ni][1] * s2.y;
            pd0 += acc[mi][ni][0] * d2.x + acc[mi][ni][1] * d2.y;
            ps1 += acc[mi][ni][2] * s2.x + acc[mi][ni][3] * s2.y;
            pd1 += acc[mi][ni][2] * d2.x + acc[mi][ni][3] * d2.y;
        }
#pragma unroll
        for (int o = 1; o < 4; o <<= 1) {
            ps0 += __shfl_xor_sync(0xffffffffu, ps0, o);
            pd0 += __shfl_xor_sync(0xffffffffu, pd0, o);
            ps1 += __shfl_xor_sync(0xffffffffu, ps1, o);
            pd1 += __shfl_xor_sync(0xffffffffu, pd1, o);
        }
        rps[mi][0] = ps0; rpd[mi][0] = pd0;
        rps[mi][1] = ps1; rpd[mi][1] = pd1;

        int r0 = bm + wm + mi * 16 + gid;
#pragma unroll
        for (int ni = 0; ni < 4; ++ni) {
            int col = bn + wn + ni * 8 + tig * 2;      // even
            if (r0 < M)
                Cb[(size_t)r0 * 128 + (col >> 1)] = pack2h(acc[mi][ni][0], acc[mi][ni][1]);
            if (r0 + 8 < M)
                Cb[(size_t)(r0 + 8) * 128 + (col >> 1)] = pack2h(acc[mi][ni][2], acc[mi][ni][3]);
        }
    }

    // warps 4-7 (wn==32 half) publish partials; warps 0-3 add and store
    if (wid >= 4 && tig == 0) {
#pragma unroll
        for (int mi = 0; mi < 2; ++mi) {
            int lr = wm + mi * 16 + gid;
            sred[lr][0]     = rps[mi][0];
            sred[lr][1]     = rpd[mi][0];
            sred[lr + 8][0] = rps[mi][1];
            sred[lr + 8][1] = rpd[mi][1];
        }
    }
    __syncthreads();
    if (wid < 4 && tig == 0) {
#pragma unroll
        for (int mi = 0; mi < 2; ++mi) {
            int lr = wm + mi * 16 + gid;
            int r0 = bm + lr;
            if (r0 < M) {
                alog[(size_t)r0 * 4 + head]                 = rps[mi][0] + sred[lr][0];
                alog[(size_t)(N_NODES_C + r0) * 4 + head]   = rpd[mi][0] + sred[lr][1];
            }
            if (r0 + 8 < M) {
                alog[(size_t)(r0 + 8) * 4 + head]               = rps[mi][1] + sred[lr + 8][0];
                alog[(size_t)(N_NODES_C + r0 + 8) * 4 + head]   = rpd[mi][1] + sred[lr + 8][1];
            }
        }
    }
#undef LOAD_G
#undef STORE_S
#undef COMPUTE
}

// ---------------- GAT aggregation: single pass, unrolled gather (MLP=8) ----------------
__global__ void aggregate_kernel(const uint32_t* __restrict__ hb,
                                 const float* __restrict__ asrc,
                                 const float* __restrict__ adst,
                                 const int* __restrict__ indptr,
                                 const int* __restrict__ esrc,
                                 const float* __restrict__ bias,
                                 uint32_t* __restrict__ xout, int N) {
    int n = (blockIdx.x * blockDim.x + threadIdx.x) >> 5;
    int lane = threadIdx.x & 31;
    if (n >= N) return;
    int s0 = indptr[n], s1 = indptr[n + 1];

    float4 ad  = *(const float4*)(adst + 4 * n);
    float4 asn = *(const float4*)(asrc + 4 * n);

    int head = lane >> 3;
    float adh   = pick4(ad.x, ad.y, ad.z, ad.w, head);
    float ash   = pick4(asn.x, asn.y, asn.z, asn.w, head);
    float wself = expf(lrelu(ash + adh));

    float acc[8];
    {
        uint4 p = *(const uint4*)(hb + (size_t)n * 128 + lane * 4);
        float2 f0 = unpack2h(p.x), f1 = unpack2h(p.y), f2 = unpack2h(p.z), f3 = unpack2h(p.w);
        acc[0] = wself * f0.x; acc[1] = wself * f0.y;
        acc[2] = wself * f1.x; acc[3] = wself * f1.y;
        acc[4] = wself * f2.x; acc[5] = wself * f2.y;
        acc[6] = wself * f3.x; acc[7] = wself * f3.y;
    }

    float wsum = 0.f;
    for (int eb = s0; eb < s1; eb += 8) {
        int idx = eb + (lane & 7);
        float wv = 0.f;
        int sv = 0;
        if (idx < s1) {
            sv = esrc[idx];
            float a = __ldg(asrc + 4 * sv + head);
            wv = expf(lrelu(a + adh));
        }
        wsum += wv;
        // constant-bound unrolled loop: 8 independent gathers in flight;
        // validity guard (eb + j < s1) is warp-uniform.
#pragma unroll
        for (int j = 0; j < 8; ++j) {
            if (eb + j < s1) {
                float wj = __shfl_sync(0xffffffffu, wv, (lane & 24) | j);
                int sj   = __shfl_sync(0xffffffffu, sv, j);
                uint4 p = *(const uint4*)(hb + (size_t)sj * 128 + lane * 4);
                float2 f0 = unpack2h(p.x), f1 = unpack2h(p.y);
                float2 f2 = unpack2h(p.z), f3 = unpack2h(p.w);
                acc[0] += wj * f0.x; acc[1] += wj * f0.y;
                acc[2] += wj * f1.x; acc[3] += wj * f1.y;
                acc[4] += wj * f2.x; acc[5] += wj * f2.y;
                acc[6] += wj * f3.x; acc[7] += wj * f3.y;
            }
        }
    }
#pragma unroll
    for (int o = 4; o; o >>= 1) wsum += __shfl_xor_sync(0xffffffffu, wsum, o);
    float inv = 1.0f / (wsum + wself);

    const float4* bp = (const float4*)(bias + lane * 8);
    float4 b0 = bp[0], b1 = bp[1];
    uint4 o;
    o.x = pack2h(elu_f(acc[0] * inv + b0.x), elu_f(acc[1] * inv + b0.y));
    o.y = pack2h(elu_f(acc[2] * inv + b0.z), elu_f(acc[3] * inv + b0.w));
    o.z = pack2h(elu_f(acc[4] * inv + b1.x), elu_f(acc[5] * inv + b1.y));
    o.w = pack2h(elu_f(acc[6] * inv + b1.z), elu_f(acc[7] * inv + b1.w));
    *(uint4*)(xout + (size_t)n * 128 + lane * 4) = o;
}

// ---------------- global add pool: one block (128 thr) per graph (batch is sorted) -----------
__global__ void pool_kernel(const uint32_t* __restrict__ x, const int* __restrict__ batch,
                            float* __restrict__ emb, int N) {
    int g = blockIdx.x;
    int c = threadIdx.x;   // 0..127 (word index = 2 channels)
    int lo = 0, hi = N;
    while (lo < hi) { int mid = (lo + hi) >> 1; if (batch[mid] < g) lo = mid + 1; else hi = mid; }
    int start = lo;
    hi = N;
    while (lo < hi) { int mid = (lo + hi) >> 1; if (batch[mid] < g + 1) lo = mid + 1; else hi = mid; }
    int end = lo;

    float ax0 = 0.f, ay0 = 0.f, ax1 = 0.f, ay1 = 0.f;
    int r = start;
    for (; r + 1 < end; r += 2) {
        float2 f0 = unpack2h(x[(size_t)(r + 0) * 128 + c]);
        float2 f1 = unpack2h(x[(size_t)(r + 1) * 128 + c]);
        ax0 += f0.x; ay0 += f0.y;
        ax1 += f1.x; ay1 += f1.y;
    }
    if (r < end) {
        float2 f0 = unpack2h(x[(size_t)r * 128 + c]);
        ax0 += f0.x; ay0 += f0.y;
    }
    emb[(size_t)g * DIM + c * 2]     = ax0 + ax1;
    emb[(size_t)g * DIM + c * 2 + 1] = ay0 + ay1;
}

// ---------------- final MLP per graph ----------------
__global__ void mlp_kernel(const float* __restrict__ hemb, const float* __restrict__ temb,
                           const float* __restrict__ kge, const int* __restrict__ rel,
                           const float* __restrict__ W1, const float* __restrict__ b1,
                           const float* __restrict__ W2, const float* __restrict__ b2,
                           float* __restrict__ out) {
    int g = blockIdx.x;
    int t = threadIdx.x;
    __shared__ float z[2 * DIM + KGE_DIM];
    for (int i = t; i < DIM; i += 64) {
        z[i]       = hemb[(size_t)g * DIM + i];
        z[DIM + i] = temb[(size_t)g * DIM + i];
    }
    int r = rel[g];
    z[2 * DIM + t] = kge[(size_t)r * KGE_DIM + t];
    __syncthreads();

    float acc = b1[t];
#pragma unroll 4
    for (int k = 0; k < 2 * DIM + KGE_DIM; ++k)
        acc = fmaf(z[k], W1[(size_t)k * 64 + t], acc);
    acc = fmaxf(acc, 0.f) * W2[t];

#pragma unroll
    for (int o = 16; o; o >>= 1) acc += __shfl_xor_sync(0xffffffffu, acc, o);
    __shared__ float wsum[2];
    if ((t & 31) == 0) wsum[t >> 5] = acc;
    __syncthreads();
    if (t == 0) out[g] = wsum[0] + wsum[1] + b2[0];
}

// ---------------- launch ----------------
extern "C" void kernel_launch(void* const* d_in, const int* in_sizes, int n_in,
                              void* d_out, int out_size) {
    const float* head_x     = (const float*)d_in[0];
    const int*   head_ei    = (const int*)  d_in[1];
    const int*   head_batch = (const int*)  d_in[2];
    const float* tail_x     = (const float*)d_in[3];
    const int*   tail_ei    = (const int*)  d_in[4];
    const int*   tail_batch = (const int*)  d_in[5];
    const int*   rel        = (const int*)  d_in[6];
    const float* Ws         = (const float*)d_in[7];
    const float* att_s      = (const float*)d_in[8];
    const float* att_d      = (const float*)d_in[9];
    const float* biases     = (const float*)d_in[10];
    const float* kge        = (const float*)d_in[11];
    const float* W1         = (const float*)d_in[12];
    const float* b1         = (const float*)d_in[13];
    const float* W2         = (const float*)d_in[14];
    const float* b2         = (const float*)d_in[15];
    float* out = (float*)d_out;

    const int N = in_sizes[0] / DIM;    // 50000
    const int E = in_sizes[1] / 2;      // 800000
    const int B = in_sizes[6];          // 512

    // lazily create streams + events (host resources only)
    static cudaStream_t sMain2 = nullptr, sCsr0 = nullptr, sCsr1 = nullptr;
    static cudaEvent_t evFork = nullptr, evJoin = nullptr, evCsr0 = nullptr, evCsr1 = nullptr;
    if (sMain2 == nullptr) {
        cudaStreamCreateWithFlags(&sMain2, cudaStreamNonBlocking);
        cudaStreamCreateWithFlags(&sCsr0, cudaStreamNonBlocking);
        cudaStreamCreateWithFlags(&sCsr1, cudaStreamNonBlocking);
        cudaEventCreateWithFlags(&evFork, cudaEventDisableTiming);
        cudaEventCreateWithFlags(&evJoin, cudaEventDisableTiming);
        cudaEventCreateWithFlags(&evCsr0, cudaEventDisableTiming);
        cudaEventCreateWithFlags(&evCsr1, cudaEventDisableTiming);
    }

    uint32_t *p_h[2], *p_xa[2], *p_xb[2];
    float *p_alog[2];
    int *p_deg[2], *p_indptr[2], *p_cursor[2], *p_esrc[2];
    float *p_hemb, *p_temb;
    __nv_bfloat16 *p_whi, *p_wlo;
    {
        uint32_t* ubase;
        cudaGetSymbolAddress((void**)&ubase, g_h);
        p_h[0] = ubase; p_h[1] = ubase + (size_t)N_NODES_C * 128;
        cudaGetSymbolAddress((void**)&ubase, g_xa);
        p_xa[0] = ubase; p_xa[1] = ubase + (size_t)N_NODES_C * 128;
        cudaGetSymbolAddress((void**)&ubase, g_xb);
        p_xb[0] = ubase; p_xb[1] = ubase + (size_t)N_NODES_C * 128;
        float* base;
        cudaGetSymbolAddress((void**)&base, g_alog);
        p_alog[0] = base; p_alog[1] = base + (size_t)N_NODES_C * 2 * HEADS;
        int* ibase;
        cudaGetSymbolAddress((void**)&ibase, g_deg);
        p_deg[0] = ibase; p_deg[1] = ibase + N_NODES_C;
        cudaGetSymbolAddress((void**)&ibase, g_indptr);
        p_indptr[0] = ibase; p_indptr[1] = ibase + N_NODES_C + 1;
        cudaGetSymbolAddress((void**)&ibase, g_cursor);
        p_cursor[0] = ibase; p_cursor[1] = ibase + N_NODES_C;
        cudaGetSymbolAddress((void**)&ibase, g_esrc);
        p_esrc[0] = ibase; p_esrc[1] = ibase + N_EDGES_C;
    }
    cudaGetSymbolAddress((void**)&p_hemb, g_hemb);
    cudaGetSymbolAddress((void**)&p_temb, g_temb);
    cudaGetSymbolAddress((void**)&p_whi, g_whi);
    cudaGetSymbolAddress((void**)&p_wlo, g_wlo);

    const int wblocks = (N * 32 + 255) / 256;

    // pre-convert the 3 layer weights (default stream, before fork)
    wconv_kernel<<<3 * 256, 256>>>(Ws, p_whi, p_wlo);

    // fork: tail encoder on sMain2, CSR builds on sCsr0/sCsr1
    cudaEventRecord(evFork, 0);
    cudaStreamWaitEvent(sMain2, evFork, 0);
    cudaStreamWaitEvent(sCsr0, evFork, 0);
    cudaStreamWaitEvent(sCsr1, evFork, 0);

    for (int enc = 0; enc < 2; ++enc) {
        cudaStream_t st  = enc ? sMain2 : 0;
        cudaStream_t stc = enc ? sCsr1 : sCsr0;
        cudaEvent_t evC  = enc ? evCsr1 : evCsr0;
        const float* x0    = enc ? tail_x : head_x;
        const int*   ei    = enc ? tail_ei : head_ei;
        const int*   batch = enc ? tail_batch : head_batch;
        float*       emb   = enc ? p_temb : p_hemb;

        cudaMemsetAsync(p_deg[enc], 0, (size_t)N * sizeof(int), stc);
        hist_kernel<<<(E + 255) / 256, 256, 0, stc>>>(ei + E, E, p_deg[enc]);
        scan_kernel<<<1, 1024, 0, stc>>>(p_deg[enc], p_indptr[enc], p_cursor[enc], N);
        scatter_kernel<<<(E + 255) / 256, 256, 0, stc>>>(ei, ei + E, E, p_cursor[enc], p_esrc[enc]);
        cudaEventRecord(evC, stc);

        float* asrc_p = p_alog[enc];
        float* adst_p = p_alog[enc] + (size_t)N_NODES_C * HEADS;
        uint32_t* bufs[2] = {p_xa[enc], p_xb[enc]};
        dim3 gg((unsigned)((N + 127) / 128), 4);

        for (int l = 0; l < 3; ++l) {
            const void* Ain = (l == 0) ? (const void*)x0 : (const void*)bufs[(l + 1) & 1];
            if (l == 0)
                gemm_tc_kernel<false><<<gg, 256, 0, st>>>(Ain, p_whi + (size_t)l * DIM * DIM,
                                                          p_wlo + (size_t)l * DIM * DIM, p_h[enc],
                                                          att_s + l * HEADS * HID,
                                                          att_d + l * HEADS * HID,
                                                          p_alog[enc], N);
            else
                gemm_tc_kernel<true><<<gg, 256, 0, st>>>(Ain, p_whi + (size_t)l * DIM * DIM,
                                                         p_wlo + (size_t)l * DIM * DIM, p_h[enc],
                                                         att_s + l * HEADS * HID,
                                                         att_d + l * HEADS * HID,
                                                         p_alog[enc], N);
            if (l == 0) cudaStreamWaitEvent(st, evC, 0);   // CSR ready before first aggregate
            aggregate_kernel<<<wblocks, 256, 0, st>>>(p_h[enc], asrc_p, adst_p,
                                                      p_indptr[enc], p_esrc[enc],
                                                      biases + l * DIM, bufs[l & 1], N);
        }

        pool_kernel<<<N_GRAPHS_C, 128, 0, st>>>(bufs[0], batch, emb, N);   // layer2 output in bufs[0]
    }

    // join: default stream waits for tail pipeline
    cudaEventRecord(evJoin, sMain2);
    cudaStreamWaitEvent(0, evJoin, 0);

    mlp_kernel<<<B, 64>>>(p_hemb, p_temb, kge, rel, W1, b1, W2, b2, out);
}